// round 2
// baseline (speedup 1.0000x reference)
#include <cuda_runtime.h>
#include <math.h>

#define B_   4
#define S_   64
#define D_   512
#define H_   8
#define DH_  64
#define DFF_ 2048
#define L_   2
#define V_   32128
#define T_   16
#define M_   256          // B_*S_
#define DD_  (D_*D_)
#define NEG_ (-1e9f)

// ---------------- device scratch (no allocation allowed) ----------------
__device__ float g_xe [M_*D_];       // encoder residual stream
__device__ float g_h  [M_*D_];       // rmsnorm output
__device__ float g_q  [M_*D_];
__device__ float g_k  [M_*D_];
__device__ float g_v  [M_*D_];
__device__ float g_at [M_*D_];       // attn out (pre-projection)
__device__ float g_ff [M_*DFF_];
__device__ float g_hs [M_*D_];       // encoder final output (normed)
__device__ float g_cK [L_*M_*D_];    // cross-attn K per layer
__device__ float g_cV [L_*M_*D_];    // cross-attn V per layer
__device__ float g_dx [B_*D_];       // decoder token residual stream
__device__ float g_dq [B_*D_];       // decoder q (self or cross)
__device__ float g_dat[B_*D_];       // decoder attn out
__device__ float g_dff[B_*DFF_];
__device__ float g_kc [L_*B_*T_*D_]; // self-K cache
__device__ float g_vc [L_*B_*T_*D_]; // self-V cache
__device__ float g_logits[B_*V_];
__device__ float g_probs [B_*V_];

// ---------------- encoder: embedding gather ----------------
__global__ void k_embed(const int* __restrict__ ids, const float* __restrict__ emb) {
    int r = blockIdx.x;
    int id = ids[r];
    for (int d = threadIdx.x; d < D_; d += 256)
        g_xe[r*D_ + d] = emb[id*D_ + d];
}

// ---------------- RMSNorm (one block per row, D=512) ----------------
__global__ void k_rms(const float* __restrict__ x, const float* __restrict__ w,
                      float* __restrict__ out) {
    int r = blockIdx.x;
    __shared__ float red[8];
    float ss = 0.f;
    for (int d = threadIdx.x; d < D_; d += 256) { float v = x[r*D_+d]; ss += v*v; }
    for (int o = 16; o; o >>= 1) ss += __shfl_xor_sync(0xffffffffu, ss, o);
    if ((threadIdx.x & 31) == 0) red[threadIdx.x >> 5] = ss;
    __syncthreads();
    if (threadIdx.x == 0) {
        float t = 0.f;
        for (int i = 0; i < 8; i++) t += red[i];
        red[0] = rsqrtf(t / (float)D_ + 1e-6f);
    }
    __syncthreads();
    float rs = red[0];
    for (int d = threadIdx.x; d < D_; d += 256)
        out[r*D_+d] = x[r*D_+d] * rs * w[d];
}

// ---------------- encoder SGEMM: C[256,N] = A[256,K] @ W[K,N] ----------------
// op bit0: C += res, bit1: relu. 64x64 tile, 4x4 microtile, 256 threads.
__global__ void k_sgemm(const float* __restrict__ A, const float* __restrict__ W,
                        const float* __restrict__ res, float* __restrict__ C,
                        int N, int K, int op) {
    __shared__ float As[16][64];
    __shared__ float Ws[16][64];
    int bx = blockIdx.x * 64, by = blockIdx.y * 64;
    int tx = threadIdx.x & 15, ty = threadIdx.x >> 4;
    float acc[4][4] = {};
    for (int k0 = 0; k0 < K; k0 += 16) {
        for (int i = threadIdx.x; i < 1024; i += 256) {
            int m = i >> 4, kk = i & 15;
            As[kk][m] = A[(by+m)*K + k0 + kk];
        }
        for (int i = threadIdx.x; i < 1024; i += 256) {
            int n = i & 63, kk = i >> 6;
            Ws[kk][n] = W[(k0+kk)*N + bx + n];
        }
        __syncthreads();
        #pragma unroll
        for (int kk = 0; kk < 16; kk++) {
            float a0 = As[kk][ty*4+0], a1 = As[kk][ty*4+1];
            float a2 = As[kk][ty*4+2], a3 = As[kk][ty*4+3];
            float b0 = Ws[kk][tx*4+0], b1 = Ws[kk][tx*4+1];
            float b2 = Ws[kk][tx*4+2], b3 = Ws[kk][tx*4+3];
            acc[0][0] += a0*b0; acc[0][1] += a0*b1; acc[0][2] += a0*b2; acc[0][3] += a0*b3;
            acc[1][0] += a1*b0; acc[1][1] += a1*b1; acc[1][2] += a1*b2; acc[1][3] += a1*b3;
            acc[2][0] += a2*b0; acc[2][1] += a2*b1; acc[2][2] += a2*b2; acc[2][3] += a2*b3;
            acc[3][0] += a3*b0; acc[3][1] += a3*b1; acc[3][2] += a3*b2; acc[3][3] += a3*b3;
        }
        __syncthreads();
    }
    #pragma unroll
    for (int i = 0; i < 4; i++)
        #pragma unroll
        for (int j = 0; j < 4; j++) {
            int m = by + ty*4 + i, n = bx + tx*4 + j;
            float v = acc[i][j];
            if (op & 1) v += res[m*N + n];
            if (op & 2) v = fmaxf(v, 0.f);
            C[m*N + n] = v;
        }
}

// ---------------- encoder attention (one block per (b,h)) ----------------
#define KS(j,d) ks[(j)][((d) ^ ((j) & 31))]
#define SC(i,j) sc[(i)][((j) ^ ((i) & 31))]
__global__ void k_encattn(const float* __restrict__ mask) {
    int b = blockIdx.x >> 3, h = blockIdx.x & 7;
    __shared__ float ks[64][64];   // K, XOR-swizzled
    __shared__ float vs[64][64];   // Q first, then V
    __shared__ float sc[64][64];   // scores, XOR-swizzled
    // load K (swizzled) and Q (plain, into vs)
    for (int i = threadIdx.x; i < 4096; i += 256) {
        int j = i >> 6, d = i & 63;
        KS(j,d) = g_k[(b*64+j)*D_ + h*64 + d];
        vs[j][d] = g_q[(b*64+j)*D_ + h*64 + d];
    }
    __syncthreads();
    // scores
    for (int idx = threadIdx.x; idx < 4096; idx += 256) {
        int i = idx >> 6, j = idx & 63;
        float s = 0.f;
        #pragma unroll 8
        for (int d = 0; d < 64; d++) s += vs[i][d] * KS(j,d);
        SC(i,j) = s * 0.125f + (1.f - mask[b*64 + j]) * NEG_;
    }
    __syncthreads();
    // overwrite vs with V
    for (int i = threadIdx.x; i < 4096; i += 256) {
        int j = i >> 6, d = i & 63;
        vs[j][d] = g_v[(b*64+j)*D_ + h*64 + d];
    }
    __syncthreads();
    // softmax per q-row
    if (threadIdx.x < 64) {
        int i = threadIdx.x;
        float m = -1e30f;
        for (int j = 0; j < 64; j++) m = fmaxf(m, SC(i,j));
        float su = 0.f;
        for (int j = 0; j < 64; j++) { float e = expf(SC(i,j) - m); SC(i,j) = e; su += e; }
        float inv = 1.f / su;
        for (int j = 0; j < 64; j++) SC(i,j) *= inv;
    }
    __syncthreads();
    // out
    for (int idx = threadIdx.x; idx < 4096; idx += 256) {
        int i = idx >> 6, d = idx & 63;
        float o = 0.f;
        #pragma unroll 8
        for (int j = 0; j < 64; j++) o += SC(i,j) * vs[j][d];
        g_at[(b*64+i)*D_ + h*64 + d] = o;
    }
}

// ---------------- decoder GEMM: C[4,N] = rms?(x)[4,K] @ W[K,N] (+res, relu) --
// 256 threads = 64 cols x 4 k-splits. grid.x = N/64, grid.z selects (W,C,rs).
__global__ void k_dgemm(const float* __restrict__ x, const float* __restrict__ ln,
                        const float* __restrict__ W0, const float* __restrict__ W1,
                        const float* __restrict__ W2,
                        float* C0, float* C1, float* C2,
                        int rs0, int rs1, int rs2,
                        const float* __restrict__ res, int N, int K, int relu) {
    const float* W = (blockIdx.z == 0) ? W0 : (blockIdx.z == 1) ? W1 : W2;
    float* C = (blockIdx.z == 0) ? C0 : (blockIdx.z == 1) ? C1 : C2;
    int rs = (blockIdx.z == 0) ? rs0 : (blockIdx.z == 1) ? rs1 : rs2;
    __shared__ float h_s[B_*DFF_];
    __shared__ float ss[B_][64];
    __shared__ float red[16*64];
    int tid = threadIdx.x;
    if (ln) {
        int r = tid >> 6, c = tid & 63;
        float s = 0.f;
        for (int k = c; k < K; k += 64) { float v = x[r*K + k]; s += v*v; }
        ss[r][c] = s;
        __syncthreads();
        if (tid < B_) {
            float t = 0.f;
            for (int c2 = 0; c2 < 64; c2++) t += ss[tid][c2];
            ss[tid][0] = rsqrtf(t / (float)K + 1e-6f);
        }
        __syncthreads();
        for (int i = tid; i < B_*K; i += 256) {
            int r2 = i / K, k = i % K;
            h_s[i] = x[i] * ss[r2][0] * ln[k];
        }
    } else {
        for (int i = tid; i < B_*K; i += 256) h_s[i] = x[i];
    }
    __syncthreads();
    int c  = tid & 63;
    int col = (blockIdx.x << 6) + c;
    int kg = tid >> 6;
    int kq = K >> 2;
    int kbeg = kg * kq, kend = kbeg + kq;
    float a0 = 0.f, a1 = 0.f, a2 = 0.f, a3 = 0.f;
    for (int k = kbeg; k < kend; k++) {
        float w = W[k*N + col];
        a0 += h_s[k]        * w;
        a1 += h_s[K + k]    * w;
        a2 += h_s[2*K + k]  * w;
        a3 += h_s[3*K + k]  * w;
    }
    red[(kg*4+0)*64 + c] = a0;
    red[(kg*4+1)*64 + c] = a1;
    red[(kg*4+2)*64 + c] = a2;
    red[(kg*4+3)*64 + c] = a3;
    __syncthreads();
    if (kg == 0) {
        #pragma unroll
        for (int r = 0; r < 4; r++) {
            float v = red[r*64+c] + red[(4+r)*64+c] + red[(8+r)*64+c] + red[(12+r)*64+c];
            if (res)  v += res[r*N + col];
            if (relu) v = fmaxf(v, 0.f);
            C[r*rs + col] = v;
        }
    }
}

// ---------------- decoder self-attention (cache), 64 threads, block=(b,h) ----
__global__ void k_selfattn(int l, int t) {
    int b = blockIdx.x >> 3, h = blockIdx.x & 7;
    int tid = threadIdx.x;
    __shared__ float p[T_];
    __shared__ float qv[DH_];
    qv[tid] = g_dq[b*D_ + h*DH_ + tid];
    __syncthreads();
    if (tid <= t) {
        const float* kp = &g_kc[((l*B_ + b)*T_ + tid)*D_ + h*DH_];
        float s = 0.f;
        #pragma unroll 8
        for (int d = 0; d < DH_; d++) s += qv[d] * kp[d];
        p[tid] = s * 0.125f;
    }
    __syncthreads();
    if (tid == 0) {
        float m = -1e30f;
        for (int j = 0; j <= t; j++) m = fmaxf(m, p[j]);
        float su = 0.f;
        for (int j = 0; j <= t; j++) { p[j] = expf(p[j] - m); su += p[j]; }
        float inv = 1.f / su;
        for (int j = 0; j <= t; j++) p[j] *= inv;
    }
    __syncthreads();
    float o = 0.f;
    for (int j = 0; j <= t; j++)
        o += p[j] * g_vc[((l*B_ + b)*T_ + j)*D_ + h*DH_ + tid];
    g_dat[b*D_ + h*DH_ + tid] = o;
}

// ---------------- decoder cross-attention, 64 threads, block=(b,h) ----------
__global__ void k_crossattn(int l, const float* __restrict__ mask) {
    int b = blockIdx.x >> 3, h = blockIdx.x & 7;
    int tid = threadIdx.x;
    __shared__ float p[S_];
    __shared__ float qv[DH_];
    qv[tid] = g_dq[b*D_ + h*DH_ + tid];
    __syncthreads();
    {
        const float* kp = &g_cK[l*M_*D_ + (b*S_ + tid)*D_ + h*DH_];
        float s = 0.f;
        #pragma unroll 8
        for (int d = 0; d < DH_; d++) s += qv[d] * kp[d];
        p[tid] = s * 0.125f + (1.f - mask[b*S_ + tid]) * NEG_;
    }
    __syncthreads();
    if (tid == 0) {
        float m = -1e30f;
        for (int j = 0; j < S_; j++) m = fmaxf(m, p[j]);
        float su = 0.f;
        for (int j = 0; j < S_; j++) { p[j] = expf(p[j] - m); su += p[j]; }
        float inv = 1.f / su;
        for (int j = 0; j < S_; j++) p[j] *= inv;
    }
    __syncthreads();
    float o = 0.f;
    for (int j = 0; j < S_; j++)
        o += p[j] * g_cV[l*M_*D_ + (b*S_ + j)*D_ + h*DH_ + tid];
    g_dat[b*D_ + h*DH_ + tid] = o;
}

// ---------------- softmax + argmax + outputs + zero next-x ------------------
__global__ void k_softmax(float* __restrict__ out, int t) {
    int b = blockIdx.x, tid = threadIdx.x;
    __shared__ float sm[256];
    __shared__ int   si[256];
    const float* lg = &g_logits[b*V_];
    float mx = -1e30f; int mi = 0;
    for (int v = tid; v < V_; v += 256) {
        float xv = lg[v];
        if (xv > mx) { mx = xv; mi = v; }
    }
    sm[tid] = mx; si[tid] = mi;
    __syncthreads();
    for (int s = 128; s; s >>= 1) {
        if (tid < s) {
            float xo = sm[tid+s]; int io = si[tid+s];
            if (xo > sm[tid] || (xo == sm[tid] && io < si[tid])) { sm[tid] = xo; si[tid] = io; }
        }
        __syncthreads();
    }
    float rowmax = sm[0];
    int amax = si[0];
    __syncthreads();
    float su = 0.f;
    for (int v = tid; v < V_; v += 256) su += expf(lg[v] - rowmax);
    sm[tid] = su;
    __syncthreads();
    for (int s = 128; s; s >>= 1) { if (tid < s) sm[tid] += sm[tid+s]; __syncthreads(); }
    float inv = 1.f / sm[0];
    float* po = &out[(b*T_ + t)*V_];
    for (int v = tid; v < V_; v += 256) {
        float pv = expf(lg[v] - rowmax) * inv;
        g_probs[b*V_ + v] = pv;
        po[v] = pv;
    }
    if (tid == 0) out[B_*T_*V_ + b*T_ + t] = (amax == 0) ? 1.0f : 0.0f;
    for (int d = tid; d < D_; d += 256) g_dx[b*D_ + d] = 0.f;
}

// ---------------- soft embedding: g_dx += probs @ emb -----------------------
// grid 128 blocks: each streams 251 vocab rows of emb. 32128 = 128*251.
__global__ void k_ynext(const float* __restrict__ emb) {
    __shared__ float ps[B_][251];
    int tid = threadIdx.x;
    int v0 = blockIdx.x * 251;
    for (int i = tid; i < B_*251; i += 256) {
        int b = i / 251, j = i % 251;
        ps[b][j] = g_probs[b*V_ + v0 + j];
    }
    __syncthreads();
    int c0 = tid, c1 = tid + 256;
    float a00=0,a01=0,a10=0,a11=0,a20=0,a21=0,a30=0,a31=0;
    for (int j = 0; j < 251; j++) {
        const float* er = &emb[(size_t)(v0 + j) * D_];
        float e0 = er[c0], e1 = er[c1];
        a00 += ps[0][j]*e0; a01 += ps[0][j]*e1;
        a10 += ps[1][j]*e0; a11 += ps[1][j]*e1;
        a20 += ps[2][j]*e0; a21 += ps[2][j]*e1;
        a30 += ps[3][j]*e0; a31 += ps[3][j]*e1;
    }
    atomicAdd(&g_dx[0*D_+c0], a00); atomicAdd(&g_dx[0*D_+c1], a01);
    atomicAdd(&g_dx[1*D_+c0], a10); atomicAdd(&g_dx[1*D_+c1], a11);
    atomicAdd(&g_dx[2*D_+c0], a20); atomicAdd(&g_dx[2*D_+c1], a21);
    atomicAdd(&g_dx[3*D_+c0], a30); atomicAdd(&g_dx[3*D_+c1], a31);
}

// ---------------- init decoder x with pad embedding -------------------------
__global__ void k_initdx(const float* __restrict__ emb) {
    int d = threadIdx.x + blockIdx.x * 256;   // grid 2 x 256 = 512
    float v = emb[d];                          // PAD_ID = 0 -> row 0
    for (int b = 0; b < B_; b++) g_dx[b*D_ + d] = v;
}

// ---------------- host driver ----------------
extern "C" void kernel_launch(void* const* d_in, const int* in_sizes, int n_in,
                              void* d_out, int out_size) {
    const int*   ids     = (const int*)  d_in[0];
    const float* mask    = (const float*)d_in[1];
    const float* emb     = (const float*)d_in[2];
    const float* enc_wq  = (const float*)d_in[3];
    const float* enc_wk  = (const float*)d_in[4];
    const float* enc_wv  = (const float*)d_in[5];
    const float* enc_wo  = (const float*)d_in[6];
    const float* enc_ln1 = (const float*)d_in[7];
    const float* enc_w1  = (const float*)d_in[8];
    const float* enc_w2  = (const float*)d_in[9];
    const float* enc_ln2 = (const float*)d_in[10];
    const float* enc_lnf = (const float*)d_in[11];
    const float* dec_sq  = (const float*)d_in[12];
    const float* dec_sk  = (const float*)d_in[13];
    const float* dec_sv  = (const float*)d_in[14];
    const float* dec_so  = (const float*)d_in[15];
    const float* dec_ln1 = (const float*)d_in[16];
    const float* dec_cq  = (const float*)d_in[17];
    const float* dec_ck  = (const float*)d_in[18];
    const float* dec_cv  = (const float*)d_in[19];
    const float* dec_co  = (const float*)d_in[20];
    const float* dec_ln2 = (const float*)d_in[21];
    const float* dec_w1  = (const float*)d_in[22];
    const float* dec_w2  = (const float*)d_in[23];
    const float* dec_ln3 = (const float*)d_in[24];
    const float* dec_lnf = (const float*)d_in[25];
    const float* lm_head = (const float*)d_in[26];
    float* out = (float*)d_out;

    void* p;
    cudaGetSymbolAddress(&p, g_xe);  float* xe  = (float*)p;
    cudaGetSymbolAddress(&p, g_h);   float* h   = (float*)p;
    cudaGetSymbolAddress(&p, g_q);   float* q   = (float*)p;
    cudaGetSymbolAddress(&p, g_k);   float* k   = (float*)p;
    cudaGetSymbolAddress(&p, g_v);   float* v   = (float*)p;
    cudaGetSymbolAddress(&p, g_at);  float* at  = (float*)p;
    cudaGetSymbolAddress(&p, g_ff);  float* ff  = (float*)p;
    cudaGetSymbolAddress(&p, g_hs);  float* hs  = (float*)p;
    cudaGetSymbolAddress(&p, g_cK);  float* cK  = (float*)p;
    cudaGetSymbolAddress(&p, g_cV);  float* cV  = (float*)p;
    cudaGetSymbolAddress(&p, g_dx);  float* dx  = (float*)p;
    cudaGetSymbolAddress(&p, g_dq);  float* dq  = (float*)p;
    cudaGetSymbolAddress(&p, g_dat); float* dat = (float*)p;
    cudaGetSymbolAddress(&p, g_dff); float* dff = (float*)p;
    cudaGetSymbolAddress(&p, g_kc);  float* kc  = (float*)p;
    cudaGetSymbolAddress(&p, g_vc);  float* vc  = (float*)p;
    cudaGetSymbolAddress(&p, g_logits); float* logits = (float*)p;

    // ================= encoder =================
    k_embed<<<M_, 256>>>(ids, emb);
    for (int l = 0; l < L_; l++) {
        k_rms<<<M_, 256>>>(xe, enc_ln1 + l*D_, h);
        k_sgemm<<<dim3(8,4), 256>>>(h, enc_wq + l*DD_, nullptr, q, D_, D_, 0);
        k_sgemm<<<dim3(8,4), 256>>>(h, enc_wk + l*DD_, nullptr, k, D_, D_, 0);
        k_sgemm<<<dim3(8,4), 256>>>(h, enc_wv + l*DD_, nullptr, v, D_, D_, 0);
        k_encattn<<<32, 256>>>(mask);
        k_sgemm<<<dim3(8,4), 256>>>(at, enc_wo + l*DD_, xe, xe, D_, D_, 1);
        k_rms<<<M_, 256>>>(xe, enc_ln2 + l*D_, h);
        k_sgemm<<<dim3(32,4), 256>>>(h, enc_w1 + l*D_*DFF_, nullptr, ff, DFF_, D_, 2);
        k_sgemm<<<dim3(8,4), 256>>>(ff, enc_w2 + l*DFF_*D_, xe, xe, D_, DFF_, 1);
    }
    k_rms<<<M_, 256>>>(xe, enc_lnf, hs);
    for (int l = 0; l < L_; l++) {
        k_sgemm<<<dim3(8,4), 256>>>(hs, dec_ck + l*DD_, nullptr, cK + l*M_*D_, D_, D_, 0);
        k_sgemm<<<dim3(8,4), 256>>>(hs, dec_cv + l*DD_, nullptr, cV + l*M_*D_, D_, D_, 0);
    }

    // ================= decoder (incremental, KV-cached) =================
    k_initdx<<<2, 256>>>(emb);
    for (int t = 0; t < T_; t++) {
        for (int l = 0; l < L_; l++) {
            float* kcb = kc + (size_t)(l*B_*T_ + t) * D_;
            float* vcb = vc + (size_t)(l*B_*T_ + t) * D_;
            // fused QKV (grid.z picks q/k/v); k,v go straight into caches
            k_dgemm<<<dim3(8,1,3), 256>>>(dx, dec_ln1 + l*D_,
                dec_sq + l*DD_, dec_sk + l*DD_, dec_sv + l*DD_,
                dq, kcb, vcb, D_, T_*D_, T_*D_, nullptr, D_, D_, 0);
            k_selfattn<<<32, 64>>>(l, t);
            k_dgemm<<<dim3(8,1,1), 256>>>(dat, nullptr,
                dec_so + l*DD_, dec_so + l*DD_, dec_so + l*DD_,
                dx, dx, dx, D_, D_, D_, dx, D_, D_, 0);
            k_dgemm<<<dim3(8,1,1), 256>>>(dx, dec_ln2 + l*D_,
                dec_cq + l*DD_, dec_cq + l*DD_, dec_cq + l*DD_,
                dq, dq, dq, D_, D_, D_, nullptr, D_, D_, 0);
            k_crossattn<<<32, 64>>>(l, mask);
            k_dgemm<<<dim3(8,1,1), 256>>>(dat, nullptr,
                dec_co + l*DD_, dec_co + l*DD_, dec_co + l*DD_,
                dx, dx, dx, D_, D_, D_, dx, D_, D_, 0);
            k_dgemm<<<dim3(32,1,1), 256>>>(dx, dec_ln3 + l*D_,
                dec_w1 + l*D_*DFF_, dec_w1 + l*D_*DFF_, dec_w1 + l*D_*DFF_,
                dff, dff, dff, DFF_, DFF_, DFF_, nullptr, DFF_, D_, 1);
            k_dgemm<<<dim3(8,1,1), 256>>>(dff, nullptr,
                dec_w2 + l*DFF_*D_, dec_w2 + l*DFF_*D_, dec_w2 + l*DFF_*D_,
                dx, dx, dx, D_, D_, D_, dx, D_, DFF_, 0);
        }
        // lm_head with final norm fused
        k_dgemm<<<dim3(V_/64,1,1), 256>>>(dx, dec_lnf,
            lm_head, lm_head, lm_head,
            logits, logits, logits, V_, V_, V_, nullptr, V_, D_, 0);
        k_softmax<<<B_, 256>>>(out, t);     // also zeroes g_dx
        k_ynext<<<128, 256>>>(emb);         // g_dx = probs @ emb
    }
}

// round 3
// speedup vs baseline: 1.0269x; 1.0269x over previous
#include <cuda_runtime.h>
#include <math.h>

#define B_   4
#define S_   64
#define D_   512
#define H_   8
#define DH_  64
#define DFF_ 2048
#define L_   2
#define V_   32128
#define T_   16
#define M_   256          // B_*S_
#define DD_  (D_*D_)
#define NEG_ (-1e9f)

// ---------------- device scratch (no allocation allowed) ----------------
__device__ float g_xe [M_*D_];       // encoder residual stream
__device__ float g_h  [M_*D_];       // rmsnorm output
__device__ float g_q  [M_*D_];
__device__ float g_k  [M_*D_];
__device__ float g_v  [M_*D_];
__device__ float g_at [M_*D_];       // attn out (pre-projection)
__device__ float g_ff [M_*DFF_];
__device__ float g_hs [M_*D_];       // encoder final output (normed)
__device__ float g_cK [L_*M_*D_];    // cross-attn K per layer
__device__ float g_cV [L_*M_*D_];    // cross-attn V per layer
__device__ float g_dx [B_*D_];       // decoder token residual stream
__device__ float g_dq [B_*D_];       // decoder q (self or cross)
__device__ float g_dat[B_*D_];       // decoder attn out
__device__ float g_dff[B_*DFF_];
__device__ float g_kc [L_*B_*T_*D_]; // self-K cache
__device__ float g_vc [L_*B_*T_*D_]; // self-V cache
__device__ float g_logits[B_*V_];
__device__ float g_probs [B_*V_];

// ---------------- encoder: embedding gather ----------------
__global__ void k_embed(const int* __restrict__ ids, const float* __restrict__ emb) {
    int r = blockIdx.x;
    int id = ids[r];
    for (int d = threadIdx.x; d < D_; d += 256)
        g_xe[r*D_ + d] = emb[id*D_ + d];
}

// ---------------- RMSNorm (one block per row, D=512) ----------------
__global__ void k_rms(const float* __restrict__ x, const float* __restrict__ w,
                      float* __restrict__ out) {
    int r = blockIdx.x;
    __shared__ float red[8];
    float ss = 0.f;
    for (int d = threadIdx.x; d < D_; d += 256) { float v = x[r*D_+d]; ss += v*v; }
    for (int o = 16; o; o >>= 1) ss += __shfl_xor_sync(0xffffffffu, ss, o);
    if ((threadIdx.x & 31) == 0) red[threadIdx.x >> 5] = ss;
    __syncthreads();
    if (threadIdx.x == 0) {
        float t = 0.f;
        for (int i = 0; i < 8; i++) t += red[i];
        red[0] = rsqrtf(t / (float)D_ + 1e-6f);
    }
    __syncthreads();
    float rs = red[0];
    for (int d = threadIdx.x; d < D_; d += 256)
        out[r*D_+d] = x[r*D_+d] * rs * w[d];
}

// ---------------- encoder SGEMM: C[256,N] = A[256,K] @ W[K,N] ----------------
// op bit0: C += res, bit1: relu. 64x64 tile, 4x4 microtile, 256 threads.
__global__ void k_sgemm(const float* __restrict__ A, const float* __restrict__ W,
                        const float* __restrict__ res, float* __restrict__ C,
                        int N, int K, int op) {
    __shared__ float As[16][64];
    __shared__ float Ws[16][64];
    int bx = blockIdx.x * 64, by = blockIdx.y * 64;
    int tx = threadIdx.x & 15, ty = threadIdx.x >> 4;
    float acc[4][4] = {};
    for (int k0 = 0; k0 < K; k0 += 16) {
        for (int i = threadIdx.x; i < 1024; i += 256) {
            int m = i >> 4, kk = i & 15;
            As[kk][m] = A[(by+m)*K + k0 + kk];
        }
        for (int i = threadIdx.x; i < 1024; i += 256) {
            int n = i & 63, kk = i >> 6;
            Ws[kk][n] = W[(k0+kk)*N + bx + n];
        }
        __syncthreads();
        #pragma unroll
        for (int kk = 0; kk < 16; kk++) {
            float a0 = As[kk][ty*4+0], a1 = As[kk][ty*4+1];
            float a2 = As[kk][ty*4+2], a3 = As[kk][ty*4+3];
            float b0 = Ws[kk][tx*4+0], b1 = Ws[kk][tx*4+1];
            float b2 = Ws[kk][tx*4+2], b3 = Ws[kk][tx*4+3];
            acc[0][0] += a0*b0; acc[0][1] += a0*b1; acc[0][2] += a0*b2; acc[0][3] += a0*b3;
            acc[1][0] += a1*b0; acc[1][1] += a1*b1; acc[1][2] += a1*b2; acc[1][3] += a1*b3;
            acc[2][0] += a2*b0; acc[2][1] += a2*b1; acc[2][2] += a2*b2; acc[2][3] += a2*b3;
            acc[3][0] += a3*b0; acc[3][1] += a3*b1; acc[3][2] += a3*b2; acc[3][3] += a3*b3;
        }
        __syncthreads();
    }
    #pragma unroll
    for (int i = 0; i < 4; i++)
        #pragma unroll
        for (int j = 0; j < 4; j++) {
            int m = by + ty*4 + i, n = bx + tx*4 + j;
            float v = acc[i][j];
            if (op & 1) v += res[m*N + n];
            if (op & 2) v = fmaxf(v, 0.f);
            C[m*N + n] = v;
        }
}

// ---------------- encoder attention (one block per (b,h)) ----------------
#define KS(j,d) ks[(j)][((d) ^ ((j) & 31))]
#define SC(i,j) sc[(i)][((j) ^ ((i) & 31))]
__global__ void k_encattn(const float* __restrict__ mask) {
    int b = blockIdx.x >> 3, h = blockIdx.x & 7;
    __shared__ float ks[64][64];   // K, XOR-swizzled
    __shared__ float vs[64][64];   // Q first, then V
    __shared__ float sc[64][64];   // scores, XOR-swizzled
    // load K (swizzled) and Q (plain, into vs)
    for (int i = threadIdx.x; i < 4096; i += 256) {
        int j = i >> 6, d = i & 63;
        KS(j,d) = g_k[(b*64+j)*D_ + h*64 + d];
        vs[j][d] = g_q[(b*64+j)*D_ + h*64 + d];
    }
    __syncthreads();
    // scores
    for (int idx = threadIdx.x; idx < 4096; idx += 256) {
        int i = idx >> 6, j = idx & 63;
        float s = 0.f;
        #pragma unroll 8
        for (int d = 0; d < 64; d++) s += vs[i][d] * KS(j,d);
        SC(i,j) = s * 0.125f + (1.f - mask[b*64 + j]) * NEG_;
    }
    __syncthreads();
    // overwrite vs with V
    for (int i = threadIdx.x; i < 4096; i += 256) {
        int j = i >> 6, d = i & 63;
        vs[j][d] = g_v[(b*64+j)*D_ + h*64 + d];
    }
    __syncthreads();
    // softmax per q-row
    if (threadIdx.x < 64) {
        int i = threadIdx.x;
        float m = -1e30f;
        for (int j = 0; j < 64; j++) m = fmaxf(m, SC(i,j));
        float su = 0.f;
        for (int j = 0; j < 64; j++) { float e = expf(SC(i,j) - m); SC(i,j) = e; su += e; }
        float inv = 1.f / su;
        for (int j = 0; j < 64; j++) SC(i,j) *= inv;
    }
    __syncthreads();
    // out
    for (int idx = threadIdx.x; idx < 4096; idx += 256) {
        int i = idx >> 6, d = idx & 63;
        float o = 0.f;
        #pragma unroll 8
        for (int j = 0; j < 64; j++) o += SC(i,j) * vs[j][d];
        g_at[(b*64+i)*D_ + h*64 + d] = o;
    }
}

// ---------------- decoder GEMM: C[4,N] = rms?(x)[4,K] @ W[K,N] (+res, relu) --
// 256 threads = 64 cols x 4 k-splits. grid.x = N/64, grid.z selects (W,C,rs).
__global__ void k_dgemm(const float* __restrict__ x, const float* __restrict__ ln,
                        const float* __restrict__ W0, const float* __restrict__ W1,
                        const float* __restrict__ W2,
                        float* C0, float* C1, float* C2,
                        int rs0, int rs1, int rs2,
                        const float* __restrict__ res, int N, int K, int relu) {
    const float* W = (blockIdx.z == 0) ? W0 : (blockIdx.z == 1) ? W1 : W2;
    float* C = (blockIdx.z == 0) ? C0 : (blockIdx.z == 1) ? C1 : C2;
    int rs = (blockIdx.z == 0) ? rs0 : (blockIdx.z == 1) ? rs1 : rs2;
    __shared__ float h_s[B_*DFF_];
    __shared__ float ss[B_][64];
    __shared__ float red[16*64];
    int tid = threadIdx.x;
    if (ln) {
        int r = tid >> 6, c = tid & 63;
        float s = 0.f;
        for (int k = c; k < K; k += 64) { float v = x[r*K + k]; s += v*v; }
        ss[r][c] = s;
        __syncthreads();
        if (tid < B_) {
            float t = 0.f;
            for (int c2 = 0; c2 < 64; c2++) t += ss[tid][c2];
            ss[tid][0] = rsqrtf(t / (float)K + 1e-6f);
        }
        __syncthreads();
        for (int i = tid; i < B_*K; i += 256) {
            int r2 = i / K, k = i % K;
            h_s[i] = x[i] * ss[r2][0] * ln[k];
        }
    } else {
        for (int i = tid; i < B_*K; i += 256) h_s[i] = x[i];
    }
    __syncthreads();
    int c  = tid & 63;
    int col = (blockIdx.x << 6) + c;
    int kg = tid >> 6;
    int kq = K >> 2;
    int kbeg = kg * kq, kend = kbeg + kq;
    float a0 = 0.f, a1 = 0.f, a2 = 0.f, a3 = 0.f;
    for (int k = kbeg; k < kend; k++) {
        float w = W[k*N + col];
        a0 += h_s[k]        * w;
        a1 += h_s[K + k]    * w;
        a2 += h_s[2*K + k]  * w;
        a3 += h_s[3*K + k]  * w;
    }
    red[(kg*4+0)*64 + c] = a0;
    red[(kg*4+1)*64 + c] = a1;
    red[(kg*4+2)*64 + c] = a2;
    red[(kg*4+3)*64 + c] = a3;
    __syncthreads();
    if (kg == 0) {
        #pragma unroll
        for (int r = 0; r < 4; r++) {
            float v = red[r*64+c] + red[(4+r)*64+c] + red[(8+r)*64+c] + red[(12+r)*64+c];
            if (res)  v += res[r*N + col];
            if (relu) v = fmaxf(v, 0.f);
            C[r*rs + col] = v;
        }
    }
}

// ---------------- decoder self-attention (cache), 64 threads, block=(b,h) ----
__global__ void k_selfattn(int l, int t) {
    int b = blockIdx.x >> 3, h = blockIdx.x & 7;
    int tid = threadIdx.x;
    __shared__ float p[T_];
    __shared__ float qv[DH_];
    qv[tid] = g_dq[b*D_ + h*DH_ + tid];
    __syncthreads();
    if (tid <= t) {
        const float* kp = &g_kc[((l*B_ + b)*T_ + tid)*D_ + h*DH_];
        float s = 0.f;
        #pragma unroll 8
        for (int d = 0; d < DH_; d++) s += qv[d] * kp[d];
        p[tid] = s * 0.125f;
    }
    __syncthreads();
    if (tid == 0) {
        float m = -1e30f;
        for (int j = 0; j <= t; j++) m = fmaxf(m, p[j]);
        float su = 0.f;
        for (int j = 0; j <= t; j++) { p[j] = expf(p[j] - m); su += p[j]; }
        float inv = 1.f / su;
        for (int j = 0; j <= t; j++) p[j] *= inv;
    }
    __syncthreads();
    float o = 0.f;
    for (int j = 0; j <= t; j++)
        o += p[j] * g_vc[((l*B_ + b)*T_ + j)*D_ + h*DH_ + tid];
    g_dat[b*D_ + h*DH_ + tid] = o;
}

// ---------------- decoder cross-attention, 64 threads, block=(b,h) ----------
__global__ void k_crossattn(int l, const float* __restrict__ mask) {
    int b = blockIdx.x >> 3, h = blockIdx.x & 7;
    int tid = threadIdx.x;
    __shared__ float p[S_];
    __shared__ float qv[DH_];
    qv[tid] = g_dq[b*D_ + h*DH_ + tid];
    __syncthreads();
    {
        const float* kp = &g_cK[l*M_*D_ + (b*S_ + tid)*D_ + h*DH_];
        float s = 0.f;
        #pragma unroll 8
        for (int d = 0; d < DH_; d++) s += qv[d] * kp[d];
        p[tid] = s * 0.125f + (1.f - mask[b*S_ + tid]) * NEG_;
    }
    __syncthreads();
    if (tid == 0) {
        float m = -1e30f;
        for (int j = 0; j < S_; j++) m = fmaxf(m, p[j]);
        float su = 0.f;
        for (int j = 0; j < S_; j++) { p[j] = expf(p[j] - m); su += p[j]; }
        float inv = 1.f / su;
        for (int j = 0; j < S_; j++) p[j] *= inv;
    }
    __syncthreads();
    float o = 0.f;
    for (int j = 0; j < S_; j++)
        o += p[j] * g_cV[l*M_*D_ + (b*S_ + j)*D_ + h*DH_ + tid];
    g_dat[b*D_ + h*DH_ + tid] = o;
}

// ---------------- softmax + argmax + outputs + zero next-x ------------------
__global__ void k_softmax(float* __restrict__ out, int t) {
    int b = blockIdx.x, tid = threadIdx.x;
    __shared__ float sm[256];
    __shared__ int   si[256];
    const float* lg = &g_logits[b*V_];
    float mx = -1e30f; int mi = 0;
    for (int v = tid; v < V_; v += 256) {
        float xv = lg[v];
        if (xv > mx) { mx = xv; mi = v; }
    }
    sm[tid] = mx; si[tid] = mi;
    __syncthreads();
    for (int s = 128; s; s >>= 1) {
        if (tid < s) {
            float xo = sm[tid+s]; int io = si[tid+s];
            if (xo > sm[tid] || (xo == sm[tid] && io < si[tid])) { sm[tid] = xo; si[tid] = io; }
        }
        __syncthreads();
    }
    float rowmax = sm[0];
    int amax = si[0];
    __syncthreads();
    float su = 0.f;
    for (int v = tid; v < V_; v += 256) su += expf(lg[v] - rowmax);
    sm[tid] = su;
    __syncthreads();
    for (int s = 128; s; s >>= 1) { if (tid < s) sm[tid] += sm[tid+s]; __syncthreads(); }
    float inv = 1.f / sm[0];
    float* po = &out[(b*T_ + t)*V_];
    for (int v = tid; v < V_; v += 256) {
        float pv = expf(lg[v] - rowmax) * inv;
        g_probs[b*V_ + v] = pv;
        po[v] = pv;
    }
    if (tid == 0) out[B_*T_*V_ + b*T_ + t] = (amax == 0) ? 1.0f : 0.0f;
    for (int d = tid; d < D_; d += 256) g_dx[b*D_ + d] = 0.f;
}

// ---------------- soft embedding: g_dx += probs @ emb -----------------------
// grid 128 blocks: each streams 251 vocab rows of emb. 32128 = 128*251.
__global__ void k_ynext(const float* __restrict__ emb) {
    __shared__ float ps[B_][251];
    int tid = threadIdx.x;
    int v0 = blockIdx.x * 251;
    for (int i = tid; i < B_*251; i += 256) {
        int b = i / 251, j = i % 251;
        ps[b][j] = g_probs[b*V_ + v0 + j];
    }
    __syncthreads();
    int c0 = tid, c1 = tid + 256;
    float a00=0,a01=0,a10=0,a11=0,a20=0,a21=0,a30=0,a31=0;
    for (int j = 0; j < 251; j++) {
        const float* er = &emb[(size_t)(v0 + j) * D_];
        float e0 = er[c0], e1 = er[c1];
        a00 += ps[0][j]*e0; a01 += ps[0][j]*e1;
        a10 += ps[1][j]*e0; a11 += ps[1][j]*e1;
        a20 += ps[2][j]*e0; a21 += ps[2][j]*e1;
        a30 += ps[3][j]*e0; a31 += ps[3][j]*e1;
    }
    atomicAdd(&g_dx[0*D_+c0], a00); atomicAdd(&g_dx[0*D_+c1], a01);
    atomicAdd(&g_dx[1*D_+c0], a10); atomicAdd(&g_dx[1*D_+c1], a11);
    atomicAdd(&g_dx[2*D_+c0], a20); atomicAdd(&g_dx[2*D_+c1], a21);
    atomicAdd(&g_dx[3*D_+c0], a30); atomicAdd(&g_dx[3*D_+c1], a31);
}

// ---------------- init decoder x with pad embedding -------------------------
__global__ void k_initdx(const float* __restrict__ emb) {
    int d = threadIdx.x + blockIdx.x * 256;   // grid 2 x 256 = 512
    float v = emb[d];                          // PAD_ID = 0 -> row 0
    for (int b = 0; b < B_; b++) g_dx[b*D_ + d] = v;
}

// ---------------- host driver ----------------
extern "C" void kernel_launch(void* const* d_in, const int* in_sizes, int n_in,
                              void* d_out, int out_size) {
    const int*   ids     = (const int*)  d_in[0];
    const float* mask    = (const float*)d_in[1];
    const float* emb     = (const float*)d_in[2];
    const float* enc_wq  = (const float*)d_in[3];
    const float* enc_wk  = (const float*)d_in[4];
    const float* enc_wv  = (const float*)d_in[5];
    const float* enc_wo  = (const float*)d_in[6];
    const float* enc_ln1 = (const float*)d_in[7];
    const float* enc_w1  = (const float*)d_in[8];
    const float* enc_w2  = (const float*)d_in[9];
    const float* enc_ln2 = (const float*)d_in[10];
    const float* enc_lnf = (const float*)d_in[11];
    const float* dec_sq  = (const float*)d_in[12];
    const float* dec_sk  = (const float*)d_in[13];
    const float* dec_sv  = (const float*)d_in[14];
    const float* dec_so  = (const float*)d_in[15];
    const float* dec_ln1 = (const float*)d_in[16];
    const float* dec_cq  = (const float*)d_in[17];
    const float* dec_ck  = (const float*)d_in[18];
    const float* dec_cv  = (const float*)d_in[19];
    const float* dec_co  = (const float*)d_in[20];
    const float* dec_ln2 = (const float*)d_in[21];
    const float* dec_w1  = (const float*)d_in[22];
    const float* dec_w2  = (const float*)d_in[23];
    const float* dec_ln3 = (const float*)d_in[24];
    const float* dec_lnf = (const float*)d_in[25];
    const float* lm_head = (const float*)d_in[26];
    float* out = (float*)d_out;

    void* p;
    cudaGetSymbolAddress(&p, g_xe);  float* xe  = (float*)p;
    cudaGetSymbolAddress(&p, g_h);   float* h   = (float*)p;
    cudaGetSymbolAddress(&p, g_q);   float* q   = (float*)p;
    cudaGetSymbolAddress(&p, g_k);   float* k   = (float*)p;
    cudaGetSymbolAddress(&p, g_v);   float* v   = (float*)p;
    cudaGetSymbolAddress(&p, g_at);  float* at  = (float*)p;
    cudaGetSymbolAddress(&p, g_ff);  float* ff  = (float*)p;
    cudaGetSymbolAddress(&p, g_hs);  float* hs  = (float*)p;
    cudaGetSymbolAddress(&p, g_cK);  float* cK  = (float*)p;
    cudaGetSymbolAddress(&p, g_cV);  float* cV  = (float*)p;
    cudaGetSymbolAddress(&p, g_dx);  float* dx  = (float*)p;
    cudaGetSymbolAddress(&p, g_dq);  float* dq  = (float*)p;
    cudaGetSymbolAddress(&p, g_dat); float* dat = (float*)p;
    cudaGetSymbolAddress(&p, g_dff); float* dff = (float*)p;
    cudaGetSymbolAddress(&p, g_kc);  float* kc  = (float*)p;
    cudaGetSymbolAddress(&p, g_vc);  float* vc  = (float*)p;
    cudaGetSymbolAddress(&p, g_logits); float* logits = (float*)p;

    // ================= encoder =================
    k_embed<<<M_, 256>>>(ids, emb);
    for (int l = 0; l < L_; l++) {
        k_rms<<<M_, 256>>>(xe, enc_ln1 + l*D_, h);
        k_sgemm<<<dim3(8,4), 256>>>(h, enc_wq + l*DD_, nullptr, q, D_, D_, 0);
        k_sgemm<<<dim3(8,4), 256>>>(h, enc_wk + l*DD_, nullptr, k, D_, D_, 0);
        k_sgemm<<<dim3(8,4), 256>>>(h, enc_wv + l*DD_, nullptr, v, D_, D_, 0);
        k_encattn<<<32, 256>>>(mask);
        k_sgemm<<<dim3(8,4), 256>>>(at, enc_wo + l*DD_, xe, xe, D_, D_, 1);
        k_rms<<<M_, 256>>>(xe, enc_ln2 + l*D_, h);
        k_sgemm<<<dim3(32,4), 256>>>(h, enc_w1 + l*D_*DFF_, nullptr, ff, DFF_, D_, 2);
        k_sgemm<<<dim3(8,4), 256>>>(ff, enc_w2 + l*DFF_*D_, xe, xe, D_, DFF_, 1);
    }
    k_rms<<<M_, 256>>>(xe, enc_lnf, hs);
    for (int l = 0; l < L_; l++) {
        k_sgemm<<<dim3(8,4), 256>>>(hs, dec_ck + l*DD_, nullptr, cK + l*M_*D_, D_, D_, 0);
        k_sgemm<<<dim3(8,4), 256>>>(hs, dec_cv + l*DD_, nullptr, cV + l*M_*D_, D_, D_, 0);
    }

    // ================= decoder (incremental, KV-cached) =================
    k_initdx<<<2, 256>>>(emb);
    for (int t = 0; t < T_; t++) {
        for (int l = 0; l < L_; l++) {
            float* kcb = kc + (size_t)(l*B_*T_ + t) * D_;
            float* vcb = vc + (size_t)(l*B_*T_ + t) * D_;
            // fused QKV (grid.z picks q/k/v); k,v go straight into caches
            k_dgemm<<<dim3(8,1,3), 256>>>(dx, dec_ln1 + l*D_,
                dec_sq + l*DD_, dec_sk + l*DD_, dec_sv + l*DD_,
                dq, kcb, vcb, D_, T_*D_, T_*D_, nullptr, D_, D_, 0);
            k_selfattn<<<32, 64>>>(l, t);
            k_dgemm<<<dim3(8,1,1), 256>>>(dat, nullptr,
                dec_so + l*DD_, dec_so + l*DD_, dec_so + l*DD_,
                dx, dx, dx, D_, D_, D_, dx, D_, D_, 0);
            k_dgemm<<<dim3(8,1,1), 256>>>(dx, dec_ln2 + l*D_,
                dec_cq + l*DD_, dec_cq + l*DD_, dec_cq + l*DD_,
                dq, dq, dq, D_, D_, D_, nullptr, D_, D_, 0);
            k_crossattn<<<32, 64>>>(l, mask);
            k_dgemm<<<dim3(8,1,1), 256>>>(dat, nullptr,
                dec_co + l*DD_, dec_co + l*DD_, dec_co + l*DD_,
                dx, dx, dx, D_, D_, D_, dx, D_, D_, 0);
            k_dgemm<<<dim3(32,1,1), 256>>>(dx, dec_ln3 + l*D_,
                dec_w1 + l*D_*DFF_, dec_w1 + l*D_*DFF_, dec_w1 + l*D_*DFF_,
                dff, dff, dff, DFF_, DFF_, DFF_, nullptr, DFF_, D_, 1);
            k_dgemm<<<dim3(8,1,1), 256>>>(dff, nullptr,
                dec_w2 + l*DFF_*D_, dec_w2 + l*DFF_*D_, dec_w2 + l*DFF_*D_,
                dx, dx, dx, D_, D_, D_, dx, D_, DFF_, 0);
        }
        // lm_head with final norm fused
        k_dgemm<<<dim3(V_/64,1,1), 256>>>(dx, dec_lnf,
            lm_head, lm_head, lm_head,
            logits, logits, logits, V_, V_, V_, nullptr, V_, D_, 0);
        k_softmax<<<B_, 256>>>(out, t);     // also zeroes g_dx
        k_ynext<<<128, 256>>>(emb);         // g_dx = probs @ emb
    }
}

// round 4
// speedup vs baseline: 1.1696x; 1.1389x over previous
#include <cuda_runtime.h>
#include <math.h>

#define B_   4
#define S_   64
#define D_   512
#define H_   8
#define DH_  64
#define DFF_ 2048
#define L_   2
#define V_   32128
#define T_   16
#define M_   256          // B_*S_
#define DD_  (D_*D_)
#define NEG_ (-1e9f)

// ---------------- device scratch (no allocation allowed) ----------------
__device__ float g_xe [M_*D_];
__device__ float g_h  [M_*D_];
__device__ float g_q  [M_*D_];
__device__ float g_k  [M_*D_];
__device__ float g_v  [M_*D_];
__device__ float g_at [M_*D_];
__device__ float g_ff [M_*DFF_];
__device__ float g_hs [M_*D_];
__device__ float g_cK [L_*M_*D_];
__device__ float g_cV [L_*M_*D_];
__device__ float g_dx [B_*D_];
__device__ float g_dq [B_*D_];
__device__ float g_dat[B_*D_];
__device__ float g_dff[B_*DFF_];
__device__ float g_kc [L_*B_*T_*D_];
__device__ float g_vc [L_*B_*T_*D_];
__device__ float g_logits[B_*V_];
__device__ float g_probs [B_*V_];

// ---------------- embedding gather ----------------
__global__ void k_embed(const int* __restrict__ ids, const float* __restrict__ emb) {
    int r = blockIdx.x;
    int id = ids[r];
    for (int d = threadIdx.x; d < D_; d += 256)
        g_xe[r*D_ + d] = emb[id*D_ + d];
}

// ---------------- RMSNorm (one block per row) ----------------
__global__ void k_rms(const float* __restrict__ x, const float* __restrict__ w,
                      float* __restrict__ out) {
    int r = blockIdx.x;
    __shared__ float red[8];
    float ss = 0.f;
    for (int d = threadIdx.x; d < D_; d += 256) { float v = x[r*D_+d]; ss += v*v; }
    for (int o = 16; o; o >>= 1) ss += __shfl_xor_sync(0xffffffffu, ss, o);
    if ((threadIdx.x & 31) == 0) red[threadIdx.x >> 5] = ss;
    __syncthreads();
    if (threadIdx.x == 0) {
        float t = 0.f;
        for (int i = 0; i < 8; i++) t += red[i];
        red[0] = rsqrtf(t / (float)D_ + 1e-6f);
    }
    __syncthreads();
    float rs = red[0];
    for (int d = threadIdx.x; d < D_; d += 256)
        out[r*D_+d] = x[r*D_+d] * rs * w[d];
}

// ---------------- encoder SGEMM ----------------
// C[M,N] = A[M,K] @ W[K,N]. 32x64 tile, 2x4 microtile, 256 threads.
// Ping-pong smem double buffering, float4 global loads.
// grid = (N/64, M/32, nz); z selects (W,C). op bit0: +res, bit1: relu.
__global__ void k_sgemm(const float* __restrict__ A,
                        const float* __restrict__ W0, const float* __restrict__ W1,
                        const float* __restrict__ W2,
                        float* __restrict__ C0, float* __restrict__ C1, float* __restrict__ C2,
                        const float* __restrict__ res, int N, int K, int op) {
    const float* __restrict__ W = (blockIdx.z == 0) ? W0 : (blockIdx.z == 1) ? W1 : W2;
    float* __restrict__ C = (blockIdx.z == 0) ? C0 : (blockIdx.z == 1) ? C1 : C2;
    __shared__ float As[2][16][33];   // [buf][kk][m] padded
    __shared__ float Ws[2][16][64];   // [buf][kk][n]
    int bx = blockIdx.x * 64, by = blockIdx.y * 32;
    int tid = threadIdx.x;
    int tx = tid & 15, ty = tid >> 4;
    int ar = tid >> 2, aq = tid & 3;      // A loader: row 0..31 (tid<128), quad 0..3
    int NT = K >> 4;

    float4 ra, rw;
    if (tid < 128) ra = *(const float4*)&A[(by+ar)*K + aq*4];
    rw = *(const float4*)&W[ty*N + bx + tx*4];
    if (tid < 128) {
        As[0][aq*4+0][ar] = ra.x; As[0][aq*4+1][ar] = ra.y;
        As[0][aq*4+2][ar] = ra.z; As[0][aq*4+3][ar] = ra.w;
    }
    *(float4*)&Ws[0][ty][tx*4] = rw;
    __syncthreads();

    float acc[2][4] = {};
    int buf = 0;
    for (int kt = 0; kt < NT; kt++) {
        bool pf = (kt + 1 < NT);
        if (pf) {
            int k0 = (kt + 1) << 4;
            if (tid < 128) ra = *(const float4*)&A[(by+ar)*K + k0 + aq*4];
            rw = *(const float4*)&W[(k0+ty)*N + bx + tx*4];
        }
        #pragma unroll
        for (int kk = 0; kk < 16; kk++) {
            float a0 = As[buf][kk][ty*2+0];
            float a1 = As[buf][kk][ty*2+1];
            float4 b = *(const float4*)&Ws[buf][kk][tx*4];
            acc[0][0] = fmaf(a0, b.x, acc[0][0]); acc[0][1] = fmaf(a0, b.y, acc[0][1]);
            acc[0][2] = fmaf(a0, b.z, acc[0][2]); acc[0][3] = fmaf(a0, b.w, acc[0][3]);
            acc[1][0] = fmaf(a1, b.x, acc[1][0]); acc[1][1] = fmaf(a1, b.y, acc[1][1]);
            acc[1][2] = fmaf(a1, b.z, acc[1][2]); acc[1][3] = fmaf(a1, b.w, acc[1][3]);
        }
        if (pf) {
            int nb = buf ^ 1;
            if (tid < 128) {
                As[nb][aq*4+0][ar] = ra.x; As[nb][aq*4+1][ar] = ra.y;
                As[nb][aq*4+2][ar] = ra.z; As[nb][aq*4+3][ar] = ra.w;
            }
            *(float4*)&Ws[nb][ty][tx*4] = rw;
            __syncthreads();
            buf = nb;
        }
    }
    #pragma unroll
    for (int i = 0; i < 2; i++) {
        int m = by + ty*2 + i, n = bx + tx*4;
        float4 v = make_float4(acc[i][0], acc[i][1], acc[i][2], acc[i][3]);
        if (op & 1) {
            float4 r4 = *(const float4*)&res[m*N + n];
            v.x += r4.x; v.y += r4.y; v.z += r4.z; v.w += r4.w;
        }
        if (op & 2) {
            v.x = fmaxf(v.x, 0.f); v.y = fmaxf(v.y, 0.f);
            v.z = fmaxf(v.z, 0.f); v.w = fmaxf(v.w, 0.f);
        }
        *(float4*)&C[m*N + n] = v;
    }
}

// ---------------- encoder attention (one block per (b,h)) ----------------
#define KS(j,d) ks[(j)][((d) ^ ((j) & 31))]
#define SC(i,j) sc[(i)][((j) ^ ((i) & 31))]
__global__ void k_encattn(const float* __restrict__ mask) {
    int b = blockIdx.x >> 3, h = blockIdx.x & 7;
    __shared__ float ks[64][64];
    __shared__ float vs[64][64];
    __shared__ float sc[64][64];
    for (int i = threadIdx.x; i < 4096; i += 256) {
        int j = i >> 6, d = i & 63;
        KS(j,d) = g_k[(b*64+j)*D_ + h*64 + d];
        vs[j][d] = g_q[(b*64+j)*D_ + h*64 + d];
    }
    __syncthreads();
    for (int idx = threadIdx.x; idx < 4096; idx += 256) {
        int i = idx >> 6, j = idx & 63;
        float s = 0.f;
        #pragma unroll 16
        for (int d = 0; d < 64; d++) s = fmaf(vs[i][d], KS(j,d), s);
        SC(i,j) = s * 0.125f + (1.f - mask[b*64 + j]) * NEG_;
    }
    __syncthreads();
    for (int i = threadIdx.x; i < 4096; i += 256) {
        int j = i >> 6, d = i & 63;
        vs[j][d] = g_v[(b*64+j)*D_ + h*64 + d];
    }
    __syncthreads();
    if (threadIdx.x < 64) {
        int i = threadIdx.x;
        float m = -1e30f;
        for (int j = 0; j < 64; j++) m = fmaxf(m, SC(i,j));
        float su = 0.f;
        for (int j = 0; j < 64; j++) { float e = __expf(SC(i,j) - m); SC(i,j) = e; su += e; }
        float inv = 1.f / su;
        for (int j = 0; j < 64; j++) SC(i,j) *= inv;
    }
    __syncthreads();
    for (int idx = threadIdx.x; idx < 4096; idx += 256) {
        int i = idx >> 6, d = idx & 63;
        float o = 0.f;
        #pragma unroll 16
        for (int j = 0; j < 64; j++) o = fmaf(SC(i,j), vs[j][d], o);
        g_at[(b*64+i)*D_ + h*64 + d] = o;
    }
}

// ---------------- decoder matvec: C[4,N] = rms?(x)[4,K] @ W[K,N] ------------
// 256 threads = 64 cols x 4 k-splits, unroll-8 pipelined weight streaming.
__global__ void k_dgemm(const float* __restrict__ x, const float* __restrict__ ln,
                        const float* __restrict__ W0, const float* __restrict__ W1,
                        const float* __restrict__ W2,
                        float* C0, float* C1, float* C2,
                        int rs0, int rs1, int rs2,
                        const float* __restrict__ res, int N, int K, int relu) {
    const float* __restrict__ W = (blockIdx.z == 0) ? W0 : (blockIdx.z == 1) ? W1 : W2;
    float* C = (blockIdx.z == 0) ? C0 : (blockIdx.z == 1) ? C1 : C2;
    int rs = (blockIdx.z == 0) ? rs0 : (blockIdx.z == 1) ? rs1 : rs2;
    __shared__ float h_s[B_*DFF_];
    __shared__ float ss[B_][64];
    __shared__ float red[16*64];
    int tid = threadIdx.x;
    if (ln) {
        int r = tid >> 6, c = tid & 63;
        float s = 0.f;
        #pragma unroll 4
        for (int k = c; k < K; k += 64) { float v = x[r*K + k]; s += v*v; }
        ss[r][c] = s;
        __syncthreads();
        if (tid < B_) {
            float t = 0.f;
            for (int c2 = 0; c2 < 64; c2++) t += ss[tid][c2];
            ss[tid][0] = rsqrtf(t / (float)K + 1e-6f);
        }
        __syncthreads();
        #pragma unroll 4
        for (int i = tid; i < B_*K; i += 256) {
            int r2 = i / K, k = i % K;
            h_s[i] = x[i] * ss[r2][0] * ln[k];
        }
    } else {
        #pragma unroll 4
        for (int i = tid; i < B_*K; i += 256) h_s[i] = x[i];
    }
    __syncthreads();
    int c   = tid & 63;
    int col = (blockIdx.x << 6) + c;
    int kg  = tid >> 6;
    int kq  = K >> 2;
    int kbeg = kg * kq, kend = kbeg + kq;
    const float* hp0 = h_s;
    const float* hp1 = h_s + K;
    const float* hp2 = h_s + 2*K;
    const float* hp3 = h_s + 3*K;
    float a0 = 0.f, a1 = 0.f, a2 = 0.f, a3 = 0.f;
    for (int k = kbeg; k < kend; k += 8) {          // kq is always a multiple of 8
        float w[8];
        #pragma unroll
        for (int u = 0; u < 8; u++) w[u] = W[(k+u)*N + col];
        #pragma unroll
        for (int u = 0; u < 8; u++) {
            a0 = fmaf(hp0[k+u], w[u], a0);
            a1 = fmaf(hp1[k+u], w[u], a1);
            a2 = fmaf(hp2[k+u], w[u], a2);
            a3 = fmaf(hp3[k+u], w[u], a3);
        }
    }
    red[(kg*4+0)*64 + c] = a0;
    red[(kg*4+1)*64 + c] = a1;
    red[(kg*4+2)*64 + c] = a2;
    red[(kg*4+3)*64 + c] = a3;
    __syncthreads();
    if (kg == 0) {
        #pragma unroll
        for (int r = 0; r < 4; r++) {
            float v = red[r*64+c] + red[(4+r)*64+c] + red[(8+r)*64+c] + red[(12+r)*64+c];
            if (res)  v += res[r*N + col];
            if (relu) v = fmaxf(v, 0.f);
            C[r*rs + col] = v;
        }
    }
}

// ---------------- decoder self-attention (cache), block=(b,h) ----------
__global__ void k_selfattn(int l, int t) {
    int b = blockIdx.x >> 3, h = blockIdx.x & 7;
    int tid = threadIdx.x;
    __shared__ float p[T_];
    __shared__ float qv[DH_];
    qv[tid] = g_dq[b*D_ + h*DH_ + tid];
    __syncthreads();
    if (tid <= t) {
        const float* kp = &g_kc[((l*B_ + b)*T_ + tid)*D_ + h*DH_];
        float s = 0.f;
        #pragma unroll 16
        for (int d = 0; d < DH_; d++) s = fmaf(qv[d], kp[d], s);
        p[tid] = s * 0.125f;
    }
    __syncthreads();
    if (tid == 0) {
        float m = -1e30f;
        for (int j = 0; j <= t; j++) m = fmaxf(m, p[j]);
        float su = 0.f;
        for (int j = 0; j <= t; j++) { p[j] = __expf(p[j] - m); su += p[j]; }
        float inv = 1.f / su;
        for (int j = 0; j <= t; j++) p[j] *= inv;
    }
    __syncthreads();
    float o = 0.f;
    for (int j = 0; j <= t; j++)
        o = fmaf(p[j], g_vc[((l*B_ + b)*T_ + j)*D_ + h*DH_ + tid], o);
    g_dat[b*D_ + h*DH_ + tid] = o;
}

// ---------------- decoder cross-attention, block=(b,h) ----------
__global__ void k_crossattn(int l, const float* __restrict__ mask) {
    int b = blockIdx.x >> 3, h = blockIdx.x & 7;
    int tid = threadIdx.x;
    __shared__ float p[S_];
    __shared__ float qv[DH_];
    qv[tid] = g_dq[b*D_ + h*DH_ + tid];
    __syncthreads();
    {
        const float* kp = &g_cK[l*M_*D_ + (b*S_ + tid)*D_ + h*DH_];
        float s = 0.f;
        #pragma unroll 16
        for (int d = 0; d < DH_; d++) s = fmaf(qv[d], kp[d], s);
        p[tid] = s * 0.125f + (1.f - mask[b*S_ + tid]) * NEG_;
    }
    __syncthreads();
    if (tid == 0) {
        float m = -1e30f;
        for (int j = 0; j < S_; j++) m = fmaxf(m, p[j]);
        float su = 0.f;
        for (int j = 0; j < S_; j++) { p[j] = __expf(p[j] - m); su += p[j]; }
        float inv = 1.f / su;
        for (int j = 0; j < S_; j++) p[j] *= inv;
    }
    __syncthreads();
    float o = 0.f;
    for (int j = 0; j < S_; j++)
        o = fmaf(p[j], g_cV[l*M_*D_ + (b*S_ + j)*D_ + h*DH_ + tid], o);
    g_dat[b*D_ + h*DH_ + tid] = o;
}

// ---------------- softmax + argmax + outputs + zero next-x ------------------
__global__ void k_softmax(float* __restrict__ out, int t) {
    int b = blockIdx.x, tid = threadIdx.x;
    __shared__ float sm[256];
    __shared__ int   si[256];
    const float* lg = &g_logits[b*V_];
    float mx = -1e30f; int mi = 0;
    for (int v0 = tid; v0 < V_; v0 += 2048) {
        float x[8];
        #pragma unroll
        for (int u = 0; u < 8; u++) {
            int v = v0 + u*256;
            x[u] = (v < V_) ? lg[v] : -1e30f;
        }
        #pragma unroll
        for (int u = 0; u < 8; u++) {
            int v = v0 + u*256;
            if (x[u] > mx) { mx = x[u]; mi = v; }
        }
    }
    sm[tid] = mx; si[tid] = mi;
    __syncthreads();
    for (int s = 128; s; s >>= 1) {
        if (tid < s) {
            float xo = sm[tid+s]; int io = si[tid+s];
            if (xo > sm[tid] || (xo == sm[tid] && io < si[tid])) { sm[tid] = xo; si[tid] = io; }
        }
        __syncthreads();
    }
    float rowmax = sm[0];
    int amax = si[0];
    __syncthreads();
    float su = 0.f;
    for (int v0 = tid; v0 < V_; v0 += 2048) {
        float x[8];
        #pragma unroll
        for (int u = 0; u < 8; u++) {
            int v = v0 + u*256;
            x[u] = (v < V_) ? lg[v] : -1e30f;
        }
        #pragma unroll
        for (int u = 0; u < 8; u++) su += __expf(x[u] - rowmax);
    }
    sm[tid] = su;
    __syncthreads();
    for (int s = 128; s; s >>= 1) { if (tid < s) sm[tid] += sm[tid+s]; __syncthreads(); }
    float inv = 1.f / sm[0];
    float* po = &out[(b*T_ + t)*V_];
    for (int v0 = tid; v0 < V_; v0 += 1024) {
        float x[4];
        #pragma unroll
        for (int u = 0; u < 4; u++) {
            int v = v0 + u*256;
            x[u] = (v < V_) ? lg[v] : 0.f;
        }
        #pragma unroll
        for (int u = 0; u < 4; u++) {
            int v = v0 + u*256;
            if (v < V_) {
                float pv = __expf(x[u] - rowmax) * inv;
                g_probs[b*V_ + v] = pv;
                po[v] = pv;
            }
        }
    }
    if (tid == 0) out[B_*T_*V_ + b*T_ + t] = (amax == 0) ? 1.0f : 0.0f;
    for (int d = tid; d < D_; d += 256) g_dx[b*D_ + d] = 0.f;
}

// ---------------- soft embedding: g_dx += probs @ emb -----------------------
// 128 blocks x 251 vocab rows each (32128 = 128*251).
__global__ void k_ynext(const float* __restrict__ emb) {
    __shared__ float ps[B_][251];
    int tid = threadIdx.x;
    int v0 = blockIdx.x * 251;
    for (int i = tid; i < B_*251; i += 256) {
        int b = i / 251, j = i % 251;
        ps[b][j] = g_probs[b*V_ + v0 + j];
    }
    __syncthreads();
    int c0 = tid, c1 = tid + 256;
    float a00=0,a01=0,a10=0,a11=0,a20=0,a21=0,a30=0,a31=0;
    int j = 0;
    for (; j + 4 <= 251; j += 4) {
        float e0[4], e1[4];
        #pragma unroll
        for (int u = 0; u < 4; u++) {
            const float* er = &emb[(size_t)(v0 + j + u) * D_];
            e0[u] = er[c0]; e1[u] = er[c1];
        }
        #pragma unroll
        for (int u = 0; u < 4; u++) {
            float p0 = ps[0][j+u], p1 = ps[1][j+u], p2 = ps[2][j+u], p3 = ps[3][j+u];
            a00 = fmaf(p0, e0[u], a00); a01 = fmaf(p0, e1[u], a01);
            a10 = fmaf(p1, e0[u], a10); a11 = fmaf(p1, e1[u], a11);
            a20 = fmaf(p2, e0[u], a20); a21 = fmaf(p2, e1[u], a21);
            a30 = fmaf(p3, e0[u], a30); a31 = fmaf(p3, e1[u], a31);
        }
    }
    for (; j < 251; j++) {
        const float* er = &emb[(size_t)(v0 + j) * D_];
        float e0 = er[c0], e1 = er[c1];
        a00 = fmaf(ps[0][j], e0, a00); a01 = fmaf(ps[0][j], e1, a01);
        a10 = fmaf(ps[1][j], e0, a10); a11 = fmaf(ps[1][j], e1, a11);
        a20 = fmaf(ps[2][j], e0, a20); a21 = fmaf(ps[2][j], e1, a21);
        a30 = fmaf(ps[3][j], e0, a30); a31 = fmaf(ps[3][j], e1, a31);
    }
    atomicAdd(&g_dx[0*D_+c0], a00); atomicAdd(&g_dx[0*D_+c1], a01);
    atomicAdd(&g_dx[1*D_+c0], a10); atomicAdd(&g_dx[1*D_+c1], a11);
    atomicAdd(&g_dx[2*D_+c0], a20); atomicAdd(&g_dx[2*D_+c1], a21);
    atomicAdd(&g_dx[3*D_+c0], a30); atomicAdd(&g_dx[3*D_+c1], a31);
}

// ---------------- init decoder x with pad embedding -------------------------
__global__ void k_initdx(const float* __restrict__ emb) {
    int d = threadIdx.x + blockIdx.x * 256;
    float v = emb[d];   // PAD_ID = 0
    for (int b = 0; b < B_; b++) g_dx[b*D_ + d] = v;
}

// ---------------- host driver ----------------
extern "C" void kernel_launch(void* const* d_in, const int* in_sizes, int n_in,
                              void* d_out, int out_size) {
    const int*   ids     = (const int*)  d_in[0];
    const float* mask    = (const float*)d_in[1];
    const float* emb     = (const float*)d_in[2];
    const float* enc_wq  = (const float*)d_in[3];
    const float* enc_wk  = (const float*)d_in[4];
    const float* enc_wv  = (const float*)d_in[5];
    const float* enc_wo  = (const float*)d_in[6];
    const float* enc_ln1 = (const float*)d_in[7];
    const float* enc_w1  = (const float*)d_in[8];
    const float* enc_w2  = (const float*)d_in[9];
    const float* enc_ln2 = (const float*)d_in[10];
    const float* enc_lnf = (const float*)d_in[11];
    const float* dec_sq  = (const float*)d_in[12];
    const float* dec_sk  = (const float*)d_in[13];
    const float* dec_sv  = (const float*)d_in[14];
    const float* dec_so  = (const float*)d_in[15];
    const float* dec_ln1 = (const float*)d_in[16];
    const float* dec_cq  = (const float*)d_in[17];
    const float* dec_ck  = (const float*)d_in[18];
    const float* dec_cv  = (const float*)d_in[19];
    const float* dec_co  = (const float*)d_in[20];
    const float* dec_ln2 = (const float*)d_in[21];
    const float* dec_w1  = (const float*)d_in[22];
    const float* dec_w2  = (const float*)d_in[23];
    const float* dec_ln3 = (const float*)d_in[24];
    const float* dec_lnf = (const float*)d_in[25];
    const float* lm_head = (const float*)d_in[26];
    float* out = (float*)d_out;

    void* p;
    cudaGetSymbolAddress(&p, g_xe);  float* xe  = (float*)p;
    cudaGetSymbolAddress(&p, g_h);   float* h   = (float*)p;
    cudaGetSymbolAddress(&p, g_q);   float* q   = (float*)p;
    cudaGetSymbolAddress(&p, g_k);   float* k   = (float*)p;
    cudaGetSymbolAddress(&p, g_v);   float* v   = (float*)p;
    cudaGetSymbolAddress(&p, g_at);  float* at  = (float*)p;
    cudaGetSymbolAddress(&p, g_ff);  float* ff  = (float*)p;
    cudaGetSymbolAddress(&p, g_hs);  float* hs  = (float*)p;
    cudaGetSymbolAddress(&p, g_cK);  float* cK  = (float*)p;
    cudaGetSymbolAddress(&p, g_cV);  float* cV  = (float*)p;
    cudaGetSymbolAddress(&p, g_dx);  float* dx  = (float*)p;
    cudaGetSymbolAddress(&p, g_dq);  float* dq  = (float*)p;
    cudaGetSymbolAddress(&p, g_dat); float* dat = (float*)p;
    cudaGetSymbolAddress(&p, g_dff); float* dff = (float*)p;
    cudaGetSymbolAddress(&p, g_kc);  float* kc  = (float*)p;
    cudaGetSymbolAddress(&p, g_vc);  float* vc  = (float*)p;
    cudaGetSymbolAddress(&p, g_logits); float* logits = (float*)p;

    // ================= encoder =================
    k_embed<<<M_, 256>>>(ids, emb);
    for (int l = 0; l < L_; l++) {
        k_rms<<<M_, 256>>>(xe, enc_ln1 + l*D_, h);
        k_sgemm<<<dim3(8,8,3), 256>>>(h, enc_wq + l*DD_, enc_wk + l*DD_, enc_wv + l*DD_,
                                      q, k, v, nullptr, D_, D_, 0);
        k_encattn<<<32, 256>>>(mask);
        k_sgemm<<<dim3(8,8,1), 256>>>(at, enc_wo + l*DD_, enc_wo + l*DD_, enc_wo + l*DD_,
                                      xe, xe, xe, xe, D_, D_, 1);
        k_rms<<<M_, 256>>>(xe, enc_ln2 + l*D_, h);
        k_sgemm<<<dim3(32,8,1), 256>>>(h, enc_w1 + l*D_*DFF_, enc_w1 + l*D_*DFF_, enc_w1 + l*D_*DFF_,
                                       ff, ff, ff, nullptr, DFF_, D_, 2);
        k_sgemm<<<dim3(8,8,1), 256>>>(ff, enc_w2 + l*DFF_*D_, enc_w2 + l*DFF_*D_, enc_w2 + l*DFF_*D_,
                                      xe, xe, xe, xe, D_, DFF_, 1);
    }
    k_rms<<<M_, 256>>>(xe, enc_lnf, hs);
    for (int l = 0; l < L_; l++) {
        k_sgemm<<<dim3(8,8,2), 256>>>(hs, dec_ck + l*DD_, dec_cv + l*DD_, dec_cv + l*DD_,
                                      cK + l*M_*D_, cV + l*M_*D_, cV + l*M_*D_,
                                      nullptr, D_, D_, 0);
    }

    // ================= decoder (incremental, KV-cached) =================
    k_initdx<<<2, 256>>>(emb);
    for (int t = 0; t < T_; t++) {
        for (int l = 0; l < L_; l++) {
            float* kcb = kc + (size_t)(l*B_*T_ + t) * D_;
            float* vcb = vc + (size_t)(l*B_*T_ + t) * D_;
            k_dgemm<<<dim3(8,1,3), 256>>>(dx, dec_ln1 + l*D_,
                dec_sq + l*DD_, dec_sk + l*DD_, dec_sv + l*DD_,
                dq, kcb, vcb, D_, T_*D_, T_*D_, nullptr, D_, D_, 0);
            k_selfattn<<<32, 64>>>(l, t);
            k_dgemm<<<dim3(8,1,1), 256>>>(dat, nullptr,
                dec_so + l*DD_, dec_so + l*DD_, dec_so + l*DD_,
                dx, dx, dx, D_, D_, D_, dx, D_, D_, 0);
            k_dgemm<<<dim3(8,1,1), 256>>>(dx, dec_ln2 + l*D_,
                dec_cq + l*DD_, dec_cq + l*DD_, dec_cq + l*DD_,
                dq, dq, dq, D_, D_, D_, nullptr, D_, D_, 0);
            k_crossattn<<<32, 64>>>(l, mask);
            k_dgemm<<<dim3(8,1,1), 256>>>(dat, nullptr,
                dec_co + l*DD_, dec_co + l*DD_, dec_co + l*DD_,
                dx, dx, dx, D_, D_, D_, dx, D_, D_, 0);
            k_dgemm<<<dim3(32,1,1), 256>>>(dx, dec_ln3 + l*D_,
                dec_w1 + l*D_*DFF_, dec_w1 + l*D_*DFF_, dec_w1 + l*D_*DFF_,
                dff, dff, dff, DFF_, DFF_, DFF_, nullptr, DFF_, D_, 1);
            k_dgemm<<<dim3(8,1,1), 256>>>(dff, nullptr,
                dec_w2 + l*DFF_*D_, dec_w2 + l*DFF_*D_, dec_w2 + l*DFF_*D_,
                dx, dx, dx, D_, D_, D_, dx, D_, DFF_, 0);
        }
        k_dgemm<<<dim3(V_/64,1,1), 256>>>(dx, dec_lnf,
            lm_head, lm_head, lm_head,
            logits, logits, logits, V_, V_, V_, nullptr, V_, D_, 0);
        k_softmax<<<B_, 256>>>(out, t);
        k_ynext<<<128, 256>>>(emb);
    }
}

// round 5
// speedup vs baseline: 3.5127x; 3.0033x over previous
#include <cuda_runtime.h>
#include <math.h>

#define B_   4
#define S_   64
#define D_   512
#define H_   8
#define DH_  64
#define DFF_ 2048
#define L_   2
#define V_   32128
#define T_   16
#define M_   256          // B_*S_
#define DD_  (D_*D_)
#define NEG_ (-1e9f)

// ---------------- device scratch ----------------
__device__ float g_xe [M_*D_];
__device__ float g_h  [M_*D_];
__device__ float g_q  [M_*D_];
__device__ float g_k  [M_*D_];
__device__ float g_v  [M_*D_];
__device__ float g_at [M_*D_];
__device__ float g_ff [M_*DFF_];
__device__ float g_hs [M_*D_];
__device__ float g_cK [L_*M_*D_];
__device__ float g_cV [L_*M_*D_];
__device__ float g_dx [B_*D_];
__device__ float g_dq [B_*D_];
__device__ float g_dat[B_*D_];
__device__ float g_dff[B_*DFF_];
__device__ float g_kc [L_*B_*T_*D_];
__device__ float g_vc [L_*B_*T_*D_];
__device__ float g_logits[B_*V_];
__device__ float g_probs [B_*V_];

// ---------------- embedding gather ----------------
__global__ void k_embed(const int* __restrict__ ids, const float* __restrict__ emb) {
    int r = blockIdx.x;
    int id = ids[r];
    for (int d = threadIdx.x; d < D_; d += 256)
        g_xe[r*D_ + d] = emb[id*D_ + d];
}

// ---------------- RMSNorm (one block per row) ----------------
__global__ void k_rms(const float* __restrict__ x, const float* __restrict__ w,
                      float* __restrict__ out) {
    int r = blockIdx.x;
    __shared__ float red[8];
    float ss = 0.f;
    for (int d = threadIdx.x; d < D_; d += 256) { float v = x[r*D_+d]; ss += v*v; }
    for (int o = 16; o; o >>= 1) ss += __shfl_xor_sync(0xffffffffu, ss, o);
    if ((threadIdx.x & 31) == 0) red[threadIdx.x >> 5] = ss;
    __syncthreads();
    if (threadIdx.x == 0) {
        float t = 0.f;
        for (int i = 0; i < 8; i++) t += red[i];
        red[0] = rsqrtf(t / (float)D_ + 1e-6f);
    }
    __syncthreads();
    float rs = red[0];
    for (int d = threadIdx.x; d < D_; d += 256)
        out[r*D_+d] = x[r*D_+d] * rs * w[d];
}

// ---------------- encoder SGEMM (unchanged from R4) ----------------
__global__ void k_sgemm(const float* __restrict__ A,
                        const float* __restrict__ W0, const float* __restrict__ W1,
                        const float* __restrict__ W2,
                        float* __restrict__ C0, float* __restrict__ C1, float* __restrict__ C2,
                        const float* __restrict__ res, int N, int K, int op) {
    const float* __restrict__ W = (blockIdx.z == 0) ? W0 : (blockIdx.z == 1) ? W1 : W2;
    float* __restrict__ C = (blockIdx.z == 0) ? C0 : (blockIdx.z == 1) ? C1 : C2;
    __shared__ float As[2][16][33];
    __shared__ float Ws[2][16][64];
    int bx = blockIdx.x * 64, by = blockIdx.y * 32;
    int tid = threadIdx.x;
    int tx = tid & 15, ty = tid >> 4;
    int ar = tid >> 2, aq = tid & 3;
    int NT = K >> 4;

    float4 ra, rw;
    if (tid < 128) ra = *(const float4*)&A[(by+ar)*K + aq*4];
    rw = *(const float4*)&W[ty*N + bx + tx*4];
    if (tid < 128) {
        As[0][aq*4+0][ar] = ra.x; As[0][aq*4+1][ar] = ra.y;
        As[0][aq*4+2][ar] = ra.z; As[0][aq*4+3][ar] = ra.w;
    }
    *(float4*)&Ws[0][ty][tx*4] = rw;
    __syncthreads();

    float acc[2][4] = {};
    int buf = 0;
    for (int kt = 0; kt < NT; kt++) {
        bool pf = (kt + 1 < NT);
        if (pf) {
            int k0 = (kt + 1) << 4;
            if (tid < 128) ra = *(const float4*)&A[(by+ar)*K + k0 + aq*4];
            rw = *(const float4*)&W[(k0+ty)*N + bx + tx*4];
        }
        #pragma unroll
        for (int kk = 0; kk < 16; kk++) {
            float a0 = As[buf][kk][ty*2+0];
            float a1 = As[buf][kk][ty*2+1];
            float4 b = *(const float4*)&Ws[buf][kk][tx*4];
            acc[0][0] = fmaf(a0, b.x, acc[0][0]); acc[0][1] = fmaf(a0, b.y, acc[0][1]);
            acc[0][2] = fmaf(a0, b.z, acc[0][2]); acc[0][3] = fmaf(a0, b.w, acc[0][3]);
            acc[1][0] = fmaf(a1, b.x, acc[1][0]); acc[1][1] = fmaf(a1, b.y, acc[1][1]);
            acc[1][2] = fmaf(a1, b.z, acc[1][2]); acc[1][3] = fmaf(a1, b.w, acc[1][3]);
        }
        if (pf) {
            int nb = buf ^ 1;
            if (tid < 128) {
                As[nb][aq*4+0][ar] = ra.x; As[nb][aq*4+1][ar] = ra.y;
                As[nb][aq*4+2][ar] = ra.z; As[nb][aq*4+3][ar] = ra.w;
            }
            *(float4*)&Ws[nb][ty][tx*4] = rw;
            __syncthreads();
            buf = nb;
        }
    }
    #pragma unroll
    for (int i = 0; i < 2; i++) {
        int m = by + ty*2 + i, n = bx + tx*4;
        float4 v = make_float4(acc[i][0], acc[i][1], acc[i][2], acc[i][3]);
        if (op & 1) {
            float4 r4 = *(const float4*)&res[m*N + n];
            v.x += r4.x; v.y += r4.y; v.z += r4.z; v.w += r4.w;
        }
        if (op & 2) {
            v.x = fmaxf(v.x, 0.f); v.y = fmaxf(v.y, 0.f);
            v.z = fmaxf(v.z, 0.f); v.w = fmaxf(v.w, 0.f);
        }
        *(float4*)&C[m*N + n] = v;
    }
}

// ---------------- encoder attention ----------------
#define KS(j,d) ks[(j)][((d) ^ ((j) & 31))]
#define SC(i,j) sc[(i)][((j) ^ ((i) & 31))]
__global__ void k_encattn(const float* __restrict__ mask) {
    int b = blockIdx.x >> 3, h = blockIdx.x & 7;
    __shared__ float ks[64][64];
    __shared__ float vs[64][64];
    __shared__ float sc[64][64];
    for (int i = threadIdx.x; i < 4096; i += 256) {
        int j = i >> 6, d = i & 63;
        KS(j,d) = g_k[(b*64+j)*D_ + h*64 + d];
        vs[j][d] = g_q[(b*64+j)*D_ + h*64 + d];
    }
    __syncthreads();
    for (int idx = threadIdx.x; idx < 4096; idx += 256) {
        int i = idx >> 6, j = idx & 63;
        float s = 0.f;
        #pragma unroll 16
        for (int d = 0; d < 64; d++) s = fmaf(vs[i][d], KS(j,d), s);
        SC(i,j) = s * 0.125f + (1.f - mask[b*64 + j]) * NEG_;
    }
    __syncthreads();
    for (int i = threadIdx.x; i < 4096; i += 256) {
        int j = i >> 6, d = i & 63;
        vs[j][d] = g_v[(b*64+j)*D_ + h*64 + d];
    }
    __syncthreads();
    if (threadIdx.x < 64) {
        int i = threadIdx.x;
        float m = -1e30f;
        for (int j = 0; j < 64; j++) m = fmaxf(m, SC(i,j));
        float su = 0.f;
        for (int j = 0; j < 64; j++) { float e = __expf(SC(i,j) - m); SC(i,j) = e; su += e; }
        float inv = 1.f / su;
        for (int j = 0; j < 64; j++) SC(i,j) *= inv;
    }
    __syncthreads();
    for (int idx = threadIdx.x; idx < 4096; idx += 256) {
        int i = idx >> 6, d = idx & 63;
        float o = 0.f;
        #pragma unroll 16
        for (int j = 0; j < 64; j++) o = fmaf(SC(i,j), vs[j][d], o);
        g_at[(b*64+i)*D_ + h*64 + d] = o;
    }
}

// ---------------- decoder matvec v2: high block-parallelism ------------------
// C[4,N] = rms?(x)[4,K] @ W[K,N]. 256 threads = COLS cols x (256/COLS) k-splits.
// lcols = log2(COLS). grid = (N/COLS, 1, nz).
__global__ void __launch_bounds__(256)
k_dgemm(const float* __restrict__ x, const float* __restrict__ ln,
        const float* __restrict__ W0, const float* __restrict__ W1,
        const float* __restrict__ W2,
        float* C0, float* C1, float* C2,
        int rs0, int rs1, int rs2,
        const float* __restrict__ res, int N, int K, int relu, int lcols) {
    const float* __restrict__ W = (blockIdx.z == 0) ? W0 : (blockIdx.z == 1) ? W1 : W2;
    float* C = (blockIdx.z == 0) ? C0 : (blockIdx.z == 1) ? C1 : C2;
    int rs = (blockIdx.z == 0) ? rs0 : (blockIdx.z == 1) ? rs1 : rs2;
    __shared__ float h_s[B_*DFF_];      // up to 32KB (K<=2048)
    __shared__ float ss[B_][64];
    __shared__ float red[1024];         // [ks][r][c]
    int tid = threadIdx.x;
    // --- optional fused RMSNorm of x into h_s ---
    if (ln) {
        int r = tid >> 6, c = tid & 63;
        float s = 0.f;
        #pragma unroll 4
        for (int k = c; k < K; k += 64) { float v = x[r*K + k]; s += v*v; }
        ss[r][c] = s;
        __syncthreads();
        if (tid < B_) {
            float t = 0.f;
            for (int c2 = 0; c2 < 64; c2++) t += ss[tid][c2];
            ss[tid][0] = rsqrtf(t / (float)K + 1e-6f);
        }
        __syncthreads();
        #pragma unroll 4
        for (int i = tid; i < B_*K; i += 256) {
            int r2 = i / K, k = i % K;
            h_s[i] = x[i] * ss[r2][0] * ln[k];
        }
    } else {
        #pragma unroll 4
        for (int i = tid; i < B_*K; i += 256) h_s[i] = x[i];
    }
    __syncthreads();
    int cols = 1 << lcols;
    int c    = tid & (cols - 1);
    int ks_i = tid >> lcols;
    int col  = (blockIdx.x << lcols) + c;
    int kcnt = (K << lcols) >> 8;       // K / (256/cols)
    int kbeg = ks_i * kcnt;
    const float* __restrict__ Wc = W + col;
    const float* __restrict__ h0 = h_s;
    const float* __restrict__ h1 = h_s + K;
    const float* __restrict__ h2 = h_s + 2*K;
    const float* __restrict__ h3 = h_s + 3*K;
    float a0 = 0.f, a1 = 0.f, a2 = 0.f, a3 = 0.f;
    for (int kb = kbeg; kb < kbeg + kcnt; kb += 16) {   // kcnt is a multiple of 16
        float w[16];
        #pragma unroll
        for (int u = 0; u < 16; u++) w[u] = Wc[(kb + u) * N];
        #pragma unroll
        for (int u = 0; u < 16; u++) {
            int k = kb + u;
            a0 = fmaf(h0[k], w[u], a0);
            a1 = fmaf(h1[k], w[u], a1);
            a2 = fmaf(h2[k], w[u], a2);
            a3 = fmaf(h3[k], w[u], a3);
        }
    }
    red[(ks_i*4 + 0)*cols + c] = a0;
    red[(ks_i*4 + 1)*cols + c] = a1;
    red[(ks_i*4 + 2)*cols + c] = a2;
    red[(ks_i*4 + 3)*cols + c] = a3;
    __syncthreads();
    int nsplit = 256 >> lcols;
    if (tid < 4*cols) {
        int r = tid >> lcols, cc = tid & (cols - 1);
        float v = 0.f;
        for (int s = 0; s < nsplit; s++) v += red[(s*4 + r)*cols + cc];
        int colw = (blockIdx.x << lcols) + cc;
        if (res)  v += res[r*N + colw];
        if (relu) v = fmaxf(v, 0.f);
        C[r*rs + colw] = v;
    }
}

// ---------------- decoder self-attention (cache) ----------
__global__ void k_selfattn(int l, int t) {
    int b = blockIdx.x >> 3, h = blockIdx.x & 7;
    int tid = threadIdx.x;
    __shared__ float p[T_];
    __shared__ float qv[DH_];
    qv[tid] = g_dq[b*D_ + h*DH_ + tid];
    __syncthreads();
    if (tid <= t) {
        const float* kp = &g_kc[((l*B_ + b)*T_ + tid)*D_ + h*DH_];
        float s = 0.f;
        #pragma unroll 16
        for (int d = 0; d < DH_; d++) s = fmaf(qv[d], kp[d], s);
        p[tid] = s * 0.125f;
    }
    __syncthreads();
    if (tid == 0) {
        float m = -1e30f;
        for (int j = 0; j <= t; j++) m = fmaxf(m, p[j]);
        float su = 0.f;
        for (int j = 0; j <= t; j++) { p[j] = __expf(p[j] - m); su += p[j]; }
        float inv = 1.f / su;
        for (int j = 0; j <= t; j++) p[j] *= inv;
    }
    __syncthreads();
    float o = 0.f;
    for (int j = 0; j <= t; j++)
        o = fmaf(p[j], g_vc[((l*B_ + b)*T_ + j)*D_ + h*DH_ + tid], o);
    g_dat[b*D_ + h*DH_ + tid] = o;
}

// ---------------- decoder cross-attention ----------
__global__ void k_crossattn(int l, const float* __restrict__ mask) {
    int b = blockIdx.x >> 3, h = blockIdx.x & 7;
    int tid = threadIdx.x;
    __shared__ float p[S_];
    __shared__ float qv[DH_];
    qv[tid] = g_dq[b*D_ + h*DH_ + tid];
    __syncthreads();
    {
        const float* kp = &g_cK[l*M_*D_ + (b*S_ + tid)*D_ + h*DH_];
        float s = 0.f;
        #pragma unroll 16
        for (int d = 0; d < DH_; d++) s = fmaf(qv[d], kp[d], s);
        p[tid] = s * 0.125f + (1.f - mask[b*S_ + tid]) * NEG_;
    }
    __syncthreads();
    if (tid == 0) {
        float m = -1e30f;
        for (int j = 0; j < S_; j++) m = fmaxf(m, p[j]);
        float su = 0.f;
        for (int j = 0; j < S_; j++) { p[j] = __expf(p[j] - m); su += p[j]; }
        float inv = 1.f / su;
        for (int j = 0; j < S_; j++) p[j] *= inv;
    }
    __syncthreads();
    float o = 0.f;
    for (int j = 0; j < S_; j++)
        o = fmaf(p[j], g_cV[l*M_*D_ + (b*S_ + j)*D_ + h*DH_ + tid], o);
    g_dat[b*D_ + h*DH_ + tid] = o;
}

// ---------------- softmax + argmax + outputs + zero next-x ------------------
__global__ void __launch_bounds__(1024)
k_softmax(float* __restrict__ out, int t) {
    int b = blockIdx.x, tid = threadIdx.x;
    __shared__ float sm[1024];
    __shared__ int   si[1024];
    const float* lg = &g_logits[b*V_];
    float mx = -1e30f; int mi = 0;
    #pragma unroll 4
    for (int v = tid; v < V_; v += 1024) {
        float xv = lg[v];
        if (xv > mx) { mx = xv; mi = v; }
    }
    sm[tid] = mx; si[tid] = mi;
    __syncthreads();
    for (int s = 512; s; s >>= 1) {
        if (tid < s) {
            float xo = sm[tid+s]; int io = si[tid+s];
            if (xo > sm[tid] || (xo == sm[tid] && io < si[tid])) { sm[tid] = xo; si[tid] = io; }
        }
        __syncthreads();
    }
    float rowmax = sm[0];
    int amax = si[0];
    __syncthreads();
    float su = 0.f;
    #pragma unroll 4
    for (int v = tid; v < V_; v += 1024) su += __expf(lg[v] - rowmax);
    sm[tid] = su;
    __syncthreads();
    for (int s = 512; s; s >>= 1) { if (tid < s) sm[tid] += sm[tid+s]; __syncthreads(); }
    float inv = 1.f / sm[0];
    float* po = &out[(b*T_ + t)*V_];
    #pragma unroll 4
    for (int v = tid; v < V_; v += 1024) {
        float pv = __expf(lg[v] - rowmax) * inv;
        g_probs[b*V_ + v] = pv;
        po[v] = pv;
    }
    if (tid == 0) out[B_*T_*V_ + b*T_ + t] = (amax == 0) ? 1.0f : 0.0f;
    if (tid < D_) g_dx[b*D_ + tid] = 0.f;
}

// ---------------- soft embedding: g_dx += probs @ emb -----------------------
// 128 blocks x 251 vocab rows. float2 per thread, unroll-8 row batches.
__global__ void __launch_bounds__(256)
k_ynext(const float* __restrict__ emb) {
    __shared__ float ps[B_][251];
    int tid = threadIdx.x;
    int v0 = blockIdx.x * 251;
    for (int i = tid; i < B_*251; i += 256) {
        int b = i / 251, j = i % 251;
        ps[b][j] = g_probs[b*V_ + v0 + j];
    }
    __syncthreads();
    const float2* eb = (const float2*)emb;   // D_/2 = 256 float2 per row; c = tid
    int c = tid;
    float a0x=0,a0y=0,a1x=0,a1y=0,a2x=0,a2y=0,a3x=0,a3y=0;
    int j = 0;
    for (; j + 8 <= 251; j += 8) {
        float2 e[8];
        #pragma unroll
        for (int u = 0; u < 8; u++)
            e[u] = eb[(size_t)(v0 + j + u) * 256 + c];
        #pragma unroll
        for (int u = 0; u < 8; u++) {
            float p0 = ps[0][j+u], p1 = ps[1][j+u], p2 = ps[2][j+u], p3 = ps[3][j+u];
            a0x = fmaf(p0, e[u].x, a0x); a0y = fmaf(p0, e[u].y, a0y);
            a1x = fmaf(p1, e[u].x, a1x); a1y = fmaf(p1, e[u].y, a1y);
            a2x = fmaf(p2, e[u].x, a2x); a2y = fmaf(p2, e[u].y, a2y);
            a3x = fmaf(p3, e[u].x, a3x); a3y = fmaf(p3, e[u].y, a3y);
        }
    }
    for (; j < 251; j++) {
        float2 e = eb[(size_t)(v0 + j) * 256 + c];
        float p0 = ps[0][j], p1 = ps[1][j], p2 = ps[2][j], p3 = ps[3][j];
        a0x = fmaf(p0, e.x, a0x); a0y = fmaf(p0, e.y, a0y);
        a1x = fmaf(p1, e.x, a1x); a1y = fmaf(p1, e.y, a1y);
        a2x = fmaf(p2, e.x, a2x); a2y = fmaf(p2, e.y, a2y);
        a3x = fmaf(p3, e.x, a3x); a3y = fmaf(p3, e.y, a3y);
    }
    int d0 = c*2, d1 = c*2 + 1;
    atomicAdd(&g_dx[0*D_+d0], a0x); atomicAdd(&g_dx[0*D_+d1], a0y);
    atomicAdd(&g_dx[1*D_+d0], a1x); atomicAdd(&g_dx[1*D_+d1], a1y);
    atomicAdd(&g_dx[2*D_+d0], a2x); atomicAdd(&g_dx[2*D_+d1], a2y);
    atomicAdd(&g_dx[3*D_+d0], a3x); atomicAdd(&g_dx[3*D_+d1], a3y);
}

// ---------------- init decoder x with pad embedding -------------------------
__global__ void k_initdx(const float* __restrict__ emb) {
    int d = threadIdx.x + blockIdx.x * 256;
    float v = emb[d];   // PAD_ID = 0
    for (int b = 0; b < B_; b++) g_dx[b*D_ + d] = v;
}

// ---------------- host driver ----------------
extern "C" void kernel_launch(void* const* d_in, const int* in_sizes, int n_in,
                              void* d_out, int out_size) {
    const int*   ids     = (const int*)  d_in[0];
    const float* mask    = (const float*)d_in[1];
    const float* emb     = (const float*)d_in[2];
    const float* enc_wq  = (const float*)d_in[3];
    const float* enc_wk  = (const float*)d_in[4];
    const float* enc_wv  = (const float*)d_in[5];
    const float* enc_wo  = (const float*)d_in[6];
    const float* enc_ln1 = (const float*)d_in[7];
    const float* enc_w1  = (const float*)d_in[8];
    const float* enc_w2  = (const float*)d_in[9];
    const float* enc_ln2 = (const float*)d_in[10];
    const float* enc_lnf = (const float*)d_in[11];
    const float* dec_sq  = (const float*)d_in[12];
    const float* dec_sk  = (const float*)d_in[13];
    const float* dec_sv  = (const float*)d_in[14];
    const float* dec_so  = (const float*)d_in[15];
    const float* dec_ln1 = (const float*)d_in[16];
    const float* dec_cq  = (const float*)d_in[17];
    const float* dec_ck  = (const float*)d_in[18];
    const float* dec_cv  = (const float*)d_in[19];
    const float* dec_co  = (const float*)d_in[20];
    const float* dec_ln2 = (const float*)d_in[21];
    const float* dec_w1  = (const float*)d_in[22];
    const float* dec_w2  = (const float*)d_in[23];
    const float* dec_ln3 = (const float*)d_in[24];
    const float* dec_lnf = (const float*)d_in[25];
    const float* lm_head = (const float*)d_in[26];
    float* out = (float*)d_out;

    void* p;
    cudaGetSymbolAddress(&p, g_xe);  float* xe  = (float*)p;
    cudaGetSymbolAddress(&p, g_h);   float* h   = (float*)p;
    cudaGetSymbolAddress(&p, g_q);   float* q   = (float*)p;
    cudaGetSymbolAddress(&p, g_k);   float* k   = (float*)p;
    cudaGetSymbolAddress(&p, g_v);   float* v   = (float*)p;
    cudaGetSymbolAddress(&p, g_at);  float* at  = (float*)p;
    cudaGetSymbolAddress(&p, g_ff);  float* ff  = (float*)p;
    cudaGetSymbolAddress(&p, g_hs);  float* hs  = (float*)p;
    cudaGetSymbolAddress(&p, g_cK);  float* cK  = (float*)p;
    cudaGetSymbolAddress(&p, g_cV);  float* cV  = (float*)p;
    cudaGetSymbolAddress(&p, g_dx);  float* dx  = (float*)p;
    cudaGetSymbolAddress(&p, g_dq);  float* dq  = (float*)p;
    cudaGetSymbolAddress(&p, g_dat); float* dat = (float*)p;
    cudaGetSymbolAddress(&p, g_dff); float* dff = (float*)p;
    cudaGetSymbolAddress(&p, g_kc);  float* kc  = (float*)p;
    cudaGetSymbolAddress(&p, g_vc);  float* vc  = (float*)p;
    cudaGetSymbolAddress(&p, g_logits); float* logits = (float*)p;

    // ================= encoder =================
    k_embed<<<M_, 256>>>(ids, emb);
    for (int l = 0; l < L_; l++) {
        k_rms<<<M_, 256>>>(xe, enc_ln1 + l*D_, h);
        k_sgemm<<<dim3(8,8,3), 256>>>(h, enc_wq + l*DD_, enc_wk + l*DD_, enc_wv + l*DD_,
                                      q, k, v, nullptr, D_, D_, 0);
        k_encattn<<<32, 256>>>(mask);
        k_sgemm<<<dim3(8,8,1), 256>>>(at, enc_wo + l*DD_, enc_wo + l*DD_, enc_wo + l*DD_,
                                      xe, xe, xe, xe, D_, D_, 1);
        k_rms<<<M_, 256>>>(xe, enc_ln2 + l*D_, h);
        k_sgemm<<<dim3(32,8,1), 256>>>(h, enc_w1 + l*D_*DFF_, enc_w1 + l*D_*DFF_, enc_w1 + l*D_*DFF_,
                                       ff, ff, ff, nullptr, DFF_, D_, 2);
        k_sgemm<<<dim3(8,8,1), 256>>>(ff, enc_w2 + l*DFF_*D_, enc_w2 + l*DFF_*D_, enc_w2 + l*DFF_*D_,
                                      xe, xe, xe, xe, D_, DFF_, 1);
    }
    k_rms<<<M_, 256>>>(xe, enc_lnf, hs);
    for (int l = 0; l < L_; l++) {
        k_sgemm<<<dim3(8,8,2), 256>>>(hs, dec_ck + l*DD_, dec_cv + l*DD_, dec_cv + l*DD_,
                                      cK + l*M_*D_, cV + l*M_*D_, cV + l*M_*D_,
                                      nullptr, D_, D_, 0);
    }

    // ================= decoder (incremental, KV-cached) =================
    k_initdx<<<2, 256>>>(emb);
    for (int t = 0; t < T_; t++) {
        for (int l = 0; l < L_; l++) {
            float* kcb = kc + (size_t)(l*B_*T_ + t) * D_;
            float* vcb = vc + (size_t)(l*B_*T_ + t) * D_;
            k_dgemm<<<dim3(32,1,3), 256>>>(dx, dec_ln1 + l*D_,
                dec_sq + l*DD_, dec_sk + l*DD_, dec_sv + l*DD_,
                dq, kcb, vcb, D_, T_*D_, T_*D_, nullptr, D_, D_, 0, 4);
            k_selfattn<<<32, 64>>>(l, t);
            k_dgemm<<<dim3(32,1,1), 256>>>(dat, nullptr,
                dec_so + l*DD_, dec_so + l*DD_, dec_so + l*DD_,
                dx, dx, dx, D_, D_, D_, dx, D_, D_, 0, 4);
            k_dgemm<<<dim3(32,1,1), 256>>>(dx, dec_ln2 + l*D_,
                dec_cq + l*DD_, dec_cq + l*DD_, dec_cq + l*DD_,
                dq, dq, dq, D_, D_, D_, nullptr, D_, D_, 0, 4);
            k_crossattn<<<32, 64>>>(l, mask);
            k_dgemm<<<dim3(32,1,1), 256>>>(dat, nullptr,
                dec_co + l*DD_, dec_co + l*DD_, dec_co + l*DD_,
                dx, dx, dx, D_, D_, D_, dx, D_, D_, 0, 4);
            k_dgemm<<<dim3(128,1,1), 256>>>(dx, dec_ln3 + l*D_,
                dec_w1 + l*D_*DFF_, dec_w1 + l*D_*DFF_, dec_w1 + l*D_*DFF_,
                dff, dff, dff, DFF_, DFF_, DFF_, nullptr, DFF_, D_, 1, 4);
            k_dgemm<<<dim3(64,1,1), 256>>>(dff, nullptr,
                dec_w2 + l*DFF_*D_, dec_w2 + l*DFF_*D_, dec_w2 + l*DFF_*D_,
                dx, dx, dx, D_, D_, D_, dx, D_, DFF_, 0, 3);
        }
        k_dgemm<<<dim3(V_/16,1,1), 256>>>(dx, dec_lnf,
            lm_head, lm_head, lm_head,
            logits, logits, logits, V_, V_, V_, nullptr, V_, D_, 0, 4);
        k_softmax<<<B_, 1024>>>(out, t);
        k_ynext<<<128, 256>>>(emb);
    }
}

// round 6
// speedup vs baseline: 4.0723x; 1.1593x over previous
#include <cuda_runtime.h>
#include <math.h>

#define B_   4
#define S_   64
#define D_   512
#define H_   8
#define DH_  64
#define DFF_ 2048
#define L_   2
#define V_   32128
#define T_   16
#define M_   256          // B_*S_
#define DD_  (D_*D_)
#define NEG_ (-1e9f)
#define NBLK 148

// ---------------- device scratch ----------------
__device__ float g_xe [M_*D_];
__device__ float g_h  [M_*D_];
__device__ float g_q  [M_*D_];
__device__ float g_k  [M_*D_];
__device__ float g_v  [M_*D_];
__device__ float g_at [M_*D_];
__device__ float g_ff [M_*DFF_];
__device__ float g_hs [M_*D_];
__device__ float g_cK [L_*M_*D_];
__device__ float g_cV [L_*M_*D_];
__device__ float g_dx [B_*D_];
__device__ float g_dq [B_*D_];
__device__ float g_dat[B_*D_];
__device__ float g_dff[B_*DFF_];
__device__ float g_kc [L_*B_*T_*D_];
__device__ float g_vc [L_*B_*T_*D_];
__device__ float g_logits[B_*V_];
__device__ float g_probs [B_*V_];
__device__ unsigned g_barc;

// ---------------- embedding gather ----------------
__global__ void k_embed(const int* __restrict__ ids, const float* __restrict__ emb) {
    int r = blockIdx.x;
    int id = ids[r];
    for (int d = threadIdx.x; d < D_; d += 256)
        g_xe[r*D_ + d] = emb[id*D_ + d];
}

// ---------------- RMSNorm (one block per row) ----------------
__global__ void k_rms(const float* __restrict__ x, const float* __restrict__ w,
                      float* __restrict__ out) {
    int r = blockIdx.x;
    __shared__ float red[8];
    float ss = 0.f;
    for (int d = threadIdx.x; d < D_; d += 256) { float v = x[r*D_+d]; ss += v*v; }
    for (int o = 16; o; o >>= 1) ss += __shfl_xor_sync(0xffffffffu, ss, o);
    if ((threadIdx.x & 31) == 0) red[threadIdx.x >> 5] = ss;
    __syncthreads();
    if (threadIdx.x == 0) {
        float t = 0.f;
        for (int i = 0; i < 8; i++) t += red[i];
        red[0] = rsqrtf(t / (float)D_ + 1e-6f);
    }
    __syncthreads();
    float rs = red[0];
    for (int d = threadIdx.x; d < D_; d += 256)
        out[r*D_+d] = x[r*D_+d] * rs * w[d];
}

// ---------------- encoder SGEMM ----------------
__global__ void k_sgemm(const float* __restrict__ A,
                        const float* __restrict__ W0, const float* __restrict__ W1,
                        const float* __restrict__ W2,
                        float* __restrict__ C0, float* __restrict__ C1, float* __restrict__ C2,
                        const float* __restrict__ res, int N, int K, int op) {
    const float* __restrict__ W = (blockIdx.z == 0) ? W0 : (blockIdx.z == 1) ? W1 : W2;
    float* __restrict__ C = (blockIdx.z == 0) ? C0 : (blockIdx.z == 1) ? C1 : C2;
    __shared__ float As[2][16][33];
    __shared__ float Ws[2][16][64];
    int bx = blockIdx.x * 64, by = blockIdx.y * 32;
    int tid = threadIdx.x;
    int tx = tid & 15, ty = tid >> 4;
    int ar = tid >> 2, aq = tid & 3;
    int NT = K >> 4;

    float4 ra, rw;
    if (tid < 128) ra = *(const float4*)&A[(by+ar)*K + aq*4];
    rw = *(const float4*)&W[ty*N + bx + tx*4];
    if (tid < 128) {
        As[0][aq*4+0][ar] = ra.x; As[0][aq*4+1][ar] = ra.y;
        As[0][aq*4+2][ar] = ra.z; As[0][aq*4+3][ar] = ra.w;
    }
    *(float4*)&Ws[0][ty][tx*4] = rw;
    __syncthreads();

    float acc[2][4] = {};
    int buf = 0;
    for (int kt = 0; kt < NT; kt++) {
        bool pf = (kt + 1 < NT);
        if (pf) {
            int k0 = (kt + 1) << 4;
            if (tid < 128) ra = *(const float4*)&A[(by+ar)*K + k0 + aq*4];
            rw = *(const float4*)&W[(k0+ty)*N + bx + tx*4];
        }
        #pragma unroll
        for (int kk = 0; kk < 16; kk++) {
            float a0 = As[buf][kk][ty*2+0];
            float a1 = As[buf][kk][ty*2+1];
            float4 b = *(const float4*)&Ws[buf][kk][tx*4];
            acc[0][0] = fmaf(a0, b.x, acc[0][0]); acc[0][1] = fmaf(a0, b.y, acc[0][1]);
            acc[0][2] = fmaf(a0, b.z, acc[0][2]); acc[0][3] = fmaf(a0, b.w, acc[0][3]);
            acc[1][0] = fmaf(a1, b.x, acc[1][0]); acc[1][1] = fmaf(a1, b.y, acc[1][1]);
            acc[1][2] = fmaf(a1, b.z, acc[1][2]); acc[1][3] = fmaf(a1, b.w, acc[1][3]);
        }
        if (pf) {
            int nb = buf ^ 1;
            if (tid < 128) {
                As[nb][aq*4+0][ar] = ra.x; As[nb][aq*4+1][ar] = ra.y;
                As[nb][aq*4+2][ar] = ra.z; As[nb][aq*4+3][ar] = ra.w;
            }
            *(float4*)&Ws[nb][ty][tx*4] = rw;
            __syncthreads();
            buf = nb;
        }
    }
    #pragma unroll
    for (int i = 0; i < 2; i++) {
        int m = by + ty*2 + i, n = bx + tx*4;
        float4 v = make_float4(acc[i][0], acc[i][1], acc[i][2], acc[i][3]);
        if (op & 1) {
            float4 r4 = *(const float4*)&res[m*N + n];
            v.x += r4.x; v.y += r4.y; v.z += r4.z; v.w += r4.w;
        }
        if (op & 2) {
            v.x = fmaxf(v.x, 0.f); v.y = fmaxf(v.y, 0.f);
            v.z = fmaxf(v.z, 0.f); v.w = fmaxf(v.w, 0.f);
        }
        *(float4*)&C[m*N + n] = v;
    }
}

// ---------------- encoder attention ----------------
#define KS(j,d) ks[(j)][((d) ^ ((j) & 31))]
#define SC(i,j) sc[(i)][((j) ^ ((i) & 31))]
__global__ void k_encattn(const float* __restrict__ mask) {
    int b = blockIdx.x >> 3, h = blockIdx.x & 7;
    __shared__ float ks[64][64];
    __shared__ float vs[64][64];
    __shared__ float sc[64][64];
    for (int i = threadIdx.x; i < 4096; i += 256) {
        int j = i >> 6, d = i & 63;
        KS(j,d) = g_k[(b*64+j)*D_ + h*64 + d];
        vs[j][d] = g_q[(b*64+j)*D_ + h*64 + d];
    }
    __syncthreads();
    for (int idx = threadIdx.x; idx < 4096; idx += 256) {
        int i = idx >> 6, j = idx & 63;
        float s = 0.f;
        #pragma unroll 16
        for (int d = 0; d < 64; d++) s = fmaf(vs[i][d], KS(j,d), s);
        SC(i,j) = s * 0.125f + (1.f - mask[b*64 + j]) * NEG_;
    }
    __syncthreads();
    for (int i = threadIdx.x; i < 4096; i += 256) {
        int j = i >> 6, d = i & 63;
        vs[j][d] = g_v[(b*64+j)*D_ + h*64 + d];
    }
    __syncthreads();
    if (threadIdx.x < 64) {
        int i = threadIdx.x;
        float m = -1e30f;
        for (int j = 0; j < 64; j++) m = fmaxf(m, SC(i,j));
        float su = 0.f;
        for (int j = 0; j < 64; j++) { float e = __expf(SC(i,j) - m); SC(i,j) = e; su += e; }
        float inv = 1.f / su;
        for (int j = 0; j < 64; j++) SC(i,j) *= inv;
    }
    __syncthreads();
    for (int idx = threadIdx.x; idx < 4096; idx += 256) {
        int i = idx >> 6, d = idx & 63;
        float o = 0.f;
        #pragma unroll 16
        for (int j = 0; j < 64; j++) o = fmaf(SC(i,j), vs[j][d], o);
        g_at[(b*64+i)*D_ + h*64 + d] = o;
    }
}

// ---------------- init decoder x with pad embedding ----------------
__global__ void k_initdx(const float* __restrict__ emb) {
    int d = threadIdx.x + blockIdx.x * 256;
    float v = emb[d];   // PAD_ID = 0
    for (int b = 0; b < B_; b++) g_dx[b*D_ + d] = v;
}

// ---------------- barrier counter reset ----------------
__global__ void k_reset() { g_barc = 0u; }

// ==================== persistent decode megakernel ====================

__device__ __forceinline__ void gbar(unsigned target) {
    __syncthreads();
    if (threadIdx.x == 0) {
        __threadfence();
        atomicAdd(&g_barc, 1u);
        while (*(volatile unsigned*)&g_barc < target) { }
        __threadfence();
    }
    __syncthreads();
}

// load x (B_ rows x K) into h_s, optionally RMS-normed with ln.
__device__ __forceinline__ void loadx(const float* __restrict__ x,
                                      const float* __restrict__ ln,
                                      int K, float* h_s, float* sred) {
    int tid = threadIdx.x;
    if (ln) {
        int r = tid >> 6, c = tid & 63;
        float s = 0.f;
        for (int k = c; k < K; k += 64) { float v = x[r*K + k]; s = fmaf(v, v, s); }
        sred[tid] = s;
        __syncthreads();
        if (tid < B_) {
            float t = 0.f;
            #pragma unroll 8
            for (int i = 0; i < 64; i++) t += sred[tid*64 + i];
            sred[256 + tid] = rsqrtf(t / (float)K + 1e-6f);
        }
        __syncthreads();
        for (int i = tid; i < B_*K; i += 256) {
            int r2 = i / K;
            h_s[i] = x[i] * sred[256 + r2] * ln[i - r2*K];
        }
    } else {
        for (int i = tid; i < B_*K; i += 256) h_s[i] = x[i];
    }
    __syncthreads();
}

// matvec: C[4, N] = h_s[4, K] @ W[K, N] (+res, relu). nblk blocks x (1<<lcols) cols.
__device__ __forceinline__ void mv(const float* __restrict__ W,
                                   float* __restrict__ C, int crs,
                                   const float* __restrict__ res,
                                   int N, int K, int relu, int nblk, int lcols,
                                   const float* h_s, float* red) {
    if ((int)blockIdx.x >= nblk) return;
    int tid  = threadIdx.x;
    int cols = 1 << lcols;
    int c    = tid & (cols - 1);
    int ks   = tid >> lcols;
    int col  = ((int)blockIdx.x << lcols) + c;
    int kcnt = (K << lcols) >> 8;
    int kbeg = ks * kcnt;
    const float* __restrict__ Wc = W + col;
    float a0 = 0.f, a1 = 0.f, a2 = 0.f, a3 = 0.f;
    for (int kb = kbeg; kb < kbeg + kcnt; kb += 8) {
        float w[8];
        #pragma unroll
        for (int u = 0; u < 8; u++) w[u] = Wc[(kb + u) * N];
        #pragma unroll
        for (int u = 0; u < 8; u++) {
            int k = kb + u;
            a0 = fmaf(h_s[k],        w[u], a0);
            a1 = fmaf(h_s[K + k],    w[u], a1);
            a2 = fmaf(h_s[2*K + k],  w[u], a2);
            a3 = fmaf(h_s[3*K + k],  w[u], a3);
        }
    }
    red[(ks*4 + 0)*cols + c] = a0;
    red[(ks*4 + 1)*cols + c] = a1;
    red[(ks*4 + 2)*cols + c] = a2;
    red[(ks*4 + 3)*cols + c] = a3;
    __syncthreads();
    if (tid < 4*cols) {
        int r = tid >> lcols, cc = tid & (cols - 1);
        int nsplit = 256 >> lcols;
        float v = 0.f;
        for (int s = 0; s < nsplit; s++) v += red[(s*4 + r)*cols + cc];
        int colw = ((int)blockIdx.x << lcols) + cc;
        if (res)  v += res[r*N + colw];
        if (relu) v = fmaxf(v, 0.f);
        C[r*crs + colw] = v;
    }
    __syncthreads();
}

__global__ void __launch_bounds__(256, 1)
k_decode(const float* __restrict__ mask, const float* __restrict__ emb,
         const float* __restrict__ dec_sq, const float* __restrict__ dec_sk,
         const float* __restrict__ dec_sv, const float* __restrict__ dec_so,
         const float* __restrict__ dec_ln1,
         const float* __restrict__ dec_cq, const float* __restrict__ dec_co,
         const float* __restrict__ dec_ln2,
         const float* __restrict__ dec_w1, const float* __restrict__ dec_w2,
         const float* __restrict__ dec_ln3, const float* __restrict__ dec_lnf,
         const float* __restrict__ lm_head,
         float* __restrict__ out) {
    __shared__ float s_h[B_*DFF_];     // 32 KB
    __shared__ float s_red[1024];
    __shared__ float s_sred[260];
    __shared__ float s_p[64];
    __shared__ float s_qv[64];
    __shared__ int   s_si[256];

    int bi  = blockIdx.x;
    int tid = threadIdx.x;
    unsigned bt = 0;
    const unsigned GD = gridDim.x;

    for (int t = 0; t < T_; t++) {
        for (int l = 0; l < L_; l++) {
            float* kcb = &g_kc[(size_t)(l*B_*T_ + t) * D_];
            float* vcb = &g_vc[(size_t)(l*B_*T_ + t) * D_];
            // ---- QKV (rms(dx, ln1) once, three matvecs) ----
            if (bi < 128) {
                loadx(g_dx, dec_ln1 + l*D_, D_, s_h, s_sred);
                mv(dec_sq + l*DD_, g_dq, D_,     nullptr, D_, D_, 0, 128, 2, s_h, s_red);
                mv(dec_sk + l*DD_, kcb,  T_*D_,  nullptr, D_, D_, 0, 128, 2, s_h, s_red);
                mv(dec_sv + l*DD_, vcb,  T_*D_,  nullptr, D_, D_, 0, 128, 2, s_h, s_red);
            }
            bt += GD; gbar(bt);
            // ---- self-attention ----
            if (bi < 32) {
                int b = bi >> 3, h = bi & 7;
                if (tid < 64) s_qv[tid] = g_dq[b*D_ + h*DH_ + tid];
                __syncthreads();
                if (tid <= t) {
                    const float* kp = &g_kc[((l*B_ + b)*T_ + tid)*D_ + h*DH_];
                    float s = 0.f;
                    #pragma unroll 16
                    for (int d = 0; d < DH_; d++) s = fmaf(s_qv[d], kp[d], s);
                    s_p[tid] = s * 0.125f;
                }
                __syncthreads();
                if (tid == 0) {
                    float m = -1e30f;
                    for (int j = 0; j <= t; j++) m = fmaxf(m, s_p[j]);
                    float su = 0.f;
                    for (int j = 0; j <= t; j++) { s_p[j] = __expf(s_p[j] - m); su += s_p[j]; }
                    float inv = 1.f / su;
                    for (int j = 0; j <= t; j++) s_p[j] *= inv;
                }
                __syncthreads();
                if (tid < 64) {
                    float o = 0.f;
                    for (int j = 0; j <= t; j++)
                        o = fmaf(s_p[j], g_vc[((l*B_ + b)*T_ + j)*D_ + h*DH_ + tid], o);
                    g_dat[b*D_ + h*DH_ + tid] = o;
                }
            }
            bt += GD; gbar(bt);
            // ---- self out-proj + residual ----
            if (bi < 128) {
                loadx(g_dat, nullptr, D_, s_h, s_sred);
                mv(dec_so + l*DD_, g_dx, D_, g_dx, D_, D_, 0, 128, 2, s_h, s_red);
            }
            bt += GD; gbar(bt);
            // ---- cross q ----
            if (bi < 128) {
                loadx(g_dx, dec_ln2 + l*D_, D_, s_h, s_sred);
                mv(dec_cq + l*DD_, g_dq, D_, nullptr, D_, D_, 0, 128, 2, s_h, s_red);
            }
            bt += GD; gbar(bt);
            // ---- cross-attention ----
            if (bi < 32) {
                int b = bi >> 3, h = bi & 7;
                if (tid < 64) s_qv[tid] = g_dq[b*D_ + h*DH_ + tid];
                __syncthreads();
                if (tid < 64) {
                    const float* kp = &g_cK[l*M_*D_ + (b*S_ + tid)*D_ + h*DH_];
                    float s = 0.f;
                    #pragma unroll 16
                    for (int d = 0; d < DH_; d++) s = fmaf(s_qv[d], kp[d], s);
                    s_p[tid] = s * 0.125f + (1.f - mask[b*S_ + tid]) * NEG_;
                }
                __syncthreads();
                if (tid == 0) {
                    float m = -1e30f;
                    for (int j = 0; j < S_; j++) m = fmaxf(m, s_p[j]);
                    float su = 0.f;
                    for (int j = 0; j < S_; j++) { s_p[j] = __expf(s_p[j] - m); su += s_p[j]; }
                    float inv = 1.f / su;
                    for (int j = 0; j < S_; j++) s_p[j] *= inv;
                }
                __syncthreads();
                if (tid < 64) {
                    float o = 0.f;
                    for (int j = 0; j < S_; j++)
                        o = fmaf(s_p[j], g_cV[l*M_*D_ + (b*S_ + j)*D_ + h*DH_ + tid], o);
                    g_dat[b*D_ + h*DH_ + tid] = o;
                }
            }
            bt += GD; gbar(bt);
            // ---- cross out-proj + residual ----
            if (bi < 128) {
                loadx(g_dat, nullptr, D_, s_h, s_sred);
                mv(dec_co + l*DD_, g_dx, D_, g_dx, D_, D_, 0, 128, 2, s_h, s_red);
            }
            bt += GD; gbar(bt);
            // ---- FFN1 (rms + relu) ----
            if (bi < 128) {
                loadx(g_dx, dec_ln3 + l*D_, D_, s_h, s_sred);
                mv(dec_w1 + l*D_*DFF_, g_dff, DFF_, nullptr, DFF_, D_, 1, 128, 4, s_h, s_red);
            }
            bt += GD; gbar(bt);
            // ---- FFN2 + residual ----
            if (bi < 128) {
                loadx(g_dff, nullptr, DFF_, s_h, s_sred);
                mv(dec_w2 + l*DFF_*D_, g_dx, D_, g_dx, D_, DFF_, 0, 128, 2, s_h, s_red);
            }
            bt += GD; gbar(bt);
        }
        // ---- lm_head (rms(dx, lnf) fused) ----
        if (bi < 128) {
            loadx(g_dx, dec_lnf, D_, s_h, s_sred);
            for (int cc = tid; cc < 251; cc += 256) {
                int col = bi*251 + cc;
                const float* __restrict__ Wc = lm_head + col;
                float a0 = 0.f, a1 = 0.f, a2 = 0.f, a3 = 0.f;
                for (int k = 0; k < D_; k += 8) {
                    float w[8];
                    #pragma unroll
                    for (int u = 0; u < 8; u++) w[u] = Wc[(k + u) * V_];
                    #pragma unroll
                    for (int u = 0; u < 8; u++) {
                        a0 = fmaf(s_h[k+u],         w[u], a0);
                        a1 = fmaf(s_h[D_ + k+u],    w[u], a1);
                        a2 = fmaf(s_h[2*D_ + k+u],  w[u], a2);
                        a3 = fmaf(s_h[3*D_ + k+u],  w[u], a3);
                    }
                }
                g_logits[0*V_ + col] = a0;
                g_logits[1*V_ + col] = a1;
                g_logits[2*V_ + col] = a2;
                g_logits[3*V_ + col] = a3;
            }
            __syncthreads();
        }
        bt += GD; gbar(bt);
        // ---- softmax + argmax + output + zero dx ----
        if (bi < B_) {
            int b = bi;
            const float* lg = &g_logits[b*V_];
            float mx = -1e30f; int mi = 0;
            for (int v = tid; v < V_; v += 256) {
                float xv = lg[v];
                if (xv > mx) { mx = xv; mi = v; }
            }
            s_red[tid] = mx; s_si[tid] = mi;
            __syncthreads();
            for (int s = 128; s; s >>= 1) {
                if (tid < s) {
                    float xo = s_red[tid+s]; int io = s_si[tid+s];
                    if (xo > s_red[tid] || (xo == s_red[tid] && io < s_si[tid])) {
                        s_red[tid] = xo; s_si[tid] = io;
                    }
                }
                __syncthreads();
            }
            float rowmax = s_red[0];
            int amax = s_si[0];
            __syncthreads();
            float su = 0.f;
            for (int v = tid; v < V_; v += 256) su += __expf(lg[v] - rowmax);
            s_red[tid] = su;
            __syncthreads();
            for (int s = 128; s; s >>= 1) { if (tid < s) s_red[tid] += s_red[tid+s]; __syncthreads(); }
            float inv = 1.f / s_red[0];
            float* po = &out[(b*T_ + t)*V_];
            for (int v = tid; v < V_; v += 256) {
                float pv = __expf(lg[v] - rowmax) * inv;
                g_probs[b*V_ + v] = pv;
                po[v] = pv;
            }
            if (tid == 0) out[B_*T_*V_ + b*T_ + t] = (amax == 0) ? 1.0f : 0.0f;
            for (int d = tid; d < D_; d += 256) g_dx[b*D_ + d] = 0.f;
            __syncthreads();
        }
        bt += GD; gbar(bt);
        // ---- ynext: g_dx += probs @ emb ----
        if (bi < 128) {
            float* ps = s_h;   // [4][251]
            int v0 = bi * 251;
            for (int i = tid; i < B_*251; i += 256) {
                int b = i / 251, j = i - b*251;
                ps[b*251 + j] = g_probs[b*V_ + v0 + j];
            }
            __syncthreads();
            const float2* eb = (const float2*)emb;
            int c = tid;
            float a0x=0,a0y=0,a1x=0,a1y=0,a2x=0,a2y=0,a3x=0,a3y=0;
            int j = 0;
            for (; j + 8 <= 251; j += 8) {
                float2 e[8];
                #pragma unroll
                for (int u = 0; u < 8; u++)
                    e[u] = eb[(size_t)(v0 + j + u) * 256 + c];
                #pragma unroll
                for (int u = 0; u < 8; u++) {
                    float p0 = ps[0*251 + j+u], p1 = ps[1*251 + j+u];
                    float p2 = ps[2*251 + j+u], p3 = ps[3*251 + j+u];
                    a0x = fmaf(p0, e[u].x, a0x); a0y = fmaf(p0, e[u].y, a0y);
                    a1x = fmaf(p1, e[u].x, a1x); a1y = fmaf(p1, e[u].y, a1y);
                    a2x = fmaf(p2, e[u].x, a2x); a2y = fmaf(p2, e[u].y, a2y);
                    a3x = fmaf(p3, e[u].x, a3x); a3y = fmaf(p3, e[u].y, a3y);
                }
            }
            for (; j < 251; j++) {
                float2 e = eb[(size_t)(v0 + j) * 256 + c];
                float p0 = ps[0*251 + j], p1 = ps[1*251 + j];
                float p2 = ps[2*251 + j], p3 = ps[3*251 + j];
                a0x = fmaf(p0, e.x, a0x); a0y = fmaf(p0, e.y, a0y);
                a1x = fmaf(p1, e.x, a1x); a1y = fmaf(p1, e.y, a1y);
                a2x = fmaf(p2, e.x, a2x); a2y = fmaf(p2, e.y, a2y);
                a3x = fmaf(p3, e.x, a3x); a3y = fmaf(p3, e.y, a3y);
            }
            int d0 = c*2, d1 = c*2 + 1;
            atomicAdd(&g_dx[0*D_+d0], a0x); atomicAdd(&g_dx[0*D_+d1], a0y);
            atomicAdd(&g_dx[1*D_+d0], a1x); atomicAdd(&g_dx[1*D_+d1], a1y);
            atomicAdd(&g_dx[2*D_+d0], a2x); atomicAdd(&g_dx[2*D_+d1], a2y);
            atomicAdd(&g_dx[3*D_+d0], a3x); atomicAdd(&g_dx[3*D_+d1], a3y);
            __syncthreads();
        }
        bt += GD; gbar(bt);
    }
}

// ---------------- host driver ----------------
extern "C" void kernel_launch(void* const* d_in, const int* in_sizes, int n_in,
                              void* d_out, int out_size) {
    const int*   ids     = (const int*)  d_in[0];
    const float* mask    = (const float*)d_in[1];
    const float* emb     = (const float*)d_in[2];
    const float* enc_wq  = (const float*)d_in[3];
    const float* enc_wk  = (const float*)d_in[4];
    const float* enc_wv  = (const float*)d_in[5];
    const float* enc_wo  = (const float*)d_in[6];
    const float* enc_ln1 = (const float*)d_in[7];
    const float* enc_w1  = (const float*)d_in[8];
    const float* enc_w2  = (const float*)d_in[9];
    const float* enc_ln2 = (const float*)d_in[10];
    const float* enc_lnf = (const float*)d_in[11];
    const float* dec_sq  = (const float*)d_in[12];
    const float* dec_sk  = (const float*)d_in[13];
    const float* dec_sv  = (const float*)d_in[14];
    const float* dec_so  = (const float*)d_in[15];
    const float* dec_ln1 = (const float*)d_in[16];
    const float* dec_cq  = (const float*)d_in[17];
    const float* dec_ck  = (const float*)d_in[18];
    const float* dec_cv  = (const float*)d_in[19];
    const float* dec_co  = (const float*)d_in[20];
    const float* dec_ln2 = (const float*)d_in[21];
    const float* dec_w1  = (const float*)d_in[22];
    const float* dec_w2  = (const float*)d_in[23];
    const float* dec_ln3 = (const float*)d_in[24];
    const float* dec_lnf = (const float*)d_in[25];
    const float* lm_head = (const float*)d_in[26];
    float* out = (float*)d_out;

    void* p;
    cudaGetSymbolAddress(&p, g_xe);  float* xe  = (float*)p;
    cudaGetSymbolAddress(&p, g_h);   float* h   = (float*)p;
    cudaGetSymbolAddress(&p, g_q);   float* q   = (float*)p;
    cudaGetSymbolAddress(&p, g_k);   float* k   = (float*)p;
    cudaGetSymbolAddress(&p, g_v);   float* v   = (float*)p;
    cudaGetSymbolAddress(&p, g_at);  float* at  = (float*)p;
    cudaGetSymbolAddress(&p, g_ff);  float* ff  = (float*)p;
    cudaGetSymbolAddress(&p, g_hs);  float* hs  = (float*)p;
    cudaGetSymbolAddress(&p, g_cK);  float* cK  = (float*)p;
    cudaGetSymbolAddress(&p, g_cV);  float* cV  = (float*)p;

    // ================= encoder =================
    k_embed<<<M_, 256>>>(ids, emb);
    for (int l = 0; l < L_; l++) {
        k_rms<<<M_, 256>>>(xe, enc_ln1 + l*D_, h);
        k_sgemm<<<dim3(8,8,3), 256>>>(h, enc_wq + l*DD_, enc_wk + l*DD_, enc_wv + l*DD_,
                                      q, k, v, nullptr, D_, D_, 0);
        k_encattn<<<32, 256>>>(mask);
        k_sgemm<<<dim3(8,8,1), 256>>>(at, enc_wo + l*DD_, enc_wo + l*DD_, enc_wo + l*DD_,
                                      xe, xe, xe, xe, D_, D_, 1);
        k_rms<<<M_, 256>>>(xe, enc_ln2 + l*D_, h);
        k_sgemm<<<dim3(32,8,1), 256>>>(h, enc_w1 + l*D_*DFF_, enc_w1 + l*D_*DFF_, enc_w1 + l*D_*DFF_,
                                       ff, ff, ff, nullptr, DFF_, D_, 2);
        k_sgemm<<<dim3(8,8,1), 256>>>(ff, enc_w2 + l*DFF_*D_, enc_w2 + l*DFF_*D_, enc_w2 + l*DFF_*D_,
                                      xe, xe, xe, xe, D_, DFF_, 1);
    }
    k_rms<<<M_, 256>>>(xe, enc_lnf, hs);
    for (int l = 0; l < L_; l++) {
        k_sgemm<<<dim3(8,8,2), 256>>>(hs, dec_ck + l*DD_, dec_cv + l*DD_, dec_cv + l*DD_,
                                      cK + l*M_*D_, cV + l*M_*D_, cV + l*M_*D_,
                                      nullptr, D_, D_, 0);
    }

    // ================= decoder: single persistent megakernel =================
    k_initdx<<<2, 256>>>(emb);
    k_reset<<<1, 1>>>();
    k_decode<<<NBLK, 256>>>(mask, emb,
                            dec_sq, dec_sk, dec_sv, dec_so, dec_ln1,
                            dec_cq, dec_co, dec_ln2,
                            dec_w1, dec_w2, dec_ln3, dec_lnf,
                            lm_head, out);
}

// round 7
// speedup vs baseline: 4.3349x; 1.0645x over previous
#include <cuda_runtime.h>
#include <math.h>

#define B_   4
#define S_   64
#define D_   512
#define H_   8
#define DH_  64
#define DFF_ 2048
#define L_   2
#define V_   32128
#define T_   16
#define M_   256          // B_*S_
#define DD_  (D_*D_)
#define NEG_ (-1e9f)
#define NBLK 128

// ---------------- device scratch ----------------
__device__ float g_xe [M_*D_];
__device__ float g_h  [M_*D_];
__device__ float g_q  [M_*D_];
__device__ float g_k  [M_*D_];
__device__ float g_v  [M_*D_];
__device__ float g_at [M_*D_];
__device__ float g_ff [M_*DFF_];
__device__ float g_hs [M_*D_];
__device__ float g_cK [L_*M_*D_];
__device__ float g_cV [L_*M_*D_];
__device__ float g_dx [B_*D_];
__device__ float g_dq [B_*D_];
__device__ float g_dat[B_*D_];
__device__ float g_dff[B_*DFF_];
__device__ float g_kc [L_*B_*T_*D_];
__device__ float g_vc [L_*B_*T_*D_];
__device__ float g_logits[B_*V_];
__device__ float g_probs [B_*V_];
__device__ unsigned g_barc;

// ---------------- shared memory union ----------------
struct SDec {
    float h[B_*DFF_];     // 32 KB
    float red[1024];
    float sred[260];
    float p[64];
    float qv[64];
    int   si[256];
};
struct SEnc {
    float As[2][16][33];
    float Ws[2][16][64];
};
struct SAtt {
    float ks[64][64];
    float vs[64][64];
    float qs[16][64];
    float sc[16][68];
};
union SU { SDec d; SEnc e; SAtt a; };

__global__ void k_reset() { g_barc = 0u; }

// ---------------- grid barrier ----------------
__device__ __forceinline__ void gbar(unsigned target) {
    __syncthreads();
    if (threadIdx.x == 0) {
        __threadfence();
        atomicAdd(&g_barc, 1u);
        while (*(volatile unsigned*)&g_barc < target) __nanosleep(64);
        __threadfence();
    }
    __syncthreads();
}

// ---------------- device SGEMM tile: C[32x64] at (mt,nt) ----------------
__device__ void dsgemm(SEnc& e, const float* __restrict__ A, const float* __restrict__ W,
                       float* __restrict__ C, const float* __restrict__ res,
                       int N, int K, int op, int mt, int nt) {
    int bx = nt * 64, by = mt * 32;
    int tid = threadIdx.x;
    int tx = tid & 15, ty = tid >> 4;
    int ar = tid >> 2, aq = tid & 3;
    int NT = K >> 4;

    float4 ra, rw;
    if (tid < 128) ra = *(const float4*)&A[(by+ar)*K + aq*4];
    rw = *(const float4*)&W[ty*N + bx + tx*4];
    if (tid < 128) {
        e.As[0][aq*4+0][ar] = ra.x; e.As[0][aq*4+1][ar] = ra.y;
        e.As[0][aq*4+2][ar] = ra.z; e.As[0][aq*4+3][ar] = ra.w;
    }
    *(float4*)&e.Ws[0][ty][tx*4] = rw;
    __syncthreads();

    float acc[2][4] = {};
    int buf = 0;
    for (int kt = 0; kt < NT; kt++) {
        bool pf = (kt + 1 < NT);
        if (pf) {
            int k0 = (kt + 1) << 4;
            if (tid < 128) ra = *(const float4*)&A[(by+ar)*K + k0 + aq*4];
            rw = *(const float4*)&W[(k0+ty)*N + bx + tx*4];
        }
        #pragma unroll
        for (int kk = 0; kk < 16; kk++) {
            float a0 = e.As[buf][kk][ty*2+0];
            float a1 = e.As[buf][kk][ty*2+1];
            float4 b = *(const float4*)&e.Ws[buf][kk][tx*4];
            acc[0][0] = fmaf(a0, b.x, acc[0][0]); acc[0][1] = fmaf(a0, b.y, acc[0][1]);
            acc[0][2] = fmaf(a0, b.z, acc[0][2]); acc[0][3] = fmaf(a0, b.w, acc[0][3]);
            acc[1][0] = fmaf(a1, b.x, acc[1][0]); acc[1][1] = fmaf(a1, b.y, acc[1][1]);
            acc[1][2] = fmaf(a1, b.z, acc[1][2]); acc[1][3] = fmaf(a1, b.w, acc[1][3]);
        }
        if (pf) {
            int nb = buf ^ 1;
            if (tid < 128) {
                e.As[nb][aq*4+0][ar] = ra.x; e.As[nb][aq*4+1][ar] = ra.y;
                e.As[nb][aq*4+2][ar] = ra.z; e.As[nb][aq*4+3][ar] = ra.w;
            }
            *(float4*)&e.Ws[nb][ty][tx*4] = rw;
            __syncthreads();
            buf = nb;
        }
    }
    #pragma unroll
    for (int i = 0; i < 2; i++) {
        int m = by + ty*2 + i, n = bx + tx*4;
        float4 v = make_float4(acc[i][0], acc[i][1], acc[i][2], acc[i][3]);
        if (op & 1) {
            float4 r4 = *(const float4*)&res[m*N + n];
            v.x += r4.x; v.y += r4.y; v.z += r4.z; v.w += r4.w;
        }
        if (op & 2) {
            v.x = fmaxf(v.x, 0.f); v.y = fmaxf(v.y, 0.f);
            v.z = fmaxf(v.z, 0.f); v.w = fmaxf(v.w, 0.f);
        }
        *(float4*)&C[m*N + n] = v;
    }
    __syncthreads();
}

// ---------------- device RMSNorm: 2 rows per block ----------------
__device__ void drms2(SDec& sd, const float* __restrict__ x, const float* __restrict__ w,
                      float* __restrict__ out) {
    int tid = threadIdx.x;
    int half = tid >> 7;            // 0,1
    int lt   = tid & 127;
    int r = blockIdx.x * 2 + half;
    float s = 0.f;
    for (int d = lt; d < D_; d += 128) { float v = x[r*D_+d]; s = fmaf(v, v, s); }
    for (int o = 16; o; o >>= 1) s += __shfl_xor_sync(0xffffffffu, s, o);
    if ((lt & 31) == 0) sd.sred[half*4 + (lt >> 5)] = s;
    __syncthreads();
    if (lt == 0) {
        float t = sd.sred[half*4] + sd.sred[half*4+1] + sd.sred[half*4+2] + sd.sred[half*4+3];
        sd.sred[8 + half] = rsqrtf(t / (float)D_ + 1e-6f);
    }
    __syncthreads();
    float rs = sd.sred[8 + half];
    for (int d = lt; d < D_; d += 128) out[r*D_+d] = x[r*D_+d] * rs * w[d];
    __syncthreads();
}

// ---------------- decode helpers ----------------
__device__ __forceinline__ void loadx(SDec& sd, const float* __restrict__ x,
                                      const float* __restrict__ ln, int K) {
    int tid = threadIdx.x;
    if (ln) {
        int r = tid >> 6, c = tid & 63;
        float s = 0.f;
        for (int k = c; k < K; k += 64) { float v = x[r*K + k]; s = fmaf(v, v, s); }
        sd.sred[tid] = s;
        __syncthreads();
        if (tid < B_) {
            float t = 0.f;
            #pragma unroll 8
            for (int i = 0; i < 64; i++) t += sd.sred[tid*64 + i];
            sd.sred[256 + tid] = rsqrtf(t / (float)K + 1e-6f);
        }
        __syncthreads();
        for (int i = tid; i < B_*K; i += 256) {
            int r2 = i / K;
            sd.h[i] = x[i] * sd.sred[256 + r2] * ln[i - r2*K];
        }
    } else {
        for (int i = tid; i < B_*K; i += 256) sd.h[i] = x[i];
    }
    __syncthreads();
}

__device__ __forceinline__ void mv(SDec& sd, const float* __restrict__ W,
                                   float* __restrict__ C, int crs,
                                   const float* __restrict__ res,
                                   int N, int K, int relu, int lcols) {
    int tid  = threadIdx.x;
    int cols = 1 << lcols;
    int c    = tid & (cols - 1);
    int ks   = tid >> lcols;
    int col  = ((int)blockIdx.x << lcols) + c;
    int kcnt = (K << lcols) >> 8;
    int kbeg = ks * kcnt;
    const float* __restrict__ Wc = W + col;
    const float* __restrict__ h_s = sd.h;
    float a0 = 0.f, a1 = 0.f, a2 = 0.f, a3 = 0.f;
    if ((kcnt & 15) == 0) {
        for (int kb = kbeg; kb < kbeg + kcnt; kb += 16) {
            float w[16];
            #pragma unroll
            for (int u = 0; u < 16; u++) w[u] = Wc[(kb + u) * N];
            #pragma unroll
            for (int u = 0; u < 16; u++) {
                int k = kb + u;
                a0 = fmaf(h_s[k],        w[u], a0);
                a1 = fmaf(h_s[K + k],    w[u], a1);
                a2 = fmaf(h_s[2*K + k],  w[u], a2);
                a3 = fmaf(h_s[3*K + k],  w[u], a3);
            }
        }
    } else {
        for (int kb = kbeg; kb < kbeg + kcnt; kb += 8) {
            float w[8];
            #pragma unroll
            for (int u = 0; u < 8; u++) w[u] = Wc[(kb + u) * N];
            #pragma unroll
            for (int u = 0; u < 8; u++) {
                int k = kb + u;
                a0 = fmaf(h_s[k],        w[u], a0);
                a1 = fmaf(h_s[K + k],    w[u], a1);
                a2 = fmaf(h_s[2*K + k],  w[u], a2);
                a3 = fmaf(h_s[3*K + k],  w[u], a3);
            }
        }
    }
    sd.red[(ks*4 + 0)*cols + c] = a0;
    sd.red[(ks*4 + 1)*cols + c] = a1;
    sd.red[(ks*4 + 2)*cols + c] = a2;
    sd.red[(ks*4 + 3)*cols + c] = a3;
    __syncthreads();
    if (tid < 4*cols) {
        int r = tid >> lcols, cc = tid & (cols - 1);
        int nsplit = 256 >> lcols;
        float v = 0.f;
        for (int s = 0; s < nsplit; s++) v += sd.red[(s*4 + r)*cols + cc];
        int colw = ((int)blockIdx.x << lcols) + cc;
        if (res)  v += res[r*N + colw];
        if (relu) v = fmaxf(v, 0.f);
        C[r*crs + colw] = v;
    }
    __syncthreads();
}

// ==================== the megakernel ====================
__global__ void __launch_bounds__(256, 1)
k_mega(const int* __restrict__ ids, const float* __restrict__ mask,
       const float* __restrict__ emb,
       const float* __restrict__ enc_wq, const float* __restrict__ enc_wk,
       const float* __restrict__ enc_wv, const float* __restrict__ enc_wo,
       const float* __restrict__ enc_ln1,
       const float* __restrict__ enc_w1, const float* __restrict__ enc_w2,
       const float* __restrict__ enc_ln2, const float* __restrict__ enc_lnf,
       const float* __restrict__ dec_sq, const float* __restrict__ dec_sk,
       const float* __restrict__ dec_sv, const float* __restrict__ dec_so,
       const float* __restrict__ dec_ln1,
       const float* __restrict__ dec_cq, const float* __restrict__ dec_ck,
       const float* __restrict__ dec_cv, const float* __restrict__ dec_co,
       const float* __restrict__ dec_ln2,
       const float* __restrict__ dec_w1, const float* __restrict__ dec_w2,
       const float* __restrict__ dec_ln3, const float* __restrict__ dec_lnf,
       const float* __restrict__ lm_head,
       float* __restrict__ out) {
    __shared__ SU u;
    int bi  = blockIdx.x;
    int tid = threadIdx.x;
    unsigned bt = 0;
    const unsigned GD = gridDim.x;

    // ================= encoder =================
    // ---- embed (2 rows per block) ----
    for (int r = bi*2; r < bi*2 + 2; r++) {
        int id = ids[r];
        for (int d = tid; d < D_; d += 256)
            g_xe[r*D_ + d] = emb[id*D_ + d];
    }
    bt += GD; gbar(bt);

    for (int l = 0; l < L_; l++) {
        // ---- rms1 ----
        drms2(u.d, g_xe, enc_ln1 + l*D_, g_h);
        bt += GD; gbar(bt);
        // ---- QKV: 192 tiles ----
        for (int tile = bi; tile < 192; tile += NBLK) {
            int z = tile / 64, tt = tile - z*64;
            const float* W = (z == 0) ? enc_wq + l*DD_ : (z == 1) ? enc_wk + l*DD_ : enc_wv + l*DD_;
            float* C = (z == 0) ? g_q : (z == 1) ? g_k : g_v;
            dsgemm(u.e, g_h, W, C, nullptr, D_, D_, 0, tt >> 3, tt & 7);
        }
        bt += GD; gbar(bt);
        // ---- attention: 128 blocks = (b,h,quarter) ----
        {
            int b = bi >> 5, h = (bi >> 2) & 7, qq = bi & 3;
            for (int i = tid; i < 4096; i += 256) {
                int j = i >> 6, d = i & 63;
                u.a.ks[j][d ^ (j & 31)] = g_k[(b*64 + j)*D_ + h*64 + d];
                u.a.vs[j][d]            = g_v[(b*64 + j)*D_ + h*64 + d];
            }
            for (int i = tid; i < 1024; i += 256) {
                int r = i >> 6, d = i & 63;
                u.a.qs[r][d] = g_q[(b*64 + qq*16 + r)*D_ + h*64 + d];
            }
            __syncthreads();
            {
                int i = tid >> 4, j0 = (tid & 15) * 4;
                float a0 = 0.f, a1 = 0.f, a2 = 0.f, a3 = 0.f;
                #pragma unroll 8
                for (int d = 0; d < 64; d++) {
                    float qv = u.a.qs[i][d];
                    a0 = fmaf(qv, u.a.ks[j0+0][d ^ ((j0+0) & 31)], a0);
                    a1 = fmaf(qv, u.a.ks[j0+1][d ^ ((j0+1) & 31)], a1);
                    a2 = fmaf(qv, u.a.ks[j0+2][d ^ ((j0+2) & 31)], a2);
                    a3 = fmaf(qv, u.a.ks[j0+3][d ^ ((j0+3) & 31)], a3);
                }
                u.a.sc[i][j0+0] = a0 * 0.125f + (1.f - mask[b*64 + j0+0]) * NEG_;
                u.a.sc[i][j0+1] = a1 * 0.125f + (1.f - mask[b*64 + j0+1]) * NEG_;
                u.a.sc[i][j0+2] = a2 * 0.125f + (1.f - mask[b*64 + j0+2]) * NEG_;
                u.a.sc[i][j0+3] = a3 * 0.125f + (1.f - mask[b*64 + j0+3]) * NEG_;
            }
            __syncthreads();
            if (tid < 16) {
                int i = tid;
                float m = -1e30f;
                for (int j = 0; j < 64; j++) m = fmaxf(m, u.a.sc[i][j]);
                float su = 0.f;
                for (int j = 0; j < 64; j++) { float e = __expf(u.a.sc[i][j] - m); u.a.sc[i][j] = e; su += e; }
                float inv = 1.f / su;
                for (int j = 0; j < 64; j++) u.a.sc[i][j] *= inv;
            }
            __syncthreads();
            {
                int i = tid >> 4, d0 = (tid & 15) * 4;
                float o0 = 0.f, o1 = 0.f, o2 = 0.f, o3 = 0.f;
                #pragma unroll 8
                for (int j = 0; j < 64; j++) {
                    float p = u.a.sc[i][j];
                    o0 = fmaf(p, u.a.vs[j][d0+0], o0);
                    o1 = fmaf(p, u.a.vs[j][d0+1], o1);
                    o2 = fmaf(p, u.a.vs[j][d0+2], o2);
                    o3 = fmaf(p, u.a.vs[j][d0+3], o3);
                }
                float* op = &g_at[(b*64 + qq*16 + i)*D_ + h*64 + d0];
                op[0] = o0; op[1] = o1; op[2] = o2; op[3] = o3;
            }
            __syncthreads();
        }
        bt += GD; gbar(bt);
        // ---- out-proj + residual: 64 tiles ----
        if (bi < 64)
            dsgemm(u.e, g_at, enc_wo + l*DD_, g_xe, g_xe, D_, D_, 1, bi >> 3, bi & 7);
        bt += GD; gbar(bt);
        // ---- rms2 ----
        drms2(u.d, g_xe, enc_ln2 + l*D_, g_h);
        bt += GD; gbar(bt);
        // ---- FFN1: 256 tiles (relu) ----
        for (int tile = bi; tile < 256; tile += NBLK) {
            int mt = tile >> 5, nt = tile & 31;
            dsgemm(u.e, g_h, enc_w1 + l*D_*DFF_, g_ff, nullptr, DFF_, D_, 2, mt, nt);
        }
        bt += GD; gbar(bt);
        // ---- FFN2 + residual: 64 tiles ----
        if (bi < 64)
            dsgemm(u.e, g_ff, enc_w2 + l*DFF_*D_, g_xe, g_xe, D_, DFF_, 1, bi >> 3, bi & 7);
        bt += GD; gbar(bt);
    }
    // ---- final rms ----
    drms2(u.d, g_xe, enc_lnf, g_hs);
    bt += GD; gbar(bt);
    // ---- cross K/V (256 tiles) + init dx ----
    for (int tile = bi; tile < 256; tile += NBLK) {
        int l = tile >> 7;
        int rem = tile & 127;
        int mat = rem >> 6;
        int tt = rem & 63;
        const float* W = mat ? dec_cv + l*DD_ : dec_ck + l*DD_;
        float* C = mat ? g_cV + l*M_*D_ : g_cK + l*M_*D_;
        dsgemm(u.e, g_hs, W, C, nullptr, D_, D_, 0, tt >> 3, tt & 7);
    }
    if (bi < B_)
        for (int d = tid; d < D_; d += 256) g_dx[bi*D_ + d] = emb[d];   // PAD_ID=0
    bt += GD; gbar(bt);

    // ================= decoder =================
    for (int t = 0; t < T_; t++) {
        for (int l = 0; l < L_; l++) {
            float* kcb = &g_kc[(size_t)(l*B_*T_ + t) * D_];
            float* vcb = &g_vc[(size_t)(l*B_*T_ + t) * D_];
            // ---- QKV ----
            loadx(u.d, g_dx, dec_ln1 + l*D_, D_);
            mv(u.d, dec_sq + l*DD_, g_dq, D_,    nullptr, D_, D_, 0, 2);
            mv(u.d, dec_sk + l*DD_, kcb,  T_*D_, nullptr, D_, D_, 0, 2);
            mv(u.d, dec_sv + l*DD_, vcb,  T_*D_, nullptr, D_, D_, 0, 2);
            bt += GD; gbar(bt);
            // ---- self-attention ----
            if (bi < 32) {
                int b = bi >> 3, h = bi & 7;
                if (tid < 64) u.d.qv[tid] = g_dq[b*D_ + h*DH_ + tid];
                __syncthreads();
                if (tid <= t) {
                    const float* kp = &g_kc[((l*B_ + b)*T_ + tid)*D_ + h*DH_];
                    float s = 0.f;
                    #pragma unroll 16
                    for (int d = 0; d < DH_; d++) s = fmaf(u.d.qv[d], kp[d], s);
                    u.d.p[tid] = s * 0.125f;
                }
                __syncthreads();
                if (tid == 0) {
                    float m = -1e30f;
                    for (int j = 0; j <= t; j++) m = fmaxf(m, u.d.p[j]);
                    float su = 0.f;
                    for (int j = 0; j <= t; j++) { u.d.p[j] = __expf(u.d.p[j] - m); su += u.d.p[j]; }
                    float inv = 1.f / su;
                    for (int j = 0; j <= t; j++) u.d.p[j] *= inv;
                }
                __syncthreads();
                if (tid < 64) {
                    float o = 0.f;
                    for (int j = 0; j <= t; j++)
                        o = fmaf(u.d.p[j], g_vc[((l*B_ + b)*T_ + j)*D_ + h*DH_ + tid], o);
                    g_dat[b*D_ + h*DH_ + tid] = o;
                }
                __syncthreads();
            }
            bt += GD; gbar(bt);
            // ---- self out-proj + residual ----
            loadx(u.d, g_dat, nullptr, D_);
            mv(u.d, dec_so + l*DD_, g_dx, D_, g_dx, D_, D_, 0, 2);
            bt += GD; gbar(bt);
            // ---- cross q ----
            loadx(u.d, g_dx, dec_ln2 + l*D_, D_);
            mv(u.d, dec_cq + l*DD_, g_dq, D_, nullptr, D_, D_, 0, 2);
            bt += GD; gbar(bt);
            // ---- cross-attention ----
            if (bi < 32) {
                int b = bi >> 3, h = bi & 7;
                if (tid < 64) u.d.qv[tid] = g_dq[b*D_ + h*DH_ + tid];
                __syncthreads();
                if (tid < 64) {
                    const float* kp = &g_cK[l*M_*D_ + (b*S_ + tid)*D_ + h*DH_];
                    float s = 0.f;
                    #pragma unroll 16
                    for (int d = 0; d < DH_; d++) s = fmaf(u.d.qv[d], kp[d], s);
                    u.d.p[tid] = s * 0.125f + (1.f - mask[b*S_ + tid]) * NEG_;
                }
                __syncthreads();
                if (tid == 0) {
                    float m = -1e30f;
                    for (int j = 0; j < S_; j++) m = fmaxf(m, u.d.p[j]);
                    float su = 0.f;
                    for (int j = 0; j < S_; j++) { u.d.p[j] = __expf(u.d.p[j] - m); su += u.d.p[j]; }
                    float inv = 1.f / su;
                    for (int j = 0; j < S_; j++) u.d.p[j] *= inv;
                }
                __syncthreads();
                if (tid < 64) {
                    float o = 0.f;
                    for (int j = 0; j < S_; j++)
                        o = fmaf(u.d.p[j], g_cV[l*M_*D_ + (b*S_ + j)*D_ + h*DH_ + tid], o);
                    g_dat[b*D_ + h*DH_ + tid] = o;
                }
                __syncthreads();
            }
            bt += GD; gbar(bt);
            // ---- cross out-proj + residual ----
            loadx(u.d, g_dat, nullptr, D_);
            mv(u.d, dec_co + l*DD_, g_dx, D_, g_dx, D_, D_, 0, 2);
            bt += GD; gbar(bt);
            // ---- FFN1 ----
            loadx(u.d, g_dx, dec_ln3 + l*D_, D_);
            mv(u.d, dec_w1 + l*D_*DFF_, g_dff, DFF_, nullptr, DFF_, D_, 1, 4);
            bt += GD; gbar(bt);
            // ---- FFN2 + residual ----
            loadx(u.d, g_dff, nullptr, DFF_);
            mv(u.d, dec_w2 + l*DFF_*D_, g_dx, D_, g_dx, D_, DFF_, 0, 2);
            bt += GD; gbar(bt);
        }
        // ---- lm_head (rms fused), 251 cols per block ----
        {
            loadx(u.d, g_dx, dec_lnf, D_);
            for (int cc = tid; cc < 251; cc += 256) {
                int col = bi*251 + cc;
                const float* __restrict__ Wc = lm_head + col;
                float a0 = 0.f, a1 = 0.f, a2 = 0.f, a3 = 0.f;
                for (int k = 0; k < D_; k += 16) {
                    float w[16];
                    #pragma unroll
                    for (int uu = 0; uu < 16; uu++) w[uu] = Wc[(k + uu) * V_];
                    #pragma unroll
                    for (int uu = 0; uu < 16; uu++) {
                        a0 = fmaf(u.d.h[k+uu],         w[uu], a0);
                        a1 = fmaf(u.d.h[D_ + k+uu],    w[uu], a1);
                        a2 = fmaf(u.d.h[2*D_ + k+uu],  w[uu], a2);
                        a3 = fmaf(u.d.h[3*D_ + k+uu],  w[uu], a3);
                    }
                }
                g_logits[0*V_ + col] = a0;
                g_logits[1*V_ + col] = a1;
                g_logits[2*V_ + col] = a2;
                g_logits[3*V_ + col] = a3;
            }
            __syncthreads();
        }
        bt += GD; gbar(bt);
        // ---- softmax + argmax + output + zero dx ----
        if (bi < B_) {
            int b = bi;
            const float* lg = &g_logits[b*V_];
            float mx = -1e30f; int mi = 0;
            for (int v = tid; v < V_; v += 256) {
                float xv = lg[v];
                if (xv > mx) { mx = xv; mi = v; }
            }
            u.d.red[tid] = mx; u.d.si[tid] = mi;
            __syncthreads();
            for (int s = 128; s; s >>= 1) {
                if (tid < s) {
                    float xo = u.d.red[tid+s]; int io = u.d.si[tid+s];
                    if (xo > u.d.red[tid] || (xo == u.d.red[tid] && io < u.d.si[tid])) {
                        u.d.red[tid] = xo; u.d.si[tid] = io;
                    }
                }
                __syncthreads();
            }
            float rowmax = u.d.red[0];
            int amax = u.d.si[0];
            __syncthreads();
            float su = 0.f;
            for (int v = tid; v < V_; v += 256) su += __expf(lg[v] - rowmax);
            u.d.red[tid] = su;
            __syncthreads();
            for (int s = 128; s; s >>= 1) { if (tid < s) u.d.red[tid] += u.d.red[tid+s]; __syncthreads(); }
            float inv = 1.f / u.d.red[0];
            float* po = &out[(b*T_ + t)*V_];
            for (int v = tid; v < V_; v += 256) {
                float pv = __expf(lg[v] - rowmax) * inv;
                g_probs[b*V_ + v] = pv;
                po[v] = pv;
            }
            if (tid == 0) out[B_*T_*V_ + b*T_ + t] = (amax == 0) ? 1.0f : 0.0f;
            for (int d = tid; d < D_; d += 256) g_dx[b*D_ + d] = 0.f;
            __syncthreads();
        }
        bt += GD; gbar(bt);
        // ---- ynext: g_dx += probs @ emb ----
        {
            float* ps = u.d.h;   // [4][251]
            int v0 = bi * 251;
            for (int i = tid; i < B_*251; i += 256) {
                int b = i / 251, j = i - b*251;
                ps[b*251 + j] = g_probs[b*V_ + v0 + j];
            }
            __syncthreads();
            const float2* eb = (const float2*)emb;
            int c = tid;
            float a0x=0,a0y=0,a1x=0,a1y=0,a2x=0,a2y=0,a3x=0,a3y=0;
            int j = 0;
            for (; j + 8 <= 251; j += 8) {
                float2 e[8];
                #pragma unroll
                for (int uu = 0; uu < 8; uu++)
                    e[uu] = eb[(size_t)(v0 + j + uu) * 256 + c];
                #pragma unroll
                for (int uu = 0; uu < 8; uu++) {
                    float p0 = ps[0*251 + j+uu], p1 = ps[1*251 + j+uu];
                    float p2 = ps[2*251 + j+uu], p3 = ps[3*251 + j+uu];
                    a0x = fmaf(p0, e[uu].x, a0x); a0y = fmaf(p0, e[uu].y, a0y);
                    a1x = fmaf(p1, e[uu].x, a1x); a1y = fmaf(p1, e[uu].y, a1y);
                    a2x = fmaf(p2, e[uu].x, a2x); a2y = fmaf(p2, e[uu].y, a2y);
                    a3x = fmaf(p3, e[uu].x, a3x); a3y = fmaf(p3, e[uu].y, a3y);
                }
            }
            for (; j < 251; j++) {
                float2 e = eb[(size_t)(v0 + j) * 256 + c];
                float p0 = ps[0*251 + j], p1 = ps[1*251 + j];
                float p2 = ps[2*251 + j], p3 = ps[3*251 + j];
                a0x = fmaf(p0, e.x, a0x); a0y = fmaf(p0, e.y, a0y);
                a1x = fmaf(p1, e.x, a1x); a1y = fmaf(p1, e.y, a1y);
                a2x = fmaf(p2, e.x, a2x); a2y = fmaf(p2, e.y, a2y);
                a3x = fmaf(p3, e.x, a3x); a3y = fmaf(p3, e.y, a3y);
            }
            int d0 = c*2, d1 = c*2 + 1;
            atomicAdd(&g_dx[0*D_+d0], a0x); atomicAdd(&g_dx[0*D_+d1], a0y);
            atomicAdd(&g_dx[1*D_+d0], a1x); atomicAdd(&g_dx[1*D_+d1], a1y);
            atomicAdd(&g_dx[2*D_+d0], a2x); atomicAdd(&g_dx[2*D_+d1], a2y);
            atomicAdd(&g_dx[3*D_+d0], a3x); atomicAdd(&g_dx[3*D_+d1], a3y);
            __syncthreads();
        }
        bt += GD; gbar(bt);
    }
}

// ---------------- host driver ----------------
extern "C" void kernel_launch(void* const* d_in, const int* in_sizes, int n_in,
                              void* d_out, int out_size) {
    const int*   ids     = (const int*)  d_in[0];
    const float* mask    = (const float*)d_in[1];
    const float* emb     = (const float*)d_in[2];
    const float* enc_wq  = (const float*)d_in[3];
    const float* enc_wk  = (const float*)d_in[4];
    const float* enc_wv  = (const float*)d_in[5];
    const float* enc_wo  = (const float*)d_in[6];
    const float* enc_ln1 = (const float*)d_in[7];
    const float* enc_w1  = (const float*)d_in[8];
    const float* enc_w2  = (const float*)d_in[9];
    const float* enc_ln2 = (const float*)d_in[10];
    const float* enc_lnf = (const float*)d_in[11];
    const float* dec_sq  = (const float*)d_in[12];
    const float* dec_sk  = (const float*)d_in[13];
    const float* dec_sv  = (const float*)d_in[14];
    const float* dec_so  = (const float*)d_in[15];
    const float* dec_ln1 = (const float*)d_in[16];
    const float* dec_cq  = (const float*)d_in[17];
    const float* dec_ck  = (const float*)d_in[18];
    const float* dec_cv  = (const float*)d_in[19];
    const float* dec_co  = (const float*)d_in[20];
    const float* dec_ln2 = (const float*)d_in[21];
    const float* dec_w1  = (const float*)d_in[22];
    const float* dec_w2  = (const float*)d_in[23];
    const float* dec_ln3 = (const float*)d_in[24];
    const float* dec_lnf = (const float*)d_in[25];
    const float* lm_head = (const float*)d_in[26];
    float* out = (float*)d_out;

    k_reset<<<1, 1>>>();
    k_mega<<<NBLK, 256>>>(ids, mask, emb,
                          enc_wq, enc_wk, enc_wv, enc_wo, enc_ln1,
                          enc_w1, enc_w2, enc_ln2, enc_lnf,
                          dec_sq, dec_sk, dec_sv, dec_so, dec_ln1,
                          dec_cq, dec_ck, dec_cv, dec_co, dec_ln2,
                          dec_w1, dec_w2, dec_ln3, dec_lnf,
                          lm_head, out);
}

// round 11
// speedup vs baseline: 5.4418x; 1.2553x over previous
#include <cuda_runtime.h>
#include <math.h>

#define B_   4
#define S_   64
#define D_   512
#define H_   8
#define DH_  64
#define DFF_ 2048
#define L_   2
#define V_   32128
#define T_   16
#define M_   256
#define DD_  (D_*D_)
#define NEG_ (-1e9f)
#define NBLK 128
#define NTH  512

// ---------------- device scratch ----------------
__device__ float g_xe [M_*D_];
__device__ float g_h  [M_*D_];
__device__ float g_q  [M_*D_];
__device__ float g_k  [M_*D_];
__device__ float g_v  [M_*D_];
__device__ float g_at [M_*D_];
__device__ float g_ff [M_*DFF_];
__device__ float g_f2a[M_*D_];
__device__ float g_f2b[M_*D_];
__device__ float g_hs [M_*D_];
__device__ float g_cK [L_*M_*D_];
__device__ float g_cV [L_*M_*D_];
__device__ float g_dxA[B_*D_];
__device__ float g_dxB[B_*D_];
__device__ float g_dq [B_*D_];
__device__ float g_dat[B_*D_];
__device__ float g_dff[B_*DFF_];
__device__ float g_kc [L_*B_*T_*D_];
__device__ float g_vc [L_*B_*T_*D_];
__device__ float g_pm [4*NBLK];
__device__ float g_ps [4*NBLK];
__device__ int   g_pi [4*NBLK];
__device__ unsigned g_barc;

// ---------------- shared memory ----------------
struct SDec {
    float h[8192];      // 32KB  (B_*DFF_ max)
    float red[2048];    // 8KB   (mv reduce / lm_head partials; red+1024 doubles as lgs)
    float sred[528];
    float p[64];
    float qv[64];
    int   si[512];
};
struct SEnc {
    float As[2][16][33];
    float Ws[2][16][64];
};
struct SAtt {
    float ks[64][64];
    float vs[64][64];
    float qs[16][64];
    float sc[16][68];
};
union SU { SDec d; SEnc e; SAtt a; };

__global__ void k_reset() { g_barc = 0u; }

// ---------------- grid barrier ----------------
__device__ __forceinline__ void gbar(unsigned target) {
    __syncthreads();
    if (threadIdx.x == 0) {
        __threadfence();
        atomicAdd(&g_barc, 1u);
        while (*(volatile unsigned*)&g_barc < target) __nanosleep(32);
        __threadfence();
    }
    __syncthreads();
}

// ---------------- encoder SGEMM tile (256-thread algorithm, 512-thread safe) --
__device__ void dsgemm(SEnc& e, const float* __restrict__ A, int lda,
                       const float* __restrict__ W,
                       float* __restrict__ C, const float* __restrict__ res,
                       int N, int K, int op, int mt, int nt) {
    int bx = nt * 64, by = mt * 32;
    int tid = threadIdx.x;
    int tx = tid & 15, ty = tid >> 4;     // valid for tid<256
    int ar = tid >> 2, aq = tid & 3;      // valid for tid<128
    int NT = K >> 4;

    float4 ra = make_float4(0,0,0,0), rw = make_float4(0,0,0,0);
    if (tid < 128) ra = *(const float4*)&A[(by+ar)*lda + aq*4];
    if (tid < 256) rw = *(const float4*)&W[ty*N + bx + tx*4];
    if (tid < 128) {
        e.As[0][aq*4+0][ar] = ra.x; e.As[0][aq*4+1][ar] = ra.y;
        e.As[0][aq*4+2][ar] = ra.z; e.As[0][aq*4+3][ar] = ra.w;
    }
    if (tid < 256) *(float4*)&e.Ws[0][ty][tx*4] = rw;
    __syncthreads();

    float acc[2][4] = {};
    int buf = 0;
    for (int kt = 0; kt < NT; kt++) {
        bool pf = (kt + 1 < NT);
        if (pf) {
            int k0 = (kt + 1) << 4;
            if (tid < 128) ra = *(const float4*)&A[(by+ar)*lda + k0 + aq*4];
            if (tid < 256) rw = *(const float4*)&W[(k0+ty)*N + bx + tx*4];
        }
        if (tid < 256) {
            #pragma unroll
            for (int kk = 0; kk < 16; kk++) {
                float a0 = e.As[buf][kk][ty*2+0];
                float a1 = e.As[buf][kk][ty*2+1];
                float4 b = *(const float4*)&e.Ws[buf][kk][tx*4];
                acc[0][0] = fmaf(a0, b.x, acc[0][0]); acc[0][1] = fmaf(a0, b.y, acc[0][1]);
                acc[0][2] = fmaf(a0, b.z, acc[0][2]); acc[0][3] = fmaf(a0, b.w, acc[0][3]);
                acc[1][0] = fmaf(a1, b.x, acc[1][0]); acc[1][1] = fmaf(a1, b.y, acc[1][1]);
                acc[1][2] = fmaf(a1, b.z, acc[1][2]); acc[1][3] = fmaf(a1, b.w, acc[1][3]);
            }
        }
        if (pf) {
            int nb = buf ^ 1;
            __syncthreads();
            if (tid < 128) {
                e.As[nb][aq*4+0][ar] = ra.x; e.As[nb][aq*4+1][ar] = ra.y;
                e.As[nb][aq*4+2][ar] = ra.z; e.As[nb][aq*4+3][ar] = ra.w;
            }
            if (tid < 256) *(float4*)&e.Ws[nb][ty][tx*4] = rw;
            __syncthreads();
            buf = nb;
        }
    }
    if (tid < 256) {
        #pragma unroll
        for (int i = 0; i < 2; i++) {
            int m = by + ty*2 + i, n = bx + tx*4;
            float4 v = make_float4(acc[i][0], acc[i][1], acc[i][2], acc[i][3]);
            if (op & 1) {
                float4 r4 = *(const float4*)&res[m*N + n];
                v.x += r4.x; v.y += r4.y; v.z += r4.z; v.w += r4.w;
            }
            if (op & 2) {
                v.x = fmaxf(v.x, 0.f); v.y = fmaxf(v.y, 0.f);
                v.z = fmaxf(v.z, 0.f); v.w = fmaxf(v.w, 0.f);
            }
            *(float4*)&C[m*N + n] = v;
        }
    }
    __syncthreads();
}

// ---------------- encoder RMSNorm (2 rows/block), optional fold x+fa+fb ------
__device__ void drms(SDec& sd, const float* __restrict__ x,
                     const float* __restrict__ fa, const float* __restrict__ fb,
                     const float* __restrict__ w,
                     float* __restrict__ xout, float* __restrict__ nout) {
    int tid = threadIdx.x;
    if (tid < 256) {
        int half = tid >> 7, lt = tid & 127;
        int r = blockIdx.x * 2 + half;
        float s = 0.f;
        for (int d = lt; d < D_; d += 128) {
            float v = x[r*D_ + d];
            if (fa) v += fa[r*D_ + d] + fb[r*D_ + d];
            sd.h[half*D_ + d] = v;
            s = fmaf(v, v, s);
        }
        for (int o = 16; o; o >>= 1) s += __shfl_xor_sync(0xffffffffu, s, o);
        if ((tid & 31) == 0) sd.sred[tid >> 5] = s;
    }
    __syncthreads();
    if (tid < 2) {
        float t = sd.sred[tid*4] + sd.sred[tid*4+1] + sd.sred[tid*4+2] + sd.sred[tid*4+3];
        sd.sred[8 + tid] = rsqrtf(t / (float)D_ + 1e-6f);
    }
    __syncthreads();
    if (tid < 256) {
        int half = tid >> 7, lt = tid & 127;
        int r = blockIdx.x * 2 + half;
        float rs = sd.sred[8 + half];
        for (int d = lt; d < D_; d += 128) {
            float v = sd.h[half*D_ + d];
            if (xout) xout[r*D_ + d] = v;
            nout[r*D_ + d] = v * rs * w[d];
        }
    }
    __syncthreads();
}

// ---------------- decode: load (optionally RMS-normed) x into smem h ---------
__device__ __forceinline__ void loadx(SDec& sd, const float* __restrict__ x,
                                      const float* __restrict__ ln, int K) {
    int tid = threadIdx.x;
    if (ln) {
        int r = tid >> 7, c = tid & 127;
        float s = 0.f;
        for (int k = c; k < K; k += 128) { float v = x[r*K + k]; s = fmaf(v, v, s); }
        sd.sred[tid] = s;
        __syncthreads();
        if (tid < B_) {
            float t = 0.f;
            for (int i = 0; i < 128; i++) t += sd.sred[tid*128 + i];
            sd.sred[512 + tid] = rsqrtf(t / (float)K + 1e-6f);
        }
        __syncthreads();
        for (int i = tid; i < B_*K; i += NTH) {
            int r2 = i / K;
            sd.h[i] = x[i] * sd.sred[512 + r2] * ln[i - r2*K];
        }
    } else {
        for (int i = tid; i < B_*K; i += NTH) sd.h[i] = x[i];
    }
    __syncthreads();
}

// ---------------- decode: one 8-col octet matvec, 64-way k-split -------------
__device__ __forceinline__ void mv_oct(SDec& sd, const float* __restrict__ W,
                                       float* __restrict__ C, int crs,
                                       const float* __restrict__ res,
                                       int N, int K, int relu, int col0) {
    int tid = threadIdx.x;
    int c  = tid & 7;
    int ks = tid >> 3;            // 0..63
    int kcnt = K >> 6;
    int kbeg = ks * kcnt;
    const float* __restrict__ Wc = W + col0 + c;
    const float* __restrict__ h_s = sd.h;
    float a0 = 0.f, a1 = 0.f, a2 = 0.f, a3 = 0.f;
    for (int kb = kbeg; kb < kbeg + kcnt; kb += 8) {
        float w[8];
        #pragma unroll
        for (int u = 0; u < 8; u++) w[u] = Wc[(kb + u) * N];
        #pragma unroll
        for (int u = 0; u < 8; u++) {
            int k = kb + u;
            a0 = fmaf(h_s[k],        w[u], a0);
            a1 = fmaf(h_s[K + k],    w[u], a1);
            a2 = fmaf(h_s[2*K + k],  w[u], a2);
            a3 = fmaf(h_s[3*K + k],  w[u], a3);
        }
    }
    int base = ks*32 + c;         // ks*32 + r*8 + c
    sd.red[base + 0 ] = a0;
    sd.red[base + 8 ] = a1;
    sd.red[base + 16] = a2;
    sd.red[base + 24] = a3;
    __syncthreads();
    // fold 64 ksplits -> 16
    sd.red[tid] += sd.red[tid + 512] + sd.red[tid + 1024] + sd.red[tid + 1536];
    __syncthreads();
    if (tid < 32) {
        int r = tid >> 3, cc = tid & 7;
        float v = 0.f;
        #pragma unroll
        for (int k2 = 0; k2 < 16; k2++) v += sd.red[k2*32 + r*8 + cc];
        int colw = col0 + cc;
        if (res)  v += res[r*crs + colw];
        if (relu) v = fmaxf(v, 0.f);
        C[r*crs + colw] = v;
    }
    __syncthreads();
}

// ==================== megakernel ====================
__global__ void __launch_bounds__(NTH, 1)
k_mega(const int* __restrict__ ids, const float* __restrict__ mask,
       const float* __restrict__ emb,
       const float* __restrict__ enc_wq, const float* __restrict__ enc_wk,
       const float* __restrict__ enc_wv, const float* __restrict__ enc_wo,
       const float* __restrict__ enc_ln1,
       const float* __restrict__ enc_w1, const float* __restrict__ enc_w2,
       const float* __restrict__ enc_ln2, const float* __restrict__ enc_lnf,
       const float* __restrict__ dec_sq, const float* __restrict__ dec_sk,
       const float* __restrict__ dec_sv, const float* __restrict__ dec_so,
       const float* __restrict__ dec_ln1,
       const float* __restrict__ dec_cq, const float* __restrict__ dec_ck,
       const float* __restrict__ dec_cv, const float* __restrict__ dec_co,
       const float* __restrict__ dec_ln2,
       const float* __restrict__ dec_w1, const float* __restrict__ dec_w2,
       const float* __restrict__ dec_ln3, const float* __restrict__ dec_lnf,
       const float* __restrict__ lm_head,
       float* __restrict__ out) {
    __shared__ SU u;
    int bi  = blockIdx.x;
    int tid = threadIdx.x;
    unsigned bt = 0;
    const unsigned GD = gridDim.x;
    float* lgs = &u.d.red[1024];   // [4][252] logits, persists lm_head -> ynext

    // ================= encoder =================
    {   // embed: 2 rows per block
        int r0 = bi * 2;
        g_xe[r0*D_ + tid]       = emb[ids[r0]*D_ + tid];
        g_xe[(r0+1)*D_ + tid]   = emb[ids[r0+1]*D_ + tid];
    }
    bt += GD; gbar(bt);

    for (int l = 0; l < L_; l++) {
        // rms1 (fold previous ffn2 halves for l>0)
        if (l == 0) drms(u.d, g_xe, nullptr, nullptr, enc_ln1, nullptr, g_h);
        else        drms(u.d, g_xe, g_f2a, g_f2b, enc_ln1 + l*D_, g_xe, g_h);
        bt += GD; gbar(bt);
        // QKV: 192 tiles
        {
            int z = bi >> 6, tt = bi & 63;
            const float* W = (z == 0) ? enc_wq + l*DD_ : enc_wk + l*DD_;
            float* C = (z == 0) ? g_q : g_k;
            dsgemm(u.e, g_h, D_, W, C, nullptr, D_, D_, 0, tt >> 3, tt & 7);
        }
        if (bi < 64)
            dsgemm(u.e, g_h, D_, enc_wv + l*DD_, g_v, nullptr, D_, D_, 0, bi >> 3, bi & 7);
        bt += GD; gbar(bt);
        // attention: 128 blocks = (b, h, quarter)
        {
            int b = bi >> 5, hh = (bi >> 2) & 7, qq = bi & 3;
            for (int i = tid; i < 4096; i += NTH) {
                int j = i >> 6, d = i & 63;
                u.a.ks[j][d ^ (j & 31)] = g_k[(b*64 + j)*D_ + hh*64 + d];
                u.a.vs[j][d]            = g_v[(b*64 + j)*D_ + hh*64 + d];
            }
            for (int i = tid; i < 1024; i += NTH) {
                int r = i >> 6, d = i & 63;
                u.a.qs[r][d] = g_q[(b*64 + qq*16 + r)*D_ + hh*64 + d];
            }
            __syncthreads();
            {
                int i = tid >> 5, j0 = (tid & 31) * 2;
                float a0 = 0.f, a1 = 0.f;
                #pragma unroll 8
                for (int d = 0; d < 64; d++) {
                    float qv = u.a.qs[i][d];
                    a0 = fmaf(qv, u.a.ks[j0+0][d ^ ((j0+0) & 31)], a0);
                    a1 = fmaf(qv, u.a.ks[j0+1][d ^ ((j0+1) & 31)], a1);
                }
                u.a.sc[i][j0+0] = a0 * 0.125f + (1.f - mask[b*64 + j0+0]) * NEG_;
                u.a.sc[i][j0+1] = a1 * 0.125f + (1.f - mask[b*64 + j0+1]) * NEG_;
            }
            __syncthreads();
            if (tid < 16) {
                int i = tid;
                float m = -1e30f;
                for (int j = 0; j < 64; j++) m = fmaxf(m, u.a.sc[i][j]);
                float su = 0.f;
                for (int j = 0; j < 64; j++) { float e = __expf(u.a.sc[i][j] - m); u.a.sc[i][j] = e; su += e; }
                float inv = 1.f / su;
                for (int j = 0; j < 64; j++) u.a.sc[i][j] *= inv;
            }
            __syncthreads();
            {
                int i = tid >> 5, d0 = (tid & 31) * 2;
                float o0 = 0.f, o1 = 0.f;
                #pragma unroll 8
                for (int j = 0; j < 64; j++) {
                    float p = u.a.sc[i][j];
                    o0 = fmaf(p, u.a.vs[j][d0+0], o0);
                    o1 = fmaf(p, u.a.vs[j][d0+1], o1);
                }
                float* op = &g_at[(b*64 + qq*16 + i)*D_ + hh*64 + d0];
                op[0] = o0; op[1] = o1;
            }
            __syncthreads();
        }
        bt += GD; gbar(bt);
        // out-proj + residual: 64 tiles
        if (bi < 64)
            dsgemm(u.e, g_at, D_, enc_wo + l*DD_, g_xe, g_xe, D_, D_, 1, bi >> 3, bi & 7);
        bt += GD; gbar(bt);
        // rms2
        drms(u.d, g_xe, nullptr, nullptr, enc_ln2 + l*D_, nullptr, g_h);
        bt += GD; gbar(bt);
        // FFN1: 256 tiles
        dsgemm(u.e, g_h, D_, enc_w1 + l*D_*DFF_, g_ff, nullptr, DFF_, D_, 2, bi >> 5, bi & 31);
        {
            int tile = bi + 128;
            dsgemm(u.e, g_h, D_, enc_w1 + l*D_*DFF_, g_ff, nullptr, DFF_, D_, 2, tile >> 5, tile & 31);
        }
        bt += GD; gbar(bt);
        // FFN2 K-split: blocks 0-63 -> f2a (K[0:1024]), 64-127 -> f2b (K[1024:2048])
        {
            int half = bi >> 6, tt = bi & 63;
            const float* W2 = enc_w2 + l*DFF_*D_ + half*1024*D_;
            const float* A2 = g_ff + half*1024;
            float* C2 = half ? g_f2b : g_f2a;
            dsgemm(u.e, A2, DFF_, W2, C2, nullptr, D_, 1024, 0, tt >> 3, tt & 7);
        }
        bt += GD; gbar(bt);
    }
    // final rms (fold last ffn2)
    drms(u.d, g_xe, g_f2a, g_f2b, enc_lnf, nullptr, g_hs);
    bt += GD; gbar(bt);
    // cross K/V (256 tiles, 2 rounds) + init dx
    for (int round = 0; round < 2; round++) {
        int tile = bi + round*128;
        int l = tile >> 7, rem = tile & 127, mat = rem >> 6, tt = rem & 63;
        const float* W = mat ? dec_cv + l*DD_ : dec_ck + l*DD_;
        float* C = mat ? g_cV + l*M_*D_ : g_cK + l*M_*D_;
        dsgemm(u.e, g_hs, D_, W, C, nullptr, D_, D_, 0, tt >> 3, tt & 7);
    }
    if (bi < B_) g_dxA[bi*D_ + tid] = emb[tid];   // PAD_ID = 0
    bt += GD; gbar(bt);

    // ================= decoder =================
    float* cur = g_dxA;
    float* nxt = g_dxB;
    for (int t = 0; t < T_; t++) {
        for (int l = 0; l < L_; l++) {
            float* kcb = &g_kc[(size_t)(l*B_*T_ + t) * D_];
            float* vcb = &g_vc[(size_t)(l*B_*T_ + t) * D_];
            // ---- QKV (octets: Q=blk0-63, K=blk64-127, V=blk0-63 round2) ----
            loadx(u.d, cur, dec_ln1 + l*D_, D_);
            if (l == 0 && tid < 16) nxt[bi*16 + tid] = 0.f;   // zero next dx buffer
            {
                int z = bi >> 6, ncol = (bi & 63) << 3;
                const float* W = z ? dec_sk + l*DD_ : dec_sq + l*DD_;
                float* C = z ? kcb : g_dq;
                int crs = z ? T_*D_ : D_;
                mv_oct(u.d, W, C, crs, nullptr, D_, D_, 0, ncol);
            }
            if (bi < 64)
                mv_oct(u.d, dec_sv + l*DD_, vcb, T_*D_, nullptr, D_, D_, 0, bi << 3);
            bt += GD; gbar(bt);
            // ---- self-attention ----
            if (bi < 32) {
                int b = bi >> 3, hh = bi & 7;
                if (tid < 64) u.d.qv[tid] = g_dq[b*D_ + hh*DH_ + tid];
                __syncthreads();
                if (tid <= t) {
                    const float* kp = &g_kc[((l*B_ + b)*T_ + tid)*D_ + hh*DH_];
                    float s = 0.f;
                    #pragma unroll 16
                    for (int d = 0; d < DH_; d++) s = fmaf(u.d.qv[d], kp[d], s);
                    u.d.p[tid] = s * 0.125f;
                }
                __syncthreads();
                if (tid == 0) {
                    float m = -1e30f;
                    for (int j = 0; j <= t; j++) m = fmaxf(m, u.d.p[j]);
                    float su = 0.f;
                    for (int j = 0; j <= t; j++) { u.d.p[j] = __expf(u.d.p[j] - m); su += u.d.p[j]; }
                    float inv = 1.f / su;
                    for (int j = 0; j <= t; j++) u.d.p[j] *= inv;
                }
                __syncthreads();
                if (tid < 64) {
                    float o = 0.f;
                    for (int j = 0; j <= t; j++)
                        o = fmaf(u.d.p[j], g_vc[((l*B_ + b)*T_ + j)*D_ + hh*DH_ + tid], o);
                    g_dat[b*D_ + hh*DH_ + tid] = o;
                }
                __syncthreads();
            }
            bt += GD; gbar(bt);
            // ---- self out-proj + residual ----
            if (bi < 64) {
                loadx(u.d, g_dat, nullptr, D_);
                mv_oct(u.d, dec_so + l*DD_, cur, D_, cur, D_, D_, 0, bi << 3);
            }
            bt += GD; gbar(bt);
            // ---- cross q ----
            if (bi < 64) {
                loadx(u.d, cur, dec_ln2 + l*D_, D_);
                mv_oct(u.d, dec_cq + l*DD_, g_dq, D_, nullptr, D_, D_, 0, bi << 3);
            }
            bt += GD; gbar(bt);
            // ---- cross-attention ----
            if (bi < 32) {
                int b = bi >> 3, hh = bi & 7;
                if (tid < 64) u.d.qv[tid] = g_dq[b*D_ + hh*DH_ + tid];
                __syncthreads();
                if (tid < 64) {
                    const float* kp = &g_cK[l*M_*D_ + (b*S_ + tid)*D_ + hh*DH_];
                    float s = 0.f;
                    #pragma unroll 16
                    for (int d = 0; d < DH_; d++) s = fmaf(u.d.qv[d], kp[d], s);
                    u.d.p[tid] = s * 0.125f + (1.f - mask[b*S_ + tid]) * NEG_;
                }
                __syncthreads();
                if (tid == 0) {
                    float m = -1e30f;
                    for (int j = 0; j < S_; j++) m = fmaxf(m, u.d.p[j]);
                    float su = 0.f;
                    for (int j = 0; j < S_; j++) { u.d.p[j] = __expf(u.d.p[j] - m); su += u.d.p[j]; }
                    float inv = 1.f / su;
                    for (int j = 0; j < S_; j++) u.d.p[j] *= inv;
                }
                __syncthreads();
                if (tid < 64) {
                    float o = 0.f;
                    for (int j = 0; j < S_; j++)
                        o = fmaf(u.d.p[j], g_cV[l*M_*D_ + (b*S_ + j)*D_ + hh*DH_ + tid], o);
                    g_dat[b*D_ + hh*DH_ + tid] = o;
                }
                __syncthreads();
            }
            bt += GD; gbar(bt);
            // ---- cross out-proj + residual ----
            if (bi < 64) {
                loadx(u.d, g_dat, nullptr, D_);
                mv_oct(u.d, dec_co + l*DD_, cur, D_, cur, D_, D_, 0, bi << 3);
            }
            bt += GD; gbar(bt);
            // ---- FFN1 (relu): 256 octets ----
            loadx(u.d, cur, dec_ln3 + l*D_, D_);
            mv_oct(u.d, dec_w1 + l*D_*DFF_, g_dff, DFF_, nullptr, DFF_, D_, 1, bi << 3);
            mv_oct(u.d, dec_w1 + l*D_*DFF_, g_dff, DFF_, nullptr, DFF_, D_, 1, (bi + 128) << 3);
            bt += GD; gbar(bt);
            // ---- FFN2 + residual: 64 octets, K=2048 ----
            if (bi < 64) {
                loadx(u.d, g_dff, nullptr, DFF_);
                mv_oct(u.d, dec_w2 + l*DFF_*D_, cur, D_, cur, D_, DFF_, 0, bi << 3);
            }
            bt += GD; gbar(bt);
        }
        // ---- lm_head (rms fused) + per-block softmax partials ----
        {
            loadx(u.d, cur, dec_lnf, D_);
            int half = tid >> 8, cc = tid & 255;
            float a0 = 0.f, a1 = 0.f, a2 = 0.f, a3 = 0.f;
            if (cc < 251) {
                const float* __restrict__ Wc = lm_head + half*256*V_ + bi*251 + cc;
                const float* __restrict__ hh = u.d.h + half*256;
                for (int k = 0; k < 256; k += 16) {
                    float w[16];
                    #pragma unroll
                    for (int uu = 0; uu < 16; uu++) w[uu] = Wc[(k + uu) * V_];
                    #pragma unroll
                    for (int uu = 0; uu < 16; uu++) {
                        a0 = fmaf(hh[k+uu],          w[uu], a0);
                        a1 = fmaf(hh[D_ + k+uu],     w[uu], a1);
                        a2 = fmaf(hh[2*D_ + k+uu],   w[uu], a2);
                        a3 = fmaf(hh[3*D_ + k+uu],   w[uu], a3);
                    }
                }
            }
            u.d.red[half*1024 + 0*256 + cc] = a0;
            u.d.red[half*1024 + 1*256 + cc] = a1;
            u.d.red[half*1024 + 2*256 + cc] = a2;
            u.d.red[half*1024 + 3*256 + cc] = a3;
            __syncthreads();
            float lgr[4];
            if (tid < 251) {
                #pragma unroll
                for (int r = 0; r < 4; r++)
                    lgr[r] = u.d.red[r*256 + tid] + u.d.red[1024 + r*256 + tid];
            }
            __syncthreads();
            if (tid < 251) {
                #pragma unroll
                for (int r = 0; r < 4; r++) lgs[r*252 + tid] = lgr[r];
            }
            __syncthreads();
            // per-block partial max/argmax/sum per row
            int r = tid >> 7, j = tid & 127;
            float v0 = lgs[r*252 + j];
            int   i0 = bi*251 + j;
            if (j + 128 < 251) {
                float v1 = lgs[r*252 + j + 128];
                if (v1 > v0) { v0 = v1; i0 = bi*251 + j + 128; }
            }
            u.d.red[tid] = v0; u.d.si[tid] = i0;
            __syncthreads();
            for (int s = 64; s; s >>= 1) {
                if (j < s) {
                    float xo = u.d.red[tid + s]; int io = u.d.si[tid + s];
                    if (xo > u.d.red[tid] || (xo == u.d.red[tid] && io < u.d.si[tid])) {
                        u.d.red[tid] = xo; u.d.si[tid] = io;
                    }
                }
                __syncthreads();
            }
            float Mb = u.d.red[r*128];
            float e = __expf(lgs[r*252 + j] - Mb);
            if (j + 128 < 251) e += __expf(lgs[r*252 + j + 128] - Mb);
            u.d.red[512 + tid] = e;
            __syncthreads();
            for (int s = 64; s; s >>= 1) {
                if (j < s) u.d.red[512 + tid] += u.d.red[512 + tid + s];
                __syncthreads();
            }
            if (j == 0) {
                g_pm[r*NBLK + bi] = Mb;
                g_ps[r*NBLK + bi] = u.d.red[512 + r*128];
                g_pi[r*NBLK + bi] = u.d.si[r*128];
            }
            __syncthreads();
        }
        bt += GD; gbar(bt);
        // ---- combine partials + probs + output + ynext ----
        {
            int r = tid >> 7, b = tid & 127;
            // max/argmax tree over 128 blocks
            u.d.red[tid] = g_pm[r*NBLK + b];
            u.d.si[tid]  = g_pi[r*NBLK + b];
            float sb = g_ps[r*NBLK + b];
            __syncthreads();
            for (int s = 64; s; s >>= 1) {
                if (b < s) {
                    float xo = u.d.red[tid + s]; int io = u.d.si[tid + s];
                    if (xo > u.d.red[tid] || (xo == u.d.red[tid] && io < u.d.si[tid])) {
                        u.d.red[tid] = xo; u.d.si[tid] = io;
                    }
                }
                __syncthreads();
            }
            float Mr = u.d.red[r*128];
            u.d.red[512 + tid] = sb * __expf(g_pm[r*NBLK + b] - Mr);
            __syncthreads();
            for (int s = 64; s; s >>= 1) {
                if (b < s) u.d.red[512 + tid] += u.d.red[512 + tid + s];
                __syncthreads();
            }
            if (b == 0) {
                u.d.sred[r] = Mr;
                u.d.sred[4 + r] = 1.f / u.d.red[512 + r*128];
            }
            __syncthreads();
            if (bi == 0 && tid < 4)
                out[B_*T_*V_ + tid*T_ + t] = (u.d.si[tid*128] == 0) ? 1.0f : 0.0f;
            // probs for this block's 251 cols (write out + smem)
            if (tid < 251) {
                #pragma unroll
                for (int rr = 0; rr < 4; rr++) {
                    float pv = __expf(lgs[rr*252 + tid] - u.d.sred[rr]) * u.d.sred[4 + rr];
                    out[(rr*T_ + t)*V_ + bi*251 + tid] = pv;
                    u.d.h[rr*251 + tid] = pv;
                }
            }
            __syncthreads();
            // nxt += probs-slice @ emb
            int v0 = bi * 251;
            int c = tid;
            float A0 = 0.f, A1 = 0.f, A2 = 0.f, A3 = 0.f;
            int j2 = 0;
            for (; j2 + 8 <= 251; j2 += 8) {
                float e8[8];
                #pragma unroll
                for (int uu = 0; uu < 8; uu++) e8[uu] = emb[(v0 + j2 + uu)*D_ + c];
                #pragma unroll
                for (int uu = 0; uu < 8; uu++) {
                    A0 = fmaf(u.d.h[0*251 + j2+uu], e8[uu], A0);
                    A1 = fmaf(u.d.h[1*251 + j2+uu], e8[uu], A1);
                    A2 = fmaf(u.d.h[2*251 + j2+uu], e8[uu], A2);
                    A3 = fmaf(u.d.h[3*251 + j2+uu], e8[uu], A3);
                }
            }
            for (; j2 < 251; j2++) {
                float e1 = emb[(v0 + j2)*D_ + c];
                A0 = fmaf(u.d.h[0*251 + j2], e1, A0);
                A1 = fmaf(u.d.h[1*251 + j2], e1, A1);
                A2 = fmaf(u.d.h[2*251 + j2], e1, A2);
                A3 = fmaf(u.d.h[3*251 + j2], e1, A3);
            }
            atomicAdd(&nxt[0*D_ + c], A0);
            atomicAdd(&nxt[1*D_ + c], A1);
            atomicAdd(&nxt[2*D_ + c], A2);
            atomicAdd(&nxt[3*D_ + c], A3);
            __syncthreads();
        }
        bt += GD; gbar(bt);
        // swap dx buffers
        float* tmp = cur; cur = nxt; nxt = tmp;
    }
}

// ---------------- host driver ----------------
extern "C" void kernel_launch(void* const* d_in, const int* in_sizes, int n_in,
                              void* d_out, int out_size) {
    const int*   ids     = (const int*)  d_in[0];
    const float* mask    = (const float*)d_in[1];
    const float* emb     = (const float*)d_in[2];
    const float* enc_wq  = (const float*)d_in[3];
    const float* enc_wk  = (const float*)d_in[4];
    const float* enc_wv  = (const float*)d_in[5];
    const float* enc_wo  = (const float*)d_in[6];
    const float* enc_ln1 = (const float*)d_in[7];
    const float* enc_w1  = (const float*)d_in[8];
    const float* enc_w2  = (const float*)d_in[9];
    const float* enc_ln2 = (const float*)d_in[10];
    const float* enc_lnf = (const float*)d_in[11];
    const float* dec_sq  = (const float*)d_in[12];
    const float* dec_sk  = (const float*)d_in[13];
    const float* dec_sv  = (const float*)d_in[14];
    const float* dec_so  = (const float*)d_in[15];
    const float* dec_ln1 = (const float*)d_in[16];
    const float* dec_cq  = (const float*)d_in[17];
    const float* dec_ck  = (const float*)d_in[18];
    const float* dec_cv  = (const float*)d_in[19];
    const float* dec_co  = (const float*)d_in[20];
    const float* dec_ln2 = (const float*)d_in[21];
    const float* dec_w1  = (const float*)d_in[22];
    const float* dec_w2  = (const float*)d_in[23];
    const float* dec_ln3 = (const float*)d_in[24];
    const float* dec_lnf = (const float*)d_in[25];
    const float* lm_head = (const float*)d_in[26];
    float* out = (float*)d_out;

    k_reset<<<1, 1>>>();
    k_mega<<<NBLK, NTH>>>(ids, mask, emb,
                          enc_wq, enc_wk, enc_wv, enc_wo, enc_ln1,
                          enc_w1, enc_w2, enc_ln2, enc_lnf,
                          dec_sq, dec_sk, dec_sv, dec_so, dec_ln1,
                          dec_cq, dec_ck, dec_cv, dec_co, dec_ln2,
                          dec_w1, dec_w2, dec_ln3, dec_lnf,
                          lm_head, out);
}

// round 12
// speedup vs baseline: 5.7437x; 1.0555x over previous
#include <cuda_runtime.h>
#include <math.h>

#define B_   4
#define S_   64
#define D_   512
#define H_   8
#define DH_  64
#define DFF_ 2048
#define L_   2
#define V_   32128
#define T_   16
#define M_   256
#define DD_  (D_*D_)
#define NEG_ (-1e9f)
#define NBLK 128
#define NTH  512

// ---------------- device scratch ----------------
__device__ float g_xe [M_*D_];
__device__ float g_h  [M_*D_];
__device__ float g_q  [M_*D_];
__device__ float g_k  [M_*D_];
__device__ float g_v  [M_*D_];
__device__ float g_at [M_*D_];
__device__ float g_ff [M_*DFF_];
__device__ float g_f2a[M_*D_];
__device__ float g_f2b[M_*D_];
__device__ float g_hs [M_*D_];
__device__ float g_cK [L_*M_*D_];
__device__ float g_cV [L_*M_*D_];
__device__ float g_dxA[B_*D_];
__device__ float g_dxB[B_*D_];
__device__ float g_so [B_*D_];
__device__ float g_co [B_*D_];
__device__ float g_dff[B_*DFF_];
__device__ float g_kc [L_*B_*T_*D_];
__device__ float g_vc [L_*B_*T_*D_];
__device__ float g_pm [4*NBLK];
__device__ float g_ps [4*NBLK];
__device__ int   g_pi [4*NBLK];
__device__ __align__(128) unsigned g_cnt;
__device__ __align__(128) volatile unsigned g_go;

// ---------------- shared memory ----------------
struct SDec {
    float h[8192];      // 32KB
    float red[2048];    // 8KB (mv reduce / lm partials; red+1024 = lgs)
    float sred[528];
    float p[64];
    float qv[64];
    int   si[512];
};
struct SEnc {
    float As[2][16][33];
    float Ws[2][16][64];
};
struct SAtt {
    float ks[64][64];
    float vs[64][64];
    float qs[16][64];
    float sc[16][68];
};
union SU { SDec d; SEnc e; SAtt a; };

__global__ void k_reset() { g_cnt = 0u; g_go = 0u; }

// ---------------- grid barrier (flag release) ----------------
__device__ __forceinline__ void gbar(unsigned ep) {
    __syncthreads();
    if (threadIdx.x == 0) {
        __threadfence();
        unsigned old = atomicAdd(&g_cnt, 1u);
        if (old + 1 == ep * gridDim.x) {
            __threadfence();
            g_go = ep;
        } else {
            while (g_go < ep) { }
        }
        __threadfence();
    }
    __syncthreads();
}

// ---------------- encoder SGEMM tile ----------------
__device__ void dsgemm(SEnc& e, const float* __restrict__ A, int lda,
                       const float* __restrict__ W,
                       float* __restrict__ C, const float* __restrict__ res,
                       int N, int K, int op, int mt, int nt) {
    int bx = nt * 64, by = mt * 32;
    int tid = threadIdx.x;
    int tx = tid & 15, ty = tid >> 4;
    int ar = tid >> 2, aq = tid & 3;
    int NT = K >> 4;

    float4 ra = make_float4(0,0,0,0), rw = make_float4(0,0,0,0);
    if (tid < 128) ra = *(const float4*)&A[(by+ar)*lda + aq*4];
    if (tid < 256) rw = *(const float4*)&W[ty*N + bx + tx*4];
    if (tid < 128) {
        e.As[0][aq*4+0][ar] = ra.x; e.As[0][aq*4+1][ar] = ra.y;
        e.As[0][aq*4+2][ar] = ra.z; e.As[0][aq*4+3][ar] = ra.w;
    }
    if (tid < 256) *(float4*)&e.Ws[0][ty][tx*4] = rw;
    __syncthreads();

    float acc[2][4] = {};
    int buf = 0;
    for (int kt = 0; kt < NT; kt++) {
        bool pf = (kt + 1 < NT);
        if (pf) {
            int k0 = (kt + 1) << 4;
            if (tid < 128) ra = *(const float4*)&A[(by+ar)*lda + k0 + aq*4];
            if (tid < 256) rw = *(const float4*)&W[(k0+ty)*N + bx + tx*4];
        }
        if (tid < 256) {
            #pragma unroll
            for (int kk = 0; kk < 16; kk++) {
                float a0 = e.As[buf][kk][ty*2+0];
                float a1 = e.As[buf][kk][ty*2+1];
                float4 b = *(const float4*)&e.Ws[buf][kk][tx*4];
                acc[0][0] = fmaf(a0, b.x, acc[0][0]); acc[0][1] = fmaf(a0, b.y, acc[0][1]);
                acc[0][2] = fmaf(a0, b.z, acc[0][2]); acc[0][3] = fmaf(a0, b.w, acc[0][3]);
                acc[1][0] = fmaf(a1, b.x, acc[1][0]); acc[1][1] = fmaf(a1, b.y, acc[1][1]);
                acc[1][2] = fmaf(a1, b.z, acc[1][2]); acc[1][3] = fmaf(a1, b.w, acc[1][3]);
            }
        }
        if (pf) {
            int nb = buf ^ 1;
            __syncthreads();
            if (tid < 128) {
                e.As[nb][aq*4+0][ar] = ra.x; e.As[nb][aq*4+1][ar] = ra.y;
                e.As[nb][aq*4+2][ar] = ra.z; e.As[nb][aq*4+3][ar] = ra.w;
            }
            if (tid < 256) *(float4*)&e.Ws[nb][ty][tx*4] = rw;
            __syncthreads();
            buf = nb;
        }
    }
    if (tid < 256) {
        #pragma unroll
        for (int i = 0; i < 2; i++) {
            int m = by + ty*2 + i, n = bx + tx*4;
            float4 v = make_float4(acc[i][0], acc[i][1], acc[i][2], acc[i][3]);
            if (op & 1) {
                float4 r4 = *(const float4*)&res[m*N + n];
                v.x += r4.x; v.y += r4.y; v.z += r4.z; v.w += r4.w;
            }
            if (op & 2) {
                v.x = fmaxf(v.x, 0.f); v.y = fmaxf(v.y, 0.f);
                v.z = fmaxf(v.z, 0.f); v.w = fmaxf(v.w, 0.f);
            }
            *(float4*)&C[m*N + n] = v;
        }
    }
    __syncthreads();
}

// ---------------- encoder RMSNorm (2 rows/block), optional fold x+fa+fb ------
__device__ void drms(SDec& sd, const float* __restrict__ x,
                     const float* __restrict__ fa, const float* __restrict__ fb,
                     const float* __restrict__ w,
                     float* __restrict__ xout, float* __restrict__ nout) {
    int tid = threadIdx.x;
    if (tid < 256) {
        int half = tid >> 7, lt = tid & 127;
        int r = blockIdx.x * 2 + half;
        float s = 0.f;
        for (int d = lt; d < D_; d += 128) {
            float v = x[r*D_ + d];
            if (fa) v += fa[r*D_ + d] + fb[r*D_ + d];
            sd.h[half*D_ + d] = v;
            s = fmaf(v, v, s);
        }
        for (int o = 16; o; o >>= 1) s += __shfl_xor_sync(0xffffffffu, s, o);
        if ((tid & 31) == 0) sd.sred[tid >> 5] = s;
    }
    __syncthreads();
    if (tid < 2) {
        float t = sd.sred[tid*4] + sd.sred[tid*4+1] + sd.sred[tid*4+2] + sd.sred[tid*4+3];
        sd.sred[8 + tid] = rsqrtf(t / (float)D_ + 1e-6f);
    }
    __syncthreads();
    if (tid < 256) {
        int half = tid >> 7, lt = tid & 127;
        int r = blockIdx.x * 2 + half;
        float rs = sd.sred[8 + half];
        for (int d = lt; d < D_; d += 128) {
            float v = sd.h[half*D_ + d];
            if (xout) xout[r*D_ + d] = v;
            nout[r*D_ + d] = v * rs * w[d];
        }
    }
    __syncthreads();
}

// ---------------- decode: load rms-normed x (4 rows) into smem h -------------
__device__ __forceinline__ void loadx(SDec& sd, const float* __restrict__ x,
                                      const float* __restrict__ ln, int K) {
    int tid = threadIdx.x;
    if (ln) {
        int r = tid >> 7, c = tid & 127;
        float s = 0.f;
        for (int k = c; k < K; k += 128) { float v = x[r*K + k]; s = fmaf(v, v, s); }
        sd.sred[tid] = s;
        __syncthreads();
        if (tid < B_) {
            float t = 0.f;
            for (int i = 0; i < 128; i++) t += sd.sred[tid*128 + i];
            sd.sred[512 + tid] = rsqrtf(t / (float)K + 1e-6f);
        }
        __syncthreads();
        for (int i = tid; i < B_*K; i += NTH) {
            int r2 = i / K;
            sd.h[i] = x[i] * sd.sred[512 + r2] * ln[i - r2*K];
        }
    } else {
        for (int i = tid; i < B_*K; i += NTH) sd.h[i] = x[i];
    }
    __syncthreads();
}

// ---------------- decode: rms-normed fold of cur+so+co (K=512) ---------------
__device__ __forceinline__ void loadx3(SDec& sd, const float* __restrict__ x,
                                       const float* __restrict__ ln) {
    int tid = threadIdx.x;
    int r = tid >> 7, c = tid & 127;
    float vv[4];
    float s = 0.f;
    #pragma unroll
    for (int q2 = 0; q2 < 4; q2++) {
        int k = c + q2*128;
        float v = x[r*D_ + k] + g_so[r*D_ + k] + g_co[r*D_ + k];
        vv[q2] = v;
        s = fmaf(v, v, s);
    }
    sd.sred[tid] = s;
    __syncthreads();
    if (tid < B_) {
        float t = 0.f;
        for (int i = 0; i < 128; i++) t += sd.sred[tid*128 + i];
        sd.sred[512 + tid] = rsqrtf(t / (float)D_ + 1e-6f);
    }
    __syncthreads();
    float rs = sd.sred[512 + r];
    #pragma unroll
    for (int q2 = 0; q2 < 4; q2++) {
        int k = c + q2*128;
        sd.h[r*D_ + k] = vv[q2] * rs * ln[k];
    }
    __syncthreads();
}

// ---------------- decode: one 8-col octet matvec, 64-way k-split -------------
__device__ __forceinline__ void mv_oct(SDec& sd, const float* __restrict__ W,
                                       float* __restrict__ C, int crs,
                                       const float* __restrict__ res,
                                       const float* __restrict__ res2,
                                       const float* __restrict__ res3,
                                       int N, int K, int relu, int col0) {
    int tid = threadIdx.x;
    int c  = tid & 7;
    int ks = tid >> 3;
    int kcnt = K >> 6;
    int kbeg = ks * kcnt;
    const float* __restrict__ Wc = W + col0 + c;
    const float* __restrict__ h_s = sd.h;
    float a0 = 0.f, a1 = 0.f, a2 = 0.f, a3 = 0.f;
    if ((kcnt & 15) == 0) {
        for (int kb = kbeg; kb < kbeg + kcnt; kb += 16) {
            float w[16];
            #pragma unroll
            for (int u = 0; u < 16; u++) w[u] = Wc[(kb + u) * N];
            #pragma unroll
            for (int u = 0; u < 16; u++) {
                int k = kb + u;
                a0 = fmaf(h_s[k],        w[u], a0);
                a1 = fmaf(h_s[K + k],    w[u], a1);
                a2 = fmaf(h_s[2*K + k],  w[u], a2);
                a3 = fmaf(h_s[3*K + k],  w[u], a3);
            }
        }
    } else {
        for (int kb = kbeg; kb < kbeg + kcnt; kb += 8) {
            float w[8];
            #pragma unroll
            for (int u = 0; u < 8; u++) w[u] = Wc[(kb + u) * N];
            #pragma unroll
            for (int u = 0; u < 8; u++) {
                int k = kb + u;
                a0 = fmaf(h_s[k],        w[u], a0);
                a1 = fmaf(h_s[K + k],    w[u], a1);
                a2 = fmaf(h_s[2*K + k],  w[u], a2);
                a3 = fmaf(h_s[3*K + k],  w[u], a3);
            }
        }
    }
    int base = ks*32 + c;
    sd.red[base + 0 ] = a0;
    sd.red[base + 8 ] = a1;
    sd.red[base + 16] = a2;
    sd.red[base + 24] = a3;
    __syncthreads();
    sd.red[tid] += sd.red[tid + 512] + sd.red[tid + 1024] + sd.red[tid + 1536];
    __syncthreads();
    if (tid < 32) {
        int r = tid >> 3, cc = tid & 7;
        float v = 0.f;
        #pragma unroll
        for (int k2 = 0; k2 < 16; k2++) v += sd.red[k2*32 + r*8 + cc];
        int colw = col0 + cc;
        if (res)  v += res[r*crs + colw];
        if (res2) v += res2[r*D_ + colw];
        if (res3) v += res3[r*D_ + colw];
        if (relu) v = fmaxf(v, 0.f);
        C[r*crs + colw] = v;
    }
    __syncthreads();
}

// ---------------- fused per-head: rms-row -> q -> attn -> outproj-acc --------
// kv: key base ptr (row j at kv + j*D_ + hh*64), nk = #keys, msk optional.
__device__ void attn_head(SDec& sd, int b, int hh,
                          const float* __restrict__ x1,
                          const float* __restrict__ x2,     // optional fold
                          const float* __restrict__ ln,
                          const float* __restrict__ Wq,
                          const float* __restrict__ kv_k, int nk,
                          const float* __restrict__ msk, int mbase,
                          const float* __restrict__ kv_v,
                          const float* __restrict__ Wo,
                          float* __restrict__ acc_out) {
    int tid = threadIdx.x;
    // rms row b
    float v = x1[b*D_ + tid];
    if (x2) v += x2[b*D_ + tid];
    float s = v * v;
    #pragma unroll
    for (int o = 16; o; o >>= 1) s += __shfl_xor_sync(0xffffffffu, s, o);
    if ((tid & 31) == 0) sd.sred[tid >> 5] = s;
    __syncthreads();
    if (tid == 0) {
        float t = 0.f;
        #pragma unroll
        for (int i = 0; i < 16; i++) t += sd.sred[i];
        sd.sred[16] = rsqrtf(t / (float)D_ + 1e-6f);
    }
    __syncthreads();
    sd.h[tid] = v * sd.sred[16] * ln[tid];
    __syncthreads();
    // q matvec: 64 cols, 8-way ksplit
    {
        int c = tid & 63, ks = tid >> 6;
        const float* __restrict__ Wqc = Wq + hh*64 + c;
        float a = 0.f;
        int kb = ks * 64;
        #pragma unroll
        for (int kk = 0; kk < 64; kk += 8) {
            float w8[8];
            #pragma unroll
            for (int u = 0; u < 8; u++) w8[u] = Wqc[(kb + kk + u) * D_];
            #pragma unroll
            for (int u = 0; u < 8; u++) a = fmaf(sd.h[kb + kk + u], w8[u], a);
        }
        sd.red[ks*64 + c] = a;
    }
    __syncthreads();
    if (tid < 64) {
        float q = 0.f;
        #pragma unroll
        for (int k2 = 0; k2 < 8; k2++) q += sd.red[k2*64 + tid];
        sd.qv[tid] = q;
    }
    __syncthreads();
    // scores
    if (tid < nk) {
        const float* kp = kv_k + tid*D_ + hh*64;
        float sc = 0.f;
        #pragma unroll 16
        for (int d = 0; d < DH_; d++) sc = fmaf(sd.qv[d], kp[d], sc);
        sc *= 0.125f;
        if (msk) sc += (1.f - msk[mbase + tid]) * NEG_;
        sd.p[tid] = sc;
    }
    __syncthreads();
    // warp softmax (nk <= 64)
    if (tid < 32) {
        float v0 = (tid < nk) ? sd.p[tid] : -1e30f;
        float v1 = (tid + 32 < nk) ? sd.p[tid + 32] : -1e30f;
        float m = fmaxf(v0, v1);
        #pragma unroll
        for (int o = 16; o; o >>= 1) m = fmaxf(m, __shfl_xor_sync(0xffffffffu, m, o));
        float e0 = (tid < nk) ? __expf(v0 - m) : 0.f;
        float e1 = (tid + 32 < nk) ? __expf(v1 - m) : 0.f;
        float su = e0 + e1;
        #pragma unroll
        for (int o = 16; o; o >>= 1) su += __shfl_xor_sync(0xffffffffu, su, o);
        float inv = 1.f / su;
        if (tid < nk) sd.p[tid] = e0 * inv;
        if (tid + 32 < nk) sd.p[tid + 32] = e1 * inv;
    }
    __syncthreads();
    // dat = p . V
    if (tid < 64) {
        float o = 0.f;
        for (int j = 0; j < nk; j++)
            o = fmaf(sd.p[j], kv_v[j*D_ + hh*64 + tid], o);
        sd.sred[256 + tid] = o;
    }
    __syncthreads();
    // out-proj partial: rank-64 update over 512 cols
    {
        const float* __restrict__ Wc = Wo + (hh*64)*D_ + tid;
        float acc = 0.f;
        #pragma unroll
        for (int d0 = 0; d0 < 64; d0 += 8) {
            float w8[8];
            #pragma unroll
            for (int u = 0; u < 8; u++) w8[u] = Wc[(d0 + u) * D_];
            #pragma unroll
            for (int u = 0; u < 8; u++) acc = fmaf(sd.sred[256 + d0 + u], w8[u], acc);
        }
        atomicAdd(&acc_out[b*D_ + tid], acc);
    }
    __syncthreads();
}

// ==================== megakernel ====================
__global__ void __launch_bounds__(NTH, 1)
k_mega(const int* __restrict__ ids, const float* __restrict__ mask,
       const float* __restrict__ emb,
       const float* __restrict__ enc_wq, const float* __restrict__ enc_wk,
       const float* __restrict__ enc_wv, const float* __restrict__ enc_wo,
       const float* __restrict__ enc_ln1,
       const float* __restrict__ enc_w1, const float* __restrict__ enc_w2,
       const float* __restrict__ enc_ln2, const float* __restrict__ enc_lnf,
       const float* __restrict__ dec_sq, const float* __restrict__ dec_sk,
       const float* __restrict__ dec_sv, const float* __restrict__ dec_so,
       const float* __restrict__ dec_ln1,
       const float* __restrict__ dec_cq, const float* __restrict__ dec_ck,
       const float* __restrict__ dec_cv, const float* __restrict__ dec_co,
       const float* __restrict__ dec_ln2,
       const float* __restrict__ dec_w1, const float* __restrict__ dec_w2,
       const float* __restrict__ dec_ln3, const float* __restrict__ dec_lnf,
       const float* __restrict__ lm_head,
       float* __restrict__ out) {
    __shared__ SU u;
    int bi  = blockIdx.x;
    int tid = threadIdx.x;
    unsigned ep = 0;
    float* lgs = &u.d.red[1024];

    // ================= encoder =================
    {
        int r0 = bi * 2;
        g_xe[r0*D_ + tid]     = emb[ids[r0]*D_ + tid];
        g_xe[(r0+1)*D_ + tid] = emb[ids[r0+1]*D_ + tid];
    }
    gbar(++ep);

    for (int l = 0; l < L_; l++) {
        if (l == 0) drms(u.d, g_xe, nullptr, nullptr, enc_ln1, nullptr, g_h);
        else        drms(u.d, g_xe, g_f2a, g_f2b, enc_ln1 + l*D_, g_xe, g_h);
        gbar(++ep);
        {
            int z = bi >> 6, tt = bi & 63;
            const float* W = (z == 0) ? enc_wq + l*DD_ : enc_wk + l*DD_;
            float* C = (z == 0) ? g_q : g_k;
            dsgemm(u.e, g_h, D_, W, C, nullptr, D_, D_, 0, tt >> 3, tt & 7);
        }
        if (bi < 64)
            dsgemm(u.e, g_h, D_, enc_wv + l*DD_, g_v, nullptr, D_, D_, 0, bi >> 3, bi & 7);
        gbar(++ep);
        {
            int b = bi >> 5, hh = (bi >> 2) & 7, qq = bi & 3;
            for (int i = tid; i < 4096; i += NTH) {
                int j = i >> 6, d = i & 63;
                u.a.ks[j][d ^ (j & 31)] = g_k[(b*64 + j)*D_ + hh*64 + d];
                u.a.vs[j][d]            = g_v[(b*64 + j)*D_ + hh*64 + d];
            }
            for (int i = tid; i < 1024; i += NTH) {
                int r = i >> 6, d = i & 63;
                u.a.qs[r][d] = g_q[(b*64 + qq*16 + r)*D_ + hh*64 + d];
            }
            __syncthreads();
            {
                int i = tid >> 5, j0 = (tid & 31) * 2;
                float a0 = 0.f, a1 = 0.f;
                #pragma unroll 8
                for (int d = 0; d < 64; d++) {
                    float qv = u.a.qs[i][d];
                    a0 = fmaf(qv, u.a.ks[j0+0][d ^ ((j0+0) & 31)], a0);
                    a1 = fmaf(qv, u.a.ks[j0+1][d ^ ((j0+1) & 31)], a1);
                }
                u.a.sc[i][j0+0] = a0 * 0.125f + (1.f - mask[b*64 + j0+0]) * NEG_;
                u.a.sc[i][j0+1] = a1 * 0.125f + (1.f - mask[b*64 + j0+1]) * NEG_;
            }
            __syncthreads();
            if (tid < 16) {
                int i = tid;
                float m = -1e30f;
                for (int j = 0; j < 64; j++) m = fmaxf(m, u.a.sc[i][j]);
                float su = 0.f;
                for (int j = 0; j < 64; j++) { float e = __expf(u.a.sc[i][j] - m); u.a.sc[i][j] = e; su += e; }
                float inv = 1.f / su;
                for (int j = 0; j < 64; j++) u.a.sc[i][j] *= inv;
            }
            __syncthreads();
            {
                int i = tid >> 5, d0 = (tid & 31) * 2;
                float o0 = 0.f, o1 = 0.f;
                #pragma unroll 8
                for (int j = 0; j < 64; j++) {
                    float p = u.a.sc[i][j];
                    o0 = fmaf(p, u.a.vs[j][d0+0], o0);
                    o1 = fmaf(p, u.a.vs[j][d0+1], o1);
                }
                float* op = &g_at[(b*64 + qq*16 + i)*D_ + hh*64 + d0];
                op[0] = o0; op[1] = o1;
            }
            __syncthreads();
        }
        gbar(++ep);
        if (bi < 64)
            dsgemm(u.e, g_at, D_, enc_wo + l*DD_, g_xe, g_xe, D_, D_, 1, bi >> 3, bi & 7);
        gbar(++ep);
        drms(u.d, g_xe, nullptr, nullptr, enc_ln2 + l*D_, nullptr, g_h);
        gbar(++ep);
        dsgemm(u.e, g_h, D_, enc_w1 + l*D_*DFF_, g_ff, nullptr, DFF_, D_, 2, bi >> 5, bi & 31);
        {
            int tile = bi + 128;
            dsgemm(u.e, g_h, D_, enc_w1 + l*D_*DFF_, g_ff, nullptr, DFF_, D_, 2, tile >> 5, tile & 31);
        }
        gbar(++ep);
        {
            int half = bi >> 6, tt = bi & 63;
            const float* W2 = enc_w2 + l*DFF_*D_ + half*1024*D_;
            const float* A2 = g_ff + half*1024;
            float* C2 = half ? g_f2b : g_f2a;
            dsgemm(u.e, A2, DFF_, W2, C2, nullptr, D_, 1024, 0, tt >> 3, tt & 7);
        }
        gbar(++ep);
    }
    drms(u.d, g_xe, g_f2a, g_f2b, enc_lnf, nullptr, g_hs);
    gbar(++ep);
    for (int round = 0; round < 2; round++) {
        int tile = bi + round*128;
        int l = tile >> 7, rem = tile & 127, mat = rem >> 6, tt = rem & 63;
        const float* W = mat ? dec_cv + l*DD_ : dec_ck + l*DD_;
        float* C = mat ? g_cV + l*M_*D_ : g_cK + l*M_*D_;
        dsgemm(u.e, g_hs, D_, W, C, nullptr, D_, D_, 0, tt >> 3, tt & 7);
    }
    if (bi < B_) g_dxA[bi*D_ + tid] = emb[tid];   // PAD_ID = 0
    gbar(++ep);

    // ================= decoder =================
    float* cur = g_dxA;
    float* nxt = g_dxB;
    for (int t = 0; t < T_; t++) {
        for (int l = 0; l < L_; l++) {
            float* kcb = &g_kc[(size_t)(l*B_*T_ + t) * D_];
            float* vcb = &g_vc[(size_t)(l*B_*T_ + t) * D_];
            // ---- S1: KV-cache (128 octets) + zero deltas (+ zero nxt) ----
            loadx(u.d, cur, dec_ln1 + l*D_, D_);
            if (tid < 16) { g_so[bi*16 + tid] = 0.f; g_co[bi*16 + tid] = 0.f; }
            if (l == 0 && tid < 16) nxt[bi*16 + tid] = 0.f;
            {
                int z = bi >> 6, ncol = (bi & 63) << 3;
                const float* W = z ? dec_sv + l*DD_ : dec_sk + l*DD_;
                float* C = z ? vcb : kcb;
                mv_oct(u.d, W, C, T_*D_, nullptr, nullptr, nullptr, D_, D_, 0, ncol);
            }
            gbar(++ep);
            // ---- S2: q + self-attn + out-proj-acc (32 blocks) ----
            if (bi < 32) {
                int b = bi >> 3, hh = bi & 7;
                attn_head(u.d, b, hh, cur, nullptr, dec_ln1 + l*D_,
                          dec_sq + l*DD_,
                          &g_kc[(size_t)(l*B_ + b)*T_*D_], t + 1, nullptr, 0,
                          &g_vc[(size_t)(l*B_ + b)*T_*D_],
                          dec_so + l*DD_, g_so);
            }
            gbar(++ep);
            // ---- S3: cq + cross-attn + out-proj-acc (32 blocks) ----
            if (bi < 32) {
                int b = bi >> 3, hh = bi & 7;
                attn_head(u.d, b, hh, cur, g_so, dec_ln2 + l*D_,
                          dec_cq + l*DD_,
                          &g_cK[(size_t)l*M_*D_ + (size_t)b*S_*D_], S_, mask, b*S_,
                          &g_cV[(size_t)l*M_*D_ + (size_t)b*S_*D_],
                          dec_co + l*DD_, g_co);
            }
            gbar(++ep);
            // ---- S4: FFN1 (relu), fold cur+so+co ----
            loadx3(u.d, cur, dec_ln3 + l*D_);
            mv_oct(u.d, dec_w1 + l*D_*DFF_, g_dff, DFF_, nullptr, nullptr, nullptr, DFF_, D_, 1, bi << 3);
            mv_oct(u.d, dec_w1 + l*D_*DFF_, g_dff, DFF_, nullptr, nullptr, nullptr, DFF_, D_, 1, (bi + 128) << 3);
            gbar(++ep);
            // ---- S5: FFN2, write cur = cur+so+co+ffn ----
            if (bi < 64) {
                loadx(u.d, g_dff, nullptr, DFF_);
                mv_oct(u.d, dec_w2 + l*DFF_*D_, cur, D_, cur, g_so, g_co, D_, DFF_, 0, bi << 3);
            }
            gbar(++ep);
        }
        // ---- lm_head + per-block softmax partials ----
        {
            loadx(u.d, cur, dec_lnf, D_);
            int half = tid >> 8, cc = tid & 255;
            float a0 = 0.f, a1 = 0.f, a2 = 0.f, a3 = 0.f;
            if (cc < 251) {
                const float* __restrict__ Wc = lm_head + half*256*V_ + bi*251 + cc;
                const float* __restrict__ hh = u.d.h + half*256;
                for (int k = 0; k < 256; k += 16) {
                    float w[16];
                    #pragma unroll
                    for (int uu = 0; uu < 16; uu++) w[uu] = Wc[(k + uu) * V_];
                    #pragma unroll
                    for (int uu = 0; uu < 16; uu++) {
                        a0 = fmaf(hh[k+uu],          w[uu], a0);
                        a1 = fmaf(hh[D_ + k+uu],     w[uu], a1);
                        a2 = fmaf(hh[2*D_ + k+uu],   w[uu], a2);
                        a3 = fmaf(hh[3*D_ + k+uu],   w[uu], a3);
                    }
                }
            }
            u.d.red[half*1024 + 0*256 + cc] = a0;
            u.d.red[half*1024 + 1*256 + cc] = a1;
            u.d.red[half*1024 + 2*256 + cc] = a2;
            u.d.red[half*1024 + 3*256 + cc] = a3;
            __syncthreads();
            float lgr[4];
            if (tid < 251) {
                #pragma unroll
                for (int r = 0; r < 4; r++)
                    lgr[r] = u.d.red[r*256 + tid] + u.d.red[1024 + r*256 + tid];
            }
            __syncthreads();
            if (tid < 251) {
                #pragma unroll
                for (int r = 0; r < 4; r++) lgs[r*252 + tid] = lgr[r];
            }
            __syncthreads();
            int r = tid >> 7, j = tid & 127;
            float v0 = lgs[r*252 + j];
            int   i0 = bi*251 + j;
            if (j + 128 < 251) {
                float v1 = lgs[r*252 + j + 128];
                if (v1 > v0) { v0 = v1; i0 = bi*251 + j + 128; }
            }
            u.d.red[tid] = v0; u.d.si[tid] = i0;
            __syncthreads();
            for (int s = 64; s; s >>= 1) {
                if (j < s) {
                    float xo = u.d.red[tid + s]; int io = u.d.si[tid + s];
                    if (xo > u.d.red[tid] || (xo == u.d.red[tid] && io < u.d.si[tid])) {
                        u.d.red[tid] = xo; u.d.si[tid] = io;
                    }
                }
                __syncthreads();
            }
            float Mb = u.d.red[r*128];
            float e = __expf(lgs[r*252 + j] - Mb);
            if (j + 128 < 251) e += __expf(lgs[r*252 + j + 128] - Mb);
            u.d.red[512 + tid] = e;
            __syncthreads();
            for (int s = 64; s; s >>= 1) {
                if (j < s) u.d.red[512 + tid] += u.d.red[512 + tid + s];
                __syncthreads();
            }
            if (j == 0) {
                g_pm[r*NBLK + bi] = Mb;
                g_ps[r*NBLK + bi] = u.d.red[512 + r*128];
                g_pi[r*NBLK + bi] = u.d.si[r*128];
            }
            __syncthreads();
        }
        gbar(++ep);
        // ---- combine partials + probs + output + ynext ----
        {
            int r = tid >> 7, b = tid & 127;
            u.d.red[tid] = g_pm[r*NBLK + b];
            u.d.si[tid]  = g_pi[r*NBLK + b];
            float sb = g_ps[r*NBLK + b];
            __syncthreads();
            for (int s = 64; s; s >>= 1) {
                if (b < s) {
                    float xo = u.d.red[tid + s]; int io = u.d.si[tid + s];
                    if (xo > u.d.red[tid] || (xo == u.d.red[tid] && io < u.d.si[tid])) {
                        u.d.red[tid] = xo; u.d.si[tid] = io;
                    }
                }
                __syncthreads();
            }
            float Mr = u.d.red[r*128];
            u.d.red[512 + tid] = sb * __expf(g_pm[r*NBLK + b] - Mr);
            __syncthreads();
            for (int s = 64; s; s >>= 1) {
                if (b < s) u.d.red[512 + tid] += u.d.red[512 + tid + s];
                __syncthreads();
            }
            if (b == 0) {
                u.d.sred[r] = Mr;
                u.d.sred[4 + r] = 1.f / u.d.red[512 + r*128];
            }
            __syncthreads();
            if (bi == 0 && tid < 4)
                out[B_*T_*V_ + tid*T_ + t] = (u.d.si[tid*128] == 0) ? 1.0f : 0.0f;
            if (tid < 251) {
                #pragma unroll
                for (int rr = 0; rr < 4; rr++) {
                    float pv = __expf(lgs[rr*252 + tid] - u.d.sred[rr]) * u.d.sred[4 + rr];
                    out[(rr*T_ + t)*V_ + bi*251 + tid] = pv;
                    u.d.h[rr*251 + tid] = pv;
                }
            }
            __syncthreads();
            int v0 = bi * 251;
            int c = tid;
            float A0 = 0.f, A1 = 0.f, A2 = 0.f, A3 = 0.f;
            int j2 = 0;
            for (; j2 + 8 <= 251; j2 += 8) {
                float e8[8];
                #pragma unroll
                for (int uu = 0; uu < 8; uu++) e8[uu] = emb[(v0 + j2 + uu)*D_ + c];
                #pragma unroll
                for (int uu = 0; uu < 8; uu++) {
                    A0 = fmaf(u.d.h[0*251 + j2+uu], e8[uu], A0);
                    A1 = fmaf(u.d.h[1*251 + j2+uu], e8[uu], A1);
                    A2 = fmaf(u.d.h[2*251 + j2+uu], e8[uu], A2);
                    A3 = fmaf(u.d.h[3*251 + j2+uu], e8[uu], A3);
                }
            }
            for (; j2 < 251; j2++) {
                float e1 = emb[(v0 + j2)*D_ + c];
                A0 = fmaf(u.d.h[0*251 + j2], e1, A0);
                A1 = fmaf(u.d.h[1*251 + j2], e1, A1);
                A2 = fmaf(u.d.h[2*251 + j2], e1, A2);
                A3 = fmaf(u.d.h[3*251 + j2], e1, A3);
            }
            atomicAdd(&nxt[0*D_ + c], A0);
            atomicAdd(&nxt[1*D_ + c], A1);
            atomicAdd(&nxt[2*D_ + c], A2);
            atomicAdd(&nxt[3*D_ + c], A3);
            __syncthreads();
        }
        gbar(++ep);
        float* tmp = cur; cur = nxt; nxt = tmp;
    }
}

// ---------------- host driver ----------------
extern "C" void kernel_launch(void* const* d_in, const int* in_sizes, int n_in,
                              void* d_out, int out_size) {
    const int*   ids     = (const int*)  d_in[0];
    const float* mask    = (const float*)d_in[1];
    const float* emb     = (const float*)d_in[2];
    const float* enc_wq  = (const float*)d_in[3];
    const float* enc_wk  = (const float*)d_in[4];
    const float* enc_wv  = (const float*)d_in[5];
    const float* enc_wo  = (const float*)d_in[6];
    const float* enc_ln1 = (const float*)d_in[7];
    const float* enc_w1  = (const float*)d_in[8];
    const float* enc_w2  = (const float*)d_in[9];
    const float* enc_ln2 = (const float*)d_in[10];
    const float* enc_lnf = (const float*)d_in[11];
    const float* dec_sq  = (const float*)d_in[12];
    const float* dec_sk  = (const float*)d_in[13];
    const float* dec_sv  = (const float*)d_in[14];
    const float* dec_so  = (const float*)d_in[15];
    const float* dec_ln1 = (const float*)d_in[16];
    const float* dec_cq  = (const float*)d_in[17];
    const float* dec_ck  = (const float*)d_in[18];
    const float* dec_cv  = (const float*)d_in[19];
    const float* dec_co  = (const float*)d_in[20];
    const float* dec_ln2 = (const float*)d_in[21];
    const float* dec_w1  = (const float*)d_in[22];
    const float* dec_w2  = (const float*)d_in[23];
    const float* dec_ln3 = (const float*)d_in[24];
    const float* dec_lnf = (const float*)d_in[25];
    const float* lm_head = (const float*)d_in[26];
    float* out = (float*)d_out;

    k_reset<<<1, 1>>>();
    k_mega<<<NBLK, NTH>>>(ids, mask, emb,
                          enc_wq, enc_wk, enc_wv, enc_wo, enc_ln1,
                          enc_w1, enc_w2, enc_ln2, enc_lnf,
                          dec_sq, dec_sk, dec_sv, dec_so, dec_ln1,
                          dec_cq, dec_ck, dec_cv, dec_co, dec_ln2,
                          dec_w1, dec_w2, dec_ln3, dec_lnf,
                          lm_head, out);
}

// round 14
// speedup vs baseline: 6.4587x; 1.1245x over previous
#include <cuda_runtime.h>
#include <cuda_fp16.h>
#include <math.h>

#define B_   4
#define S_   64
#define D_   512
#define H_   8
#define DH_  64
#define DFF_ 2048
#define L_   2
#define V_   32128
#define T_   16
#define M_   256
#define DD_  (D_*D_)
#define NEG_ (-1e9f)
#define NBLK 128
#define NTH  512

// ---------------- device scratch ----------------
__device__ float g_xe [M_*D_];
__device__ float g_h  [M_*D_];
__device__ float g_q  [M_*D_];
__device__ float g_k  [M_*D_];
__device__ float g_v  [M_*D_];
__device__ float g_at [M_*D_];
__device__ float g_ff [M_*DFF_];
__device__ float g_f2a[M_*D_];
__device__ float g_f2b[M_*D_];
__device__ float g_hs [M_*D_];
__device__ float g_cK [L_*M_*D_];
__device__ float g_cV [L_*M_*D_];
__device__ float g_dxA[B_*D_];
__device__ float g_dxB[B_*D_];
__device__ float g_dq [B_*D_];
__device__ float g_dso[B_*D_];
__device__ float g_dco[B_*D_];
__device__ float g_dff[B_*DFF_];
__device__ float g_kc [L_*B_*T_*D_];
__device__ float g_vc [L_*B_*T_*D_];
__device__ float g_pm [4*NBLK];
__device__ float g_ps [4*NBLK];
__device__ int   g_pi [4*NBLK];
// fp16 weight copies
__device__ __half w_sq[L_*DD_];
__device__ __half w_sk[L_*DD_];
__device__ __half w_sv[L_*DD_];
__device__ __half w_so[L_*DD_];
__device__ __half w_cq[L_*DD_];
__device__ __half w_co[L_*DD_];
__device__ __half w_w1[L_*D_*DFF_];
__device__ __half w_w2[L_*DFF_*D_];
__device__ __half w_lm[D_*V_];
__device__ __half w_em[V_*D_];
// barrier state
__device__ unsigned g_arr[NBLK*32];
__device__ __align__(128) volatile unsigned g_go;

// ---------------- shared memory ----------------
struct SDec {
    float h[8192];
    float red[2048];
    float sred[528];
    float p[64];
    float qv[64];
    int   si[512];
};
struct SEnc {
    float As[2][16][33];
    float Ws[2][16][64];
};
struct SAtt {
    float ks[64][64];
    float vs[64][64];
    float qs[16][64];
    float sc[16][68];
};
union SU { SDec d; SEnc e; SAtt a; };

__global__ void k_reset() {
    for (int i = threadIdx.x; i < NBLK*32; i += 128) g_arr[i] = 0u;
    if (threadIdx.x == 0) g_go = 0u;
}

// ---------------- grid barrier: distinct-slot arrive + block0 release --------
__device__ __forceinline__ void gbar(unsigned ep) {
    __syncthreads();
    int tid = threadIdx.x, bi = blockIdx.x;
    if (tid == 0) {
        __threadfence();
        *(volatile unsigned*)&g_arr[bi*32] = ep;
    }
    if (bi == 0) {
        if (tid < NBLK)
            while (*(volatile unsigned*)&g_arr[tid*32] < ep) { }
        __syncthreads();
        if (tid == 0) { __threadfence(); g_go = ep; }
        __syncthreads();
    } else {
        if (tid == 0) {
            while (g_go < ep) { }
            __threadfence();
        }
        __syncthreads();
    }
}

// ---------------- fp32 -> fp16 conversion ----------------
__device__ __forceinline__ void cvt16(const float* __restrict__ s, __half* __restrict__ d, int n) {
    int base = blockIdx.x*NTH + threadIdx.x;
    #pragma unroll 4
    for (int i = base; i < n; i += NBLK*NTH) d[i] = __float2half(s[i]);
}

// ---------------- encoder SGEMM tile ----------------
__device__ void dsgemm(SEnc& e, const float* __restrict__ A, int lda,
                       const float* __restrict__ W,
                       float* __restrict__ C, const float* __restrict__ res,
                       int N, int K, int op, int mt, int nt) {
    int bx = nt * 64, by = mt * 32;
    int tid = threadIdx.x;
    int tx = tid & 15, ty = tid >> 4;
    int ar = tid >> 2, aq = tid & 3;
    int NT = K >> 4;

    float4 ra = make_float4(0,0,0,0), rw = make_float4(0,0,0,0);
    if (tid < 128) ra = *(const float4*)&A[(by+ar)*lda + aq*4];
    if (tid < 256) rw = *(const float4*)&W[ty*N + bx + tx*4];
    if (tid < 128) {
        e.As[0][aq*4+0][ar] = ra.x; e.As[0][aq*4+1][ar] = ra.y;
        e.As[0][aq*4+2][ar] = ra.z; e.As[0][aq*4+3][ar] = ra.w;
    }
    if (tid < 256) *(float4*)&e.Ws[0][ty][tx*4] = rw;
    __syncthreads();

    float acc[2][4] = {};
    int buf = 0;
    for (int kt = 0; kt < NT; kt++) {
        bool pf = (kt + 1 < NT);
        if (pf) {
            int k0 = (kt + 1) << 4;
            if (tid < 128) ra = *(const float4*)&A[(by+ar)*lda + k0 + aq*4];
            if (tid < 256) rw = *(const float4*)&W[(k0+ty)*N + bx + tx*4];
        }
        if (tid < 256) {
            #pragma unroll
            for (int kk = 0; kk < 16; kk++) {
                float a0 = e.As[buf][kk][ty*2+0];
                float a1 = e.As[buf][kk][ty*2+1];
                float4 b = *(const float4*)&e.Ws[buf][kk][tx*4];
                acc[0][0] = fmaf(a0, b.x, acc[0][0]); acc[0][1] = fmaf(a0, b.y, acc[0][1]);
                acc[0][2] = fmaf(a0, b.z, acc[0][2]); acc[0][3] = fmaf(a0, b.w, acc[0][3]);
                acc[1][0] = fmaf(a1, b.x, acc[1][0]); acc[1][1] = fmaf(a1, b.y, acc[1][1]);
                acc[1][2] = fmaf(a1, b.z, acc[1][2]); acc[1][3] = fmaf(a1, b.w, acc[1][3]);
            }
        }
        if (pf) {
            int nb = buf ^ 1;
            __syncthreads();
            if (tid < 128) {
                e.As[nb][aq*4+0][ar] = ra.x; e.As[nb][aq*4+1][ar] = ra.y;
                e.As[nb][aq*4+2][ar] = ra.z; e.As[nb][aq*4+3][ar] = ra.w;
            }
            if (tid < 256) *(float4*)&e.Ws[nb][ty][tx*4] = rw;
            __syncthreads();
            buf = nb;
        }
    }
    if (tid < 256) {
        #pragma unroll
        for (int i = 0; i < 2; i++) {
            int m = by + ty*2 + i, n = bx + tx*4;
            float4 v = make_float4(acc[i][0], acc[i][1], acc[i][2], acc[i][3]);
            if (op & 1) {
                float4 r4 = *(const float4*)&res[m*N + n];
                v.x += r4.x; v.y += r4.y; v.z += r4.z; v.w += r4.w;
            }
            if (op & 2) {
                v.x = fmaxf(v.x, 0.f); v.y = fmaxf(v.y, 0.f);
                v.z = fmaxf(v.z, 0.f); v.w = fmaxf(v.w, 0.f);
            }
            *(float4*)&C[m*N + n] = v;
        }
    }
    __syncthreads();
}

// ---------------- encoder RMSNorm (2 rows/block) ----------------
__device__ void drms(SDec& sd, const float* __restrict__ x,
                     const float* __restrict__ fa, const float* __restrict__ fb,
                     const float* __restrict__ w,
                     float* __restrict__ xout, float* __restrict__ nout) {
    int tid = threadIdx.x;
    if (tid < 256) {
        int half = tid >> 7, lt = tid & 127;
        int r = blockIdx.x * 2 + half;
        float s = 0.f;
        for (int d = lt; d < D_; d += 128) {
            float v = x[r*D_ + d];
            if (fa) v += fa[r*D_ + d] + fb[r*D_ + d];
            sd.h[half*D_ + d] = v;
            s = fmaf(v, v, s);
        }
        for (int o = 16; o; o >>= 1) s += __shfl_xor_sync(0xffffffffu, s, o);
        if ((tid & 31) == 0) sd.sred[tid >> 5] = s;
    }
    __syncthreads();
    if (tid < 2) {
        float t = sd.sred[tid*4] + sd.sred[tid*4+1] + sd.sred[tid*4+2] + sd.sred[tid*4+3];
        sd.sred[8 + tid] = rsqrtf(t / (float)D_ + 1e-6f);
    }
    __syncthreads();
    if (tid < 256) {
        int half = tid >> 7, lt = tid & 127;
        int r = blockIdx.x * 2 + half;
        float rs = sd.sred[8 + half];
        for (int d = lt; d < D_; d += 128) {
            float v = sd.h[half*D_ + d];
            if (xout) xout[r*D_ + d] = v;
            nout[r*D_ + d] = v * rs * w[d];
        }
    }
    __syncthreads();
}

// ---------------- decode: load rms-normed x into smem h ----------------
__device__ __forceinline__ void loadx(SDec& sd, const float* __restrict__ x,
                                      const float* __restrict__ ln, int K) {
    int tid = threadIdx.x;
    if (ln) {
        int r = tid >> 7, c = tid & 127;
        float s = 0.f;
        for (int k = c; k < K; k += 128) { float v = x[r*K + k]; s = fmaf(v, v, s); }
        sd.sred[tid] = s;
        __syncthreads();
        if (tid < B_) {
            float t = 0.f;
            for (int i = 0; i < 128; i++) t += sd.sred[tid*128 + i];
            sd.sred[512 + tid] = rsqrtf(t / (float)K + 1e-6f);
        }
        __syncthreads();
        for (int i = tid; i < B_*K; i += NTH) {
            int r2 = i / K;
            sd.h[i] = x[i] * sd.sred[512 + r2] * ln[i - r2*K];
        }
    } else {
        for (int i = tid; i < B_*K; i += NTH) sd.h[i] = x[i];
    }
    __syncthreads();
}

// ---------------- decode: rms-normed fold of cur+dso+dco ----------------
__device__ __forceinline__ void loadx3(SDec& sd, const float* __restrict__ x,
                                       const float* __restrict__ ln) {
    int tid = threadIdx.x;
    int r = tid >> 7, c = tid & 127;
    float vv[4];
    float s = 0.f;
    #pragma unroll
    for (int q2 = 0; q2 < 4; q2++) {
        int k = c + q2*128;
        float v = x[r*D_ + k] + g_dso[r*D_ + k] + g_dco[r*D_ + k];
        vv[q2] = v;
        s = fmaf(v, v, s);
    }
    sd.sred[tid] = s;
    __syncthreads();
    if (tid < B_) {
        float t = 0.f;
        for (int i = 0; i < 128; i++) t += sd.sred[tid*128 + i];
        sd.sred[512 + tid] = rsqrtf(t / (float)D_ + 1e-6f);
    }
    __syncthreads();
    float rs = sd.sred[512 + r];
    #pragma unroll
    for (int q2 = 0; q2 < 4; q2++) {
        int k = c + q2*128;
        sd.h[r*D_ + k] = vv[q2] * rs * ln[k];
    }
    __syncthreads();
}

// ---------------- fp16 matvec: 16 cols/block, 32-way k-split -----------------
__device__ __forceinline__ void mv_hex(SDec& sd, const __half* __restrict__ W,
                                       float* __restrict__ C, int crs,
                                       const float* __restrict__ res,
                                       const float* __restrict__ res2,
                                       const float* __restrict__ res3,
                                       int N, int K, int relu, int col0) {
    int tid = threadIdx.x;
    int cp = tid & 7;
    int rh = (tid >> 3) & 1;
    int ks = tid >> 4;               // 0..31
    int kcnt = K >> 5;
    int kbeg = ks * kcnt;
    const __half* __restrict__ Wc = W + col0 + cp*2;
    int r0 = rh*2;
    const float* __restrict__ h0 = sd.h + r0*K;
    const float* __restrict__ h1 = sd.h + (r0+1)*K;
    float a00=0.f, a01=0.f, a10=0.f, a11=0.f;
    for (int kb = kbeg; kb < kbeg + kcnt; kb += 8) {
        __half2 w2[8];
        #pragma unroll
        for (int u = 0; u < 8; u++) w2[u] = *(const __half2*)(Wc + (size_t)(kb+u)*N);
        #pragma unroll
        for (int u = 0; u < 8; u++) {
            float2 wf = __half22float2(w2[u]);
            float hv0 = h0[kb+u], hv1 = h1[kb+u];
            a00 = fmaf(hv0, wf.x, a00); a01 = fmaf(hv0, wf.y, a01);
            a10 = fmaf(hv1, wf.x, a10); a11 = fmaf(hv1, wf.y, a11);
        }
    }
    int ci = cp*2;
    sd.red[ks*64 + (r0  )*16 + ci  ] = a00;
    sd.red[ks*64 + (r0  )*16 + ci+1] = a01;
    sd.red[ks*64 + (r0+1)*16 + ci  ] = a10;
    sd.red[ks*64 + (r0+1)*16 + ci+1] = a11;
    __syncthreads();
    // FIX (R13 bug): fold 32 ksplits with 512 threads — all partials accounted.
    sd.red[tid] += sd.red[tid + 512] + sd.red[tid + 1024] + sd.red[tid + 1536];
    __syncthreads();
    if (tid < 256) sd.red[tid] += sd.red[tid + 256];
    __syncthreads();
    if (tid < 128) sd.red[tid] += sd.red[tid + 128];
    __syncthreads();
    if (tid < 64) {
        float v = sd.red[tid] + sd.red[tid + 64];
        int r = tid >> 4, c = tid & 15;
        int colw = col0 + c;
        if (res)  v += res[r*crs + colw];
        if (res2) v += res2[r*D_ + colw];
        if (res3) v += res3[r*D_ + colw];
        if (relu) v = fmaxf(v, 0.f);
        C[r*crs + colw] = v;
    }
    __syncthreads();
}

// ---------------- self-attn (q precomputed) + fp16 out-proj ------------------
__device__ void self_attn(SDec& sd, int b, int hh, int t, int l) {
    int tid = threadIdx.x;
    if (tid < 64) sd.qv[tid] = g_dq[b*D_ + hh*DH_ + tid];
    __syncthreads();
    int nk = t + 1;
    if (tid < nk) {
        const float* kp = &g_kc[((size_t)(l*B_ + b)*T_ + tid)*D_ + hh*DH_];
        float sc = 0.f;
        #pragma unroll 16
        for (int d = 0; d < DH_; d++) sc = fmaf(sd.qv[d], kp[d], sc);
        sd.p[tid] = sc * 0.125f;
    }
    __syncthreads();
    if (tid < 32) {
        float v0 = (tid < nk) ? sd.p[tid] : -1e30f;
        float v1 = (tid + 32 < nk) ? sd.p[tid + 32] : -1e30f;
        float m = fmaxf(v0, v1);
        #pragma unroll
        for (int o = 16; o; o >>= 1) m = fmaxf(m, __shfl_xor_sync(0xffffffffu, m, o));
        float e0 = (tid < nk) ? __expf(v0 - m) : 0.f;
        float e1 = (tid + 32 < nk) ? __expf(v1 - m) : 0.f;
        float su = e0 + e1;
        #pragma unroll
        for (int o = 16; o; o >>= 1) su += __shfl_xor_sync(0xffffffffu, su, o);
        float inv = 1.f / su;
        if (tid < nk) sd.p[tid] = e0 * inv;
        if (tid + 32 < nk) sd.p[tid + 32] = e1 * inv;
    }
    __syncthreads();
    if (tid < 64) {
        float o = 0.f;
        for (int j = 0; j < nk; j++)
            o = fmaf(sd.p[j], g_vc[((size_t)(l*B_ + b)*T_ + j)*D_ + hh*DH_ + tid], o);
        sd.sred[256 + tid] = o;
    }
    __syncthreads();
    // fp16 out-proj: rank-64 update, 2 cols/thread, 2-way row split
    {
        int cp = tid & 255, rh = tid >> 8;
        const __half* __restrict__ Wc = w_so + (size_t)l*DD_ + (size_t)(hh*64 + rh*32)*D_ + cp*2;
        const float* __restrict__ dv = &sd.sred[256 + rh*32];
        float a0 = 0.f, a1 = 0.f;
        #pragma unroll
        for (int d0 = 0; d0 < 32; d0 += 8) {
            __half2 w2[8];
            #pragma unroll
            for (int u = 0; u < 8; u++) w2[u] = *(const __half2*)(Wc + (size_t)(d0+u)*D_);
            #pragma unroll
            for (int u = 0; u < 8; u++) {
                float2 wf = __half22float2(w2[u]);
                a0 = fmaf(dv[d0+u], wf.x, a0);
                a1 = fmaf(dv[d0+u], wf.y, a1);
            }
        }
        atomicAdd(&g_dso[b*D_ + cp*2    ], a0);
        atomicAdd(&g_dso[b*D_ + cp*2 + 1], a1);
    }
    __syncthreads();
}

// ---------------- cross-attn: rms(cur+dso) -> q -> attn -> fp16 out-proj -----
__device__ void cross_attn(SDec& sd, int b, int hh, int l,
                           const float* __restrict__ cur,
                           const float* __restrict__ mask,
                           const float* __restrict__ ln) {
    int tid = threadIdx.x;
    float v = cur[b*D_ + tid] + g_dso[b*D_ + tid];
    float s = v * v;
    #pragma unroll
    for (int o = 16; o; o >>= 1) s += __shfl_xor_sync(0xffffffffu, s, o);
    if ((tid & 31) == 0) sd.sred[tid >> 5] = s;
    __syncthreads();
    if (tid == 0) {
        float t = 0.f;
        #pragma unroll
        for (int i = 0; i < 16; i++) t += sd.sred[i];
        sd.sred[16] = rsqrtf(t / (float)D_ + 1e-6f);
    }
    __syncthreads();
    sd.h[tid] = v * sd.sred[16] * ln[tid];
    __syncthreads();
    // q matvec (fp16): 32 col-pairs x 16 k-splits
    {
        int c2 = tid & 31, ks = tid >> 5;
        const __half* __restrict__ Wqc = w_cq + (size_t)l*DD_ + hh*64 + c2*2;
        int kb0 = ks * 32;
        float a0 = 0.f, a1 = 0.f;
        #pragma unroll
        for (int kk = 0; kk < 32; kk += 8) {
            __half2 w2[8];
            #pragma unroll
            for (int u = 0; u < 8; u++) w2[u] = *(const __half2*)(Wqc + (size_t)(kb0+kk+u)*D_);
            #pragma unroll
            for (int u = 0; u < 8; u++) {
                float2 wf = __half22float2(w2[u]);
                float hv = sd.h[kb0+kk+u];
                a0 = fmaf(hv, wf.x, a0);
                a1 = fmaf(hv, wf.y, a1);
            }
        }
        sd.red[ks*64 + c2*2    ] = a0;
        sd.red[ks*64 + c2*2 + 1] = a1;
    }
    __syncthreads();
    #pragma unroll
    for (int s2 = 512; s2 >= 64; s2 >>= 1) {
        if (tid < s2) sd.red[tid] += sd.red[tid + s2];
        __syncthreads();
    }
    if (tid < 64) sd.qv[tid] = sd.red[tid];
    __syncthreads();
    // scores over 64 encoder positions
    if (tid < S_) {
        const float* kp = &g_cK[(size_t)l*M_*D_ + (size_t)(b*S_ + tid)*D_ + hh*DH_];
        float sc = 0.f;
        #pragma unroll 16
        for (int d = 0; d < DH_; d++) sc = fmaf(sd.qv[d], kp[d], sc);
        sd.p[tid] = sc * 0.125f + (1.f - mask[b*S_ + tid]) * NEG_;
    }
    __syncthreads();
    if (tid < 32) {
        float v0 = sd.p[tid], v1 = sd.p[tid + 32];
        float m = fmaxf(v0, v1);
        #pragma unroll
        for (int o = 16; o; o >>= 1) m = fmaxf(m, __shfl_xor_sync(0xffffffffu, m, o));
        float e0 = __expf(v0 - m), e1 = __expf(v1 - m);
        float su = e0 + e1;
        #pragma unroll
        for (int o = 16; o; o >>= 1) su += __shfl_xor_sync(0xffffffffu, su, o);
        float inv = 1.f / su;
        sd.p[tid] = e0 * inv;
        sd.p[tid + 32] = e1 * inv;
    }
    __syncthreads();
    if (tid < 64) {
        float o = 0.f;
        for (int j = 0; j < S_; j++)
            o = fmaf(sd.p[j], g_cV[(size_t)l*M_*D_ + (size_t)(b*S_ + j)*D_ + hh*DH_ + tid], o);
        sd.sred[256 + tid] = o;
    }
    __syncthreads();
    {
        int cp = tid & 255, rh = tid >> 8;
        const __half* __restrict__ Wc = w_co + (size_t)l*DD_ + (size_t)(hh*64 + rh*32)*D_ + cp*2;
        const float* __restrict__ dv = &sd.sred[256 + rh*32];
        float a0 = 0.f, a1 = 0.f;
        #pragma unroll
        for (int d0 = 0; d0 < 32; d0 += 8) {
            __half2 w2[8];
            #pragma unroll
            for (int u = 0; u < 8; u++) w2[u] = *(const __half2*)(Wc + (size_t)(d0+u)*D_);
            #pragma unroll
            for (int u = 0; u < 8; u++) {
                float2 wf = __half22float2(w2[u]);
                a0 = fmaf(dv[d0+u], wf.x, a0);
                a1 = fmaf(dv[d0+u], wf.y, a1);
            }
        }
        atomicAdd(&g_dco[b*D_ + cp*2    ], a0);
        atomicAdd(&g_dco[b*D_ + cp*2 + 1], a1);
    }
    __syncthreads();
}

// ==================== megakernel ====================
__global__ void __launch_bounds__(NTH, 1)
k_mega(const int* __restrict__ ids, const float* __restrict__ mask,
       const float* __restrict__ emb,
       const float* __restrict__ enc_wq, const float* __restrict__ enc_wk,
       const float* __restrict__ enc_wv, const float* __restrict__ enc_wo,
       const float* __restrict__ enc_ln1,
       const float* __restrict__ enc_w1, const float* __restrict__ enc_w2,
       const float* __restrict__ enc_ln2, const float* __restrict__ enc_lnf,
       const float* __restrict__ dec_sq, const float* __restrict__ dec_sk,
       const float* __restrict__ dec_sv, const float* __restrict__ dec_so,
       const float* __restrict__ dec_ln1,
       const float* __restrict__ dec_cq, const float* __restrict__ dec_ck,
       const float* __restrict__ dec_cv, const float* __restrict__ dec_co,
       const float* __restrict__ dec_ln2,
       const float* __restrict__ dec_w1, const float* __restrict__ dec_w2,
       const float* __restrict__ dec_ln3, const float* __restrict__ dec_lnf,
       const float* __restrict__ lm_head,
       float* __restrict__ out) {
    __shared__ SU u;
    int bi  = blockIdx.x;
    int tid = threadIdx.x;
    unsigned ep = 0;
    float* lgs = &u.d.red[1024];

    // ---- fp32 -> fp16 weight conversion (one-time per launch) ----
    cvt16(dec_sq, w_sq, L_*DD_);
    cvt16(dec_sk, w_sk, L_*DD_);
    cvt16(dec_sv, w_sv, L_*DD_);
    cvt16(dec_so, w_so, L_*DD_);
    cvt16(dec_cq, w_cq, L_*DD_);
    cvt16(dec_co, w_co, L_*DD_);
    cvt16(dec_w1, w_w1, L_*D_*DFF_);
    cvt16(dec_w2, w_w2, L_*DFF_*D_);
    cvt16(lm_head, w_lm, D_*V_);
    cvt16(emb, w_em, V_*D_);

    // ================= encoder =================
    {
        int r0 = bi * 2;
        g_xe[r0*D_ + tid]     = emb[ids[r0]*D_ + tid];
        g_xe[(r0+1)*D_ + tid] = emb[ids[r0+1]*D_ + tid];
    }
    gbar(++ep);

    for (int l = 0; l < L_; l++) {
        if (l == 0) drms(u.d, g_xe, nullptr, nullptr, enc_ln1, nullptr, g_h);
        else        drms(u.d, g_xe, g_f2a, g_f2b, enc_ln1 + l*D_, g_xe, g_h);
        gbar(++ep);
        {
            int z = bi >> 6, tt = bi & 63;
            const float* W = (z == 0) ? enc_wq + l*DD_ : enc_wk + l*DD_;
            float* C = (z == 0) ? g_q : g_k;
            dsgemm(u.e, g_h, D_, W, C, nullptr, D_, D_, 0, tt >> 3, tt & 7);
        }
        if (bi < 64)
            dsgemm(u.e, g_h, D_, enc_wv + l*DD_, g_v, nullptr, D_, D_, 0, bi >> 3, bi & 7);
        gbar(++ep);
        {
            int b = bi >> 5, hh = (bi >> 2) & 7, qq = bi & 3;
            for (int i = tid; i < 4096; i += NTH) {
                int j = i >> 6, d = i & 63;
                u.a.ks[j][d ^ (j & 31)] = g_k[(b*64 + j)*D_ + hh*64 + d];
                u.a.vs[j][d]            = g_v[(b*64 + j)*D_ + hh*64 + d];
            }
            for (int i = tid; i < 1024; i += NTH) {
                int r = i >> 6, d = i & 63;
                u.a.qs[r][d] = g_q[(b*64 + qq*16 + r)*D_ + hh*64 + d];
            }
            __syncthreads();
            {
                int i = tid >> 5, j0 = (tid & 31) * 2;
                float a0 = 0.f, a1 = 0.f;
                #pragma unroll 8
                for (int d = 0; d < 64; d++) {
                    float qv = u.a.qs[i][d];
                    a0 = fmaf(qv, u.a.ks[j0+0][d ^ ((j0+0) & 31)], a0);
                    a1 = fmaf(qv, u.a.ks[j0+1][d ^ ((j0+1) & 31)], a1);
                }
                u.a.sc[i][j0+0] = a0 * 0.125f + (1.f - mask[b*64 + j0+0]) * NEG_;
                u.a.sc[i][j0+1] = a1 * 0.125f + (1.f - mask[b*64 + j0+1]) * NEG_;
            }
            __syncthreads();
            if (tid < 16) {
                int i = tid;
                float m = -1e30f;
                for (int j = 0; j < 64; j++) m = fmaxf(m, u.a.sc[i][j]);
                float su = 0.f;
                for (int j = 0; j < 64; j++) { float e = __expf(u.a.sc[i][j] - m); u.a.sc[i][j] = e; su += e; }
                float inv = 1.f / su;
                for (int j = 0; j < 64; j++) u.a.sc[i][j] *= inv;
            }
            __syncthreads();
            {
                int i = tid >> 5, d0 = (tid & 31) * 2;
                float o0 = 0.f, o1 = 0.f;
                #pragma unroll 8
                for (int j = 0; j < 64; j++) {
                    float p = u.a.sc[i][j];
                    o0 = fmaf(p, u.a.vs[j][d0+0], o0);
                    o1 = fmaf(p, u.a.vs[j][d0+1], o1);
                }
                float* op = &g_at[(b*64 + qq*16 + i)*D_ + hh*64 + d0];
                op[0] = o0; op[1] = o1;
            }
            __syncthreads();
        }
        gbar(++ep);
        if (bi < 64)
            dsgemm(u.e, g_at, D_, enc_wo + l*DD_, g_xe, g_xe, D_, D_, 1, bi >> 3, bi & 7);
        gbar(++ep);
        drms(u.d, g_xe, nullptr, nullptr, enc_ln2 + l*D_, nullptr, g_h);
        gbar(++ep);
        dsgemm(u.e, g_h, D_, enc_w1 + l*D_*DFF_, g_ff, nullptr, DFF_, D_, 2, bi >> 5, bi & 31);
        {
            int tile = bi + 128;
            dsgemm(u.e, g_h, D_, enc_w1 + l*D_*DFF_, g_ff, nullptr, DFF_, D_, 2, tile >> 5, tile & 31);
        }
        gbar(++ep);
        {
            int half = bi >> 6, tt = bi & 63;
            const float* W2 = enc_w2 + l*DFF_*D_ + half*1024*D_;
            const float* A2 = g_ff + half*1024;
            float* C2 = half ? g_f2b : g_f2a;
            dsgemm(u.e, A2, DFF_, W2, C2, nullptr, D_, 1024, 0, tt >> 3, tt & 7);
        }
        gbar(++ep);
    }
    drms(u.d, g_xe, g_f2a, g_f2b, enc_lnf, nullptr, g_hs);
    gbar(++ep);
    for (int round = 0; round < 2; round++) {
        int tile = bi + round*128;
        int l = tile >> 7, rem = tile & 127, mat = rem >> 6, tt = rem & 63;
        const float* W = mat ? dec_cv + l*DD_ : dec_ck + l*DD_;
        float* C = mat ? g_cV + l*M_*D_ : g_cK + l*M_*D_;
        dsgemm(u.e, g_hs, D_, W, C, nullptr, D_, D_, 0, tt >> 3, tt & 7);
    }
    if (bi < B_) g_dxA[bi*D_ + tid] = emb[tid];   // PAD_ID = 0
    gbar(++ep);

    // ================= decoder =================
    float* cur = g_dxA;
    float* nxt = g_dxB;
    for (int t = 0; t < T_; t++) {
        for (int l = 0; l < L_; l++) {
            float* kcb = &g_kc[(size_t)(l*B_*T_ + t) * D_];
            float* vcb = &g_vc[(size_t)(l*B_*T_ + t) * D_];
            // ---- S1: K,V,Q projections (96 blocks) + zero deltas ----
            if (bi < 96) loadx(u.d, cur, dec_ln1 + l*D_, D_);
            if (tid < 16) { g_dso[bi*16 + tid] = 0.f; g_dco[bi*16 + tid] = 0.f; }
            if (l == 0 && tid < 16) nxt[bi*16 + tid] = 0.f;
            if (bi < 32)
                mv_hex(u.d, w_sk + (size_t)l*DD_, kcb, T_*D_, nullptr, nullptr, nullptr, D_, D_, 0, bi*16);
            else if (bi < 64)
                mv_hex(u.d, w_sv + (size_t)l*DD_, vcb, T_*D_, nullptr, nullptr, nullptr, D_, D_, 0, (bi-32)*16);
            else if (bi < 96)
                mv_hex(u.d, w_sq + (size_t)l*DD_, g_dq, D_, nullptr, nullptr, nullptr, D_, D_, 0, (bi-64)*16);
            gbar(++ep);
            // ---- S2: self-attn + out-proj (32 blocks) ----
            if (bi < 32) self_attn(u.d, bi >> 3, bi & 7, t, l);
            gbar(++ep);
            // ---- S3: cross q + attn + out-proj (32 blocks) ----
            if (bi < 32) cross_attn(u.d, bi >> 3, bi & 7, l, cur, mask, dec_ln2 + l*D_);
            gbar(++ep);
            // ---- S4: FFN1 (relu), fold cur+dso+dco, 128 blocks x 16 cols ----
            loadx3(u.d, cur, dec_ln3 + l*D_);
            mv_hex(u.d, w_w1 + (size_t)l*D_*DFF_, g_dff, DFF_, nullptr, nullptr, nullptr, DFF_, D_, 1, bi*16);
            gbar(++ep);
            // ---- S5: FFN2 + all residuals (32 blocks) ----
            if (bi < 32) {
                loadx(u.d, g_dff, nullptr, DFF_);
                mv_hex(u.d, w_w2 + (size_t)l*DFF_*D_, cur, D_, cur, g_dso, g_dco, D_, DFF_, 0, bi*16);
            }
            gbar(++ep);
        }
        // ---- lm_head (fp16) + per-block softmax partials ----
        {
            loadx(u.d, cur, dec_lnf, D_);
            int half = tid >> 8, cc = tid & 255;
            float a0 = 0.f, a1 = 0.f, a2 = 0.f, a3 = 0.f;
            if (cc < 251) {
                const __half* __restrict__ Wc = w_lm + (size_t)half*256*V_ + bi*251 + cc;
                const float* __restrict__ hh = u.d.h + half*256;
                for (int k = 0; k < 256; k += 16) {
                    float w[16];
                    #pragma unroll
                    for (int uu = 0; uu < 16; uu++) w[uu] = __half2float(Wc[(size_t)(k + uu) * V_]);
                    #pragma unroll
                    for (int uu = 0; uu < 16; uu++) {
                        a0 = fmaf(hh[k+uu],          w[uu], a0);
                        a1 = fmaf(hh[D_ + k+uu],     w[uu], a1);
                        a2 = fmaf(hh[2*D_ + k+uu],   w[uu], a2);
                        a3 = fmaf(hh[3*D_ + k+uu],   w[uu], a3);
                    }
                }
            }
            u.d.red[half*1024 + 0*256 + cc] = a0;
            u.d.red[half*1024 + 1*256 + cc] = a1;
            u.d.red[half*1024 + 2*256 + cc] = a2;
            u.d.red[half*1024 + 3*256 + cc] = a3;
            __syncthreads();
            float lgr[4];
            if (tid < 251) {
                #pragma unroll
                for (int r = 0; r < 4; r++)
                    lgr[r] = u.d.red[r*256 + tid] + u.d.red[1024 + r*256 + tid];
            }
            __syncthreads();
            if (tid < 251) {
                #pragma unroll
                for (int r = 0; r < 4; r++) lgs[r*252 + tid] = lgr[r];
            }
            __syncthreads();
            int r = tid >> 7, j = tid & 127;
            float v0 = lgs[r*252 + j];
            int   i0 = bi*251 + j;
            if (j + 128 < 251) {
                float v1 = lgs[r*252 + j + 128];
                if (v1 > v0) { v0 = v1; i0 = bi*251 + j + 128; }
            }
            u.d.red[tid] = v0; u.d.si[tid] = i0;
            __syncthreads();
            for (int s = 64; s; s >>= 1) {
                if (j < s) {
                    float xo = u.d.red[tid + s]; int io = u.d.si[tid + s];
                    if (xo > u.d.red[tid] || (xo == u.d.red[tid] && io < u.d.si[tid])) {
                        u.d.red[tid] = xo; u.d.si[tid] = io;
                    }
                }
                __syncthreads();
            }
            float Mb = u.d.red[r*128];
            float e = __expf(lgs[r*252 + j] - Mb);
            if (j + 128 < 251) e += __expf(lgs[r*252 + j + 128] - Mb);
            u.d.red[512 + tid] = e;
            __syncthreads();
            for (int s = 64; s; s >>= 1) {
                if (j < s) u.d.red[512 + tid] += u.d.red[512 + tid + s];
                __syncthreads();
            }
            if (j == 0) {
                g_pm[r*NBLK + bi] = Mb;
                g_ps[r*NBLK + bi] = u.d.red[512 + r*128];
                g_pi[r*NBLK + bi] = u.d.si[r*128];
            }
            __syncthreads();
        }
        gbar(++ep);
        // ---- combine partials + probs + output + ynext (fp16 emb) ----
        {
            int r = tid >> 7, b = tid & 127;
            u.d.red[tid] = g_pm[r*NBLK + b];
            u.d.si[tid]  = g_pi[r*NBLK + b];
            float sb = g_ps[r*NBLK + b];
            __syncthreads();
            for (int s = 64; s; s >>= 1) {
                if (b < s) {
                    float xo = u.d.red[tid + s]; int io = u.d.si[tid + s];
                    if (xo > u.d.red[tid] || (xo == u.d.red[tid] && io < u.d.si[tid])) {
                        u.d.red[tid] = xo; u.d.si[tid] = io;
                    }
                }
                __syncthreads();
            }
            float Mr = u.d.red[r*128];
            u.d.red[512 + tid] = sb * __expf(g_pm[r*NBLK + b] - Mr);
            __syncthreads();
            for (int s = 64; s; s >>= 1) {
                if (b < s) u.d.red[512 + tid] += u.d.red[512 + tid + s];
                __syncthreads();
            }
            if (b == 0) {
                u.d.sred[r] = Mr;
                u.d.sred[4 + r] = 1.f / u.d.red[512 + r*128];
            }
            __syncthreads();
            if (bi == 0 && tid < 4)
                out[B_*T_*V_ + tid*T_ + t] = (u.d.si[tid*128] == 0) ? 1.0f : 0.0f;
            if (tid < 251) {
                #pragma unroll
                for (int rr = 0; rr < 4; rr++) {
                    float pv = __expf(lgs[rr*252 + tid] - u.d.sred[rr]) * u.d.sred[4 + rr];
                    out[(rr*T_ + t)*V_ + bi*251 + tid] = pv;
                    u.d.h[rr*251 + tid] = pv;
                }
            }
            __syncthreads();
            int v0 = bi * 251;
            int c = tid;
            float A0 = 0.f, A1 = 0.f, A2 = 0.f, A3 = 0.f;
            int j2 = 0;
            for (; j2 + 8 <= 251; j2 += 8) {
                float e8[8];
                #pragma unroll
                for (int uu = 0; uu < 8; uu++)
                    e8[uu] = __half2float(w_em[(size_t)(v0 + j2 + uu)*D_ + c]);
                #pragma unroll
                for (int uu = 0; uu < 8; uu++) {
                    A0 = fmaf(u.d.h[0*251 + j2+uu], e8[uu], A0);
                    A1 = fmaf(u.d.h[1*251 + j2+uu], e8[uu], A1);
                    A2 = fmaf(u.d.h[2*251 + j2+uu], e8[uu], A2);
                    A3 = fmaf(u.d.h[3*251 + j2+uu], e8[uu], A3);
                }
            }
            for (; j2 < 251; j2++) {
                float e1 = __half2float(w_em[(size_t)(v0 + j2)*D_ + c]);
                A0 = fmaf(u.d.h[0*251 + j2], e1, A0);
                A1 = fmaf(u.d.h[1*251 + j2], e1, A1);
                A2 = fmaf(u.d.h[2*251 + j2], e1, A2);
                A3 = fmaf(u.d.h[3*251 + j2], e1, A3);
            }
            atomicAdd(&nxt[0*D_ + c], A0);
            atomicAdd(&nxt[1*D_ + c], A1);
            atomicAdd(&nxt[2*D_ + c], A2);
            atomicAdd(&nxt[3*D_ + c], A3);
            __syncthreads();
        }
        gbar(++ep);
        float* tmp = cur; cur = nxt; nxt = tmp;
    }
}

// ---------------- host driver ----------------
extern "C" void kernel_launch(void* const* d_in, const int* in_sizes, int n_in,
                              void* d_out, int out_size) {
    const int*   ids     = (const int*)  d_in[0];
    const float* mask    = (const float*)d_in[1];
    const float* emb     = (const float*)d_in[2];
    const float* enc_wq  = (const float*)d_in[3];
    const float* enc_wk  = (const float*)d_in[4];
    const float* enc_wv  = (const float*)d_in[5];
    const float* enc_wo  = (const float*)d_in[6];
    const float* enc_ln1 = (const float*)d_in[7];
    const float* enc_w1  = (const float*)d_in[8];
    const float* enc_w2  = (const float*)d_in[9];
    const float* enc_ln2 = (const float*)d_in[10];
    const float* enc_lnf = (const float*)d_in[11];
    const float* dec_sq  = (const float*)d_in[12];
    const float* dec_sk  = (const float*)d_in[13];
    const float* dec_sv  = (const float*)d_in[14];
    const float* dec_so  = (const float*)d_in[15];
    const float* dec_ln1 = (const float*)d_in[16];
    const float* dec_cq  = (const float*)d_in[17];
    const float* dec_ck  = (const float*)d_in[18];
    const float* dec_cv  = (const float*)d_in[19];
    const float* dec_co  = (const float*)d_in[20];
    const float* dec_ln2 = (const float*)d_in[21];
    const float* dec_w1  = (const float*)d_in[22];
    const float* dec_w2  = (const float*)d_in[23];
    const float* dec_ln3 = (const float*)d_in[24];
    const float* dec_lnf = (const float*)d_in[25];
    const float* lm_head = (const float*)d_in[26];
    float* out = (float*)d_out;

    k_reset<<<1, 128>>>();
    k_mega<<<NBLK, NTH>>>(ids, mask, emb,
                          enc_wq, enc_wk, enc_wv, enc_wo, enc_ln1,
                          enc_w1, enc_w2, enc_ln2, enc_lnf,
                          dec_sq, dec_sk, dec_sv, dec_so, dec_ln1,
                          dec_cq, dec_ck, dec_cv, dec_co, dec_ln2,
                          dec_w1, dec_w2, dec_ln3, dec_lnf,
                          lm_head, out);
}